// round 1
// baseline (speedup 1.0000x reference)
#include <cuda_runtime.h>
#include <math.h>

// Problem constants
#define NB   2
#define CINC 256
#define CT   512
#define GR   8
#define CGC  64
#define HH   48
#define HW   2304      // 48*48
#define HOUT 46
#define DS   2116      // 46*46
#define TOT  (NB*CT*HW)

// ------------------------------------------------------------------
// Scratch (device globals: allocation-free)
// ------------------------------------------------------------------
__device__ float g_xh[NB * 2 * CT * HW];   // interleaved [n, 2C, H, W]
__device__ float g_q [NB * CT * HW];       // [n,G,CG,Q]
__device__ float g_k [NB * CT * DS];       // [n,G,CG,D]
__device__ float g_v [NB * CT * DS];
__device__ float g_a [NB * CT * HW];       // attention output
__device__ float g_gates[4][NB * CT * HW]; // i,f,g,o pre-activations

// ------------------------------------------------------------------
// Kernel 1: proj_x (two 1x1 convs as GEMM) + build interleaved xh
// grid (18 px-tiles, 8 co-tiles(=groups), 2 batch), 256 threads
// block tile: 64 out-ch x 128 px, thread tile 8x4
// ------------------------------------------------------------------
__global__ __launch_bounds__(256) void proj_kernel(
    const float* __restrict__ x_in, const float* __restrict__ h,
    const float* __restrict__ Wx,  const float* __restrict__ Wig)
{
    int px0 = blockIdx.x * 128;
    int g   = blockIdx.y;
    int n   = blockIdx.z;
    int tid = threadIdx.x;
    int toc = tid >> 5;      // 0..7 : out-channel chunk
    int tp  = tid & 31;      // 0..31: pixel chunk

    __shared__ float As[16][68];   // [k][co], pitch 68 (16B aligned rows)
    __shared__ float Bs[16][128];  // [k][px]

    float acc[8][4];
#pragma unroll
    for (int i = 0; i < 8; i++)
#pragma unroll
        for (int j = 0; j < 4; j++) acc[i][j] = 0.f;

    for (int phase = 0; phase < 2; phase++) {
        const float* Wp  = phase ? Wig : Wx;
        int Kd           = phase ? CT : CINC;
        const float* inp = phase ? (h + n * CT * HW) : (x_in + n * CINC * HW);
        for (int k0 = 0; k0 < Kd; k0 += 16) {
            __syncthreads();
            for (int i = tid; i < 1024; i += 256) {
                int kk = i & 15, co = i >> 4;
                As[kk][co] = Wp[(g * 64 + co) * Kd + k0 + kk];
            }
            for (int i = tid; i < 2048; i += 256) {
                int p = i & 127, kk = i >> 7;
                Bs[kk][p] = inp[(k0 + kk) * HW + px0 + p];
            }
            __syncthreads();
#pragma unroll
            for (int kk = 0; kk < 16; kk++) {
                float4 a0 = *(const float4*)&As[kk][toc * 8];
                float4 a1 = *(const float4*)&As[kk][toc * 8 + 4];
                float4 b  = *(const float4*)&Bs[kk][tp * 4];
                float av[8] = {a0.x, a0.y, a0.z, a0.w, a1.x, a1.y, a1.z, a1.w};
                float bv[4] = {b.x, b.y, b.z, b.w};
#pragma unroll
                for (int i = 0; i < 8; i++)
#pragma unroll
                    for (int j = 0; j < 4; j++) acc[i][j] += av[i] * bv[j];
            }
        }
    }

    // write x into first CG of group block; copy h into second CG
#pragma unroll
    for (int i = 0; i < 8; i++) {
        int oc = toc * 8 + i;
        float* dstx = g_xh + (n * 2 * CT + g * 128 + oc) * HW + px0 + tp * 4;
#pragma unroll
        for (int j = 0; j < 4; j++) dstx[j] = acc[i][j];
        const float* hs = h + (n * CT + g * 64 + oc) * HW + px0 + tp * 4;
        float* dsth = g_xh + (n * 2 * CT + g * 128 + 64 + oc) * HW + px0 + tp * 4;
#pragma unroll
        for (int j = 0; j < 4; j++) dsth[j] = hs[j];
    }
}

// ------------------------------------------------------------------
// Kernel 2: grouped 3x3 convs for q (pad1), k (pad0), v (pad0)
// grid (9 tiles, 16 heads, 3 which), 256 threads
// block tile: 64 oc x 16x16 px; thread tile: 8 oc x 8 px (one row)
// ------------------------------------------------------------------
__global__ __launch_bounds__(256) void qkv_kernel(
    const float* __restrict__ Wq, const float* __restrict__ Wk,
    const float* __restrict__ Wv)
{
    int z = blockIdx.z;
    const float* Wp = (z == 0) ? Wq : (z == 1) ? Wk : Wv;
    float* outp     = (z == 0) ? g_q : (z == 1) ? g_k : g_v;
    const int pad   = (z == 0) ? 1 : 0;
    const int OH    = (z == 0) ? 48 : 46;

    int head = blockIdx.y;
    int n = head >> 3, g = head & 7;
    int ty = blockIdx.x / 3, tx = blockIdx.x % 3;
    int oy0 = ty * 16, ox0 = tx * 16;
    int tid = threadIdx.x;
    int toc = tid >> 5, tpx = tid & 31;
    int row = tpx >> 1, col0 = (tpx & 1) * 8;

    __shared__ float ins[18][19];
    __shared__ float ws[64][9];

    float acc[8][8];
#pragma unroll
    for (int i = 0; i < 8; i++)
#pragma unroll
        for (int j = 0; j < 8; j++) acc[i][j] = 0.f;

    const float* inb = g_xh + (n * 2 * CT + g * 128) * HW;

    for (int c = 0; c < 128; c++) {
        __syncthreads();
        for (int i = tid; i < 324; i += 256) {
            int r = i / 18, cl = i - r * 18;
            int iy = oy0 + r - pad, ix = ox0 + cl - pad;
            float v = 0.f;
            if ((unsigned)iy < 48u && (unsigned)ix < 48u)
                v = inb[c * HW + iy * 48 + ix];
            ins[r][cl] = v;
        }
        for (int i = tid; i < 576; i += 256) {
            int oc = i / 9, tap = i - oc * 9;
            ws[oc][tap] = Wp[((g * 64 + oc) * 128 + c) * 9 + tap];
        }
        __syncthreads();
#pragma unroll
        for (int ky = 0; ky < 3; ky++) {
#pragma unroll
            for (int kx = 0; kx < 3; kx++) {
                float iv[8];
#pragma unroll
                for (int j = 0; j < 8; j++) iv[j] = ins[row + ky][col0 + kx + j];
#pragma unroll
                for (int i = 0; i < 8; i++) {
                    float wv = ws[toc * 8 + i][ky * 3 + kx];
#pragma unroll
                    for (int j = 0; j < 8; j++) acc[i][j] += wv * iv[j];
                }
            }
        }
    }

    int oy = oy0 + row;
    if (oy < OH) {
#pragma unroll
        for (int i = 0; i < 8; i++) {
            int oc = toc * 8 + i;
            float* dst = outp + (head * 64 + oc) * (OH * OH) + oy * OH;
#pragma unroll
            for (int j = 0; j < 8; j++) {
                int ox = ox0 + col0 + j;
                if (ox < OH) dst[ox] = acc[i][j];
            }
        }
    }
}

// ------------------------------------------------------------------
// Kernel 3: fused attention (flash-style, never materializes logits)
// grid (18 q-tiles, 16 heads), 128 threads; 1 query per thread
// ------------------------------------------------------------------
template <bool FULL>
__device__ __forceinline__ void attn_chunk(
    int dc, const float (&qr)[64], float (&o)[64], float& m, float& l,
    const float (*ks)[68], const float (*vs)[68])
{
    for (int db = 0; db < (FULL ? 64 : dc); db += 16) {
        float s[16];
        float mx = m;
#pragma unroll
        for (int j = 0; j < 16; j++) {
            if (FULL || db + j < dc) {
                const float4* kr = (const float4*)&ks[db + j][0];
                float a0 = 0.f, a1 = 0.f, a2 = 0.f, a3 = 0.f;
#pragma unroll
                for (int c4 = 0; c4 < 16; c4++) {
                    float4 kk = kr[c4];
                    a0 += qr[4 * c4 + 0] * kk.x;
                    a1 += qr[4 * c4 + 1] * kk.y;
                    a2 += qr[4 * c4 + 2] * kk.z;
                    a3 += qr[4 * c4 + 3] * kk.w;
                }
                float sv = (a0 + a1) + (a2 + a3);
                s[j] = sv;
                mx = fmaxf(mx, sv);
            }
        }
        float alpha = __expf(m - mx);
        m = mx;
        l *= alpha;
#pragma unroll
        for (int c = 0; c < 64; c++) o[c] *= alpha;
#pragma unroll
        for (int j = 0; j < 16; j++) {
            if (FULL || db + j < dc) {
                float w = __expf(s[j] - m);
                l += w;
                const float4* vr = (const float4*)&vs[db + j][0];
#pragma unroll
                for (int c4 = 0; c4 < 16; c4++) {
                    float4 vv = vr[c4];
                    o[4 * c4 + 0] += w * vv.x;
                    o[4 * c4 + 1] += w * vv.y;
                    o[4 * c4 + 2] += w * vv.z;
                    o[4 * c4 + 3] += w * vv.w;
                }
            }
        }
    }
}

__global__ __launch_bounds__(128) void attn_kernel(const float* __restrict__ tau)
{
    int head = blockIdx.y;
    int g = head & 7;
    int qi = blockIdx.x * 128 + threadIdx.x;

    const float* qg = g_q + (size_t)head * 64 * HW;
    const float* kg = g_k + (size_t)head * 64 * DS;
    const float* vg = g_v + (size_t)head * 64 * DS;
    float tv = tau[g];

    float qr[64];
#pragma unroll
    for (int c = 0; c < 64; c++) qr[c] = tv * qg[c * HW + qi];

    float o[64];
#pragma unroll
    for (int c = 0; c < 64; c++) o[c] = 0.f;
    float m = -1e30f, l = 0.f;

    __shared__ float ks[64][68];   // [d][c] transposed, pitch 68 (16B aligned)
    __shared__ float vs[64][68];

    for (int d0 = 0; d0 < DS; d0 += 64) {
        int dc = min(64, DS - d0);
        __syncthreads();
        for (int i = threadIdx.x; i < 4096; i += 128) {
            int c = i >> 6, dd = i & 63;
            if (dd < dc) {
                ks[dd][c] = kg[c * DS + d0 + dd];
                vs[dd][c] = vg[c * DS + d0 + dd];
            }
        }
        __syncthreads();
        if (dc == 64) attn_chunk<true >(dc, qr, o, m, l, ks, vs);
        else          attn_chunk<false>(dc, qr, o, m, l, ks, vs);
    }

    float inv = 1.f / l;
    float* ag = g_a + (size_t)head * 64 * HW;
#pragma unroll
    for (int c = 0; c < 64; c++) ag[c * HW + qi] = o[c] * inv;
}

// ------------------------------------------------------------------
// Kernel 4: gate pre-activations: grouped 3x3 on xh (pad1) +
//           grouped 1x1 on a + bias.  grid (9, 16 heads, 4 gates)
// ------------------------------------------------------------------
__global__ __launch_bounds__(256) void gate_kernel(
    const float* __restrict__ Wia, const float* __restrict__ Wix, const float* __restrict__ bi,
    const float* __restrict__ Wfa, const float* __restrict__ Wfx, const float* __restrict__ bf,
    const float* __restrict__ Wga, const float* __restrict__ Wgx, const float* __restrict__ bg,
    const float* __restrict__ Woa, const float* __restrict__ Wox, const float* __restrict__ bo)
{
    int z = blockIdx.z;
    const float* Wa = (z == 0) ? Wia : (z == 1) ? Wfa : (z == 2) ? Wga : Woa;
    const float* Wp = (z == 0) ? Wix : (z == 1) ? Wfx : (z == 2) ? Wgx : Wox;
    const float* bb = (z == 0) ? bi  : (z == 1) ? bf  : (z == 2) ? bg  : bo;
    float* outp = g_gates[z];

    int head = blockIdx.y;
    int n = head >> 3, g = head & 7;
    int ty = blockIdx.x / 3, tx = blockIdx.x % 3;
    int oy0 = ty * 16, ox0 = tx * 16;
    int tid = threadIdx.x;
    int toc = tid >> 5, tpx = tid & 31;
    int row = tpx >> 1, col0 = (tpx & 1) * 8;

    __shared__ float ins[18][19];
    __shared__ float ws[64][9];
    __shared__ float as_[16][17];
    __shared__ float wa[64];

    float acc[8][8];
#pragma unroll
    for (int i = 0; i < 8; i++)
#pragma unroll
        for (int j = 0; j < 8; j++) acc[i][j] = 0.f;

    const float* inb = g_xh + (n * 2 * CT + g * 128) * HW;

    // 3x3 grouped conv on xh, pad = 1
    for (int c = 0; c < 128; c++) {
        __syncthreads();
        for (int i = tid; i < 324; i += 256) {
            int r = i / 18, cl = i - r * 18;
            int iy = oy0 + r - 1, ix = ox0 + cl - 1;
            float v = 0.f;
            if ((unsigned)iy < 48u && (unsigned)ix < 48u)
                v = inb[c * HW + iy * 48 + ix];
            ins[r][cl] = v;
        }
        for (int i = tid; i < 576; i += 256) {
            int oc = i / 9, tap = i - oc * 9;
            ws[oc][tap] = Wp[((g * 64 + oc) * 128 + c) * 9 + tap];
        }
        __syncthreads();
#pragma unroll
        for (int ky = 0; ky < 3; ky++) {
#pragma unroll
            for (int kx = 0; kx < 3; kx++) {
                float iv[8];
#pragma unroll
                for (int j = 0; j < 8; j++) iv[j] = ins[row + ky][col0 + kx + j];
#pragma unroll
                for (int i = 0; i < 8; i++) {
                    float wv = ws[toc * 8 + i][ky * 3 + kx];
#pragma unroll
                    for (int j = 0; j < 8; j++) acc[i][j] += wv * iv[j];
                }
            }
        }
    }

    // grouped 1x1 on a
    for (int ca = 0; ca < 64; ca++) {
        __syncthreads();
        {
            int r = tid >> 4, cl = tid & 15;
            if (tid < 256)
                as_[r][cl] = g_a[(head * 64 + ca) * HW + (oy0 + r) * 48 + ox0 + cl];
        }
        if (tid < 64) wa[tid] = Wa[(g * 64 + tid) * 64 + ca];
        __syncthreads();
        float iv[8];
#pragma unroll
        for (int j = 0; j < 8; j++) iv[j] = as_[row][col0 + j];
#pragma unroll
        for (int i = 0; i < 8; i++) {
            float wv = wa[toc * 8 + i];
#pragma unroll
            for (int j = 0; j < 8; j++) acc[i][j] += wv * iv[j];
        }
    }

    // epilogue with bias (48x48 tiles exact)
    int oy = oy0 + row;
#pragma unroll
    for (int i = 0; i < 8; i++) {
        int oc = toc * 8 + i;
        float bv = bb[g * 64 + oc];
        float* dst = outp + (head * 64 + oc) * HW + oy * 48;
#pragma unroll
        for (int j = 0; j < 8; j++) dst[ox0 + col0 + j] = acc[i][j] + bv;
    }
}

// ------------------------------------------------------------------
// Kernel 5: LSTM pointwise update
// ------------------------------------------------------------------
__global__ void final_kernel(const float* __restrict__ cold, float* __restrict__ out)
{
    int idx = blockIdx.x * 256 + threadIdx.x;
    if (idx >= TOT) return;
    float pi = g_gates[0][idx];
    float pf = g_gates[1][idx];
    float pg = g_gates[2][idx];
    float po = g_gates[3][idx];
    float ig = 1.f / (1.f + __expf(-pi));
    float fg = 1.f / (1.f + __expf(-pf));
    float gg = tanhf(pg);
    float og = 1.f / (1.f + __expf(-po));
    float cn = fg * cold[idx] + ig * gg;
    out[idx] = og * tanhf(cn);
}

// ------------------------------------------------------------------
extern "C" void kernel_launch(void* const* d_in, const int* in_sizes, int n_in,
                              void* d_out, int out_size)
{
    const float* x_in = (const float*)d_in[0];
    const float* h    = (const float*)d_in[1];
    const float* c    = (const float*)d_in[2];
    const float* tau  = (const float*)d_in[3];
    const float* Wx   = (const float*)d_in[4];
    const float* Wig  = (const float*)d_in[5];
    const float* Wq   = (const float*)d_in[6];
    const float* Wk   = (const float*)d_in[7];
    const float* Wv   = (const float*)d_in[8];
    const float* Wia  = (const float*)d_in[9];
    const float* Wix  = (const float*)d_in[10];
    const float* bi   = (const float*)d_in[11];
    const float* Wfa  = (const float*)d_in[12];
    const float* Wfx  = (const float*)d_in[13];
    const float* bf   = (const float*)d_in[14];
    const float* Wga  = (const float*)d_in[15];
    const float* Wgx  = (const float*)d_in[16];
    const float* bg   = (const float*)d_in[17];
    const float* Woa  = (const float*)d_in[18];
    const float* Wox  = (const float*)d_in[19];
    const float* bo   = (const float*)d_in[20];
    float* out = (float*)d_out;

    proj_kernel<<<dim3(18, 8, 2), 256>>>(x_in, h, Wx, Wig);
    qkv_kernel<<<dim3(9, 16, 3), 256>>>(Wq, Wk, Wv);
    attn_kernel<<<dim3(18, 16), 128>>>(tau);
    gate_kernel<<<dim3(9, 16, 4), 256>>>(Wia, Wix, bi, Wfa, Wfx, bf,
                                         Wga, Wgx, bg, Woa, Wox, bo);
    final_kernel<<<(TOT + 255) / 256, 256>>>(c, out);
}

// round 2
// speedup vs baseline: 1.3016x; 1.3016x over previous
#include <cuda_runtime.h>
#include <math.h>
#include <stdint.h>

// Problem constants
#define NB   2
#define CINC 256
#define CT   512
#define GR   8
#define CGC  64
#define HH   48
#define HW   2304      // 48*48
#define HOUT 46
#define DS   2116      // 46*46
#define TOT  (NB*CT*HW)

// ------------------------------------------------------------------
// Scratch (device globals: allocation-free)
// ------------------------------------------------------------------
__device__ float g_xh[NB * 2 * CT * HW];    // interleaved [n, 2C, H, W]
__device__ float g_q [NB * CT * HW];        // [head, c, q]
__device__ float g_kT[NB * CT * DS];        // [head, d, c]  (transposed!)
__device__ float g_vT[NB * CT * DS];        // [head, d, c]
__device__ float g_a [NB * CT * HW];        // attention output [head, c, q]
__device__ float g_gates[4][NB * CT * HW];  // i,f,g,o pre-activations

// ------------------------------------------------------------------
// cp.async helpers
// ------------------------------------------------------------------
__device__ __forceinline__ uint32_t s2u(const void* p) {
    return (uint32_t)__cvta_generic_to_shared(p);
}
__device__ __forceinline__ void cpa4(uint32_t dst, const void* src, bool pred) {
    int sz = pred ? 4 : 0;
    asm volatile("cp.async.ca.shared.global [%0], [%1], 4, %2;\n"
                 :: "r"(dst), "l"(src), "r"(sz) : "memory");
}
__device__ __forceinline__ void cpa16(uint32_t dst, const void* src, bool pred) {
    int sz = pred ? 16 : 0;
    asm volatile("cp.async.cg.shared.global [%0], [%1], 16, %2;\n"
                 :: "r"(dst), "l"(src), "r"(sz) : "memory");
}
#define CP_COMMIT() asm volatile("cp.async.commit_group;\n" ::: "memory")
#define CP_WAIT1()  asm volatile("cp.async.wait_group 1;\n" ::: "memory")

// ------------------------------------------------------------------
// Kernel 1: proj_x (two 1x1 convs as GEMM) + build interleaved xh
// grid (18 px-tiles, 8 groups, 2 batch), 256 threads
// 2-stage cp.async pipeline over 48 k-rounds (16 for W_x, 32 for W_ig)
// ------------------------------------------------------------------
__global__ __launch_bounds__(256) void proj_kernel(
    const float* __restrict__ x_in, const float* __restrict__ h,
    const float* __restrict__ Wx,  const float* __restrict__ Wig)
{
    int px0 = blockIdx.x * 128;
    int g   = blockIdx.y;
    int n   = blockIdx.z;
    int tid = threadIdx.x;
    int toc = tid >> 5;
    int tp  = tid & 31;

    __shared__ float As[2][16][68];
    __shared__ float Bs[2][16][128];

    float acc[8][4];
#pragma unroll
    for (int i = 0; i < 8; i++)
#pragma unroll
        for (int j = 0; j < 4; j++) acc[i][j] = 0.f;

    const float* inp0 = x_in + n * CINC * HW;
    const float* inp1 = h + n * CT * HW;

    const int ROUNDS = 48;  // 16 (phase0) + 32 (phase1)

    // fill round r into buffer b
    auto fill = [&](int b, int r) {
        const float* Wp;
        const float* inp;
        int Kd, k0;
        if (r < 16) { Wp = Wx;  inp = inp0; Kd = CINC; k0 = r * 16; }
        else        { Wp = Wig; inp = inp1; Kd = CT;   k0 = (r - 16) * 16; }
        for (int i = tid; i < 1024; i += 256) {
            int kk = i & 15, co = i >> 4;
            cpa4(s2u(&As[b][kk][co]), Wp + (g * 64 + co) * Kd + k0 + kk, true);
        }
        for (int i = tid; i < 512; i += 256) {
            int kk = i >> 5, p4 = i & 31;
            cpa16(s2u(&Bs[b][kk][p4 * 4]), inp + (k0 + kk) * HW + px0 + p4 * 4, true);
        }
    };

    fill(0, 0);
    CP_COMMIT();
    for (int r = 0; r < ROUNDS; r++) {
        if (r + 1 < ROUNDS) fill((r + 1) & 1, r + 1);
        CP_COMMIT();
        CP_WAIT1();
        __syncthreads();
        int b = r & 1;
#pragma unroll
        for (int kk = 0; kk < 16; kk++) {
            float4 a0 = *(const float4*)&As[b][kk][toc * 8];
            float4 a1 = *(const float4*)&As[b][kk][toc * 8 + 4];
            float4 bv4 = *(const float4*)&Bs[b][kk][tp * 4];
            float av[8] = {a0.x, a0.y, a0.z, a0.w, a1.x, a1.y, a1.z, a1.w};
            float bv[4] = {bv4.x, bv4.y, bv4.z, bv4.w};
#pragma unroll
            for (int i = 0; i < 8; i++)
#pragma unroll
                for (int j = 0; j < 4; j++) acc[i][j] += av[i] * bv[j];
        }
        __syncthreads();
    }

#pragma unroll
    for (int i = 0; i < 8; i++) {
        int oc = toc * 8 + i;
        float* dstx = g_xh + (n * 2 * CT + g * 128 + oc) * HW + px0 + tp * 4;
#pragma unroll
        for (int j = 0; j < 4; j++) dstx[j] = acc[i][j];
        const float* hs = h + (n * CT + g * 64 + oc) * HW + px0 + tp * 4;
        float* dsth = g_xh + (n * 2 * CT + g * 128 + 64 + oc) * HW + px0 + tp * 4;
#pragma unroll
        for (int j = 0; j < 4; j++) dsth[j] = hs[j];
    }
}

// ------------------------------------------------------------------
// Kernel 2: grouped 3x3 convs for q (pad1), k (pad0, transposed out),
// v (pad0, transposed out).  grid (9 tiles, 16 heads, 3 which), 256 thr
// 2-stage cp.async pipeline, 2 channels per round
// ------------------------------------------------------------------
__global__ __launch_bounds__(256) void qkv_kernel(
    const float* __restrict__ Wq, const float* __restrict__ Wk,
    const float* __restrict__ Wv)
{
    int z = blockIdx.z;
    const float* Wp = (z == 0) ? Wq : (z == 1) ? Wk : Wv;
    const int pad   = (z == 0) ? 1 : 0;
    const int OH    = (z == 0) ? 48 : 46;

    int head = blockIdx.y;
    int n = head >> 3, g = head & 7;
    int ty = blockIdx.x / 3, tx = blockIdx.x % 3;
    int oy0 = ty * 16, ox0 = tx * 16;
    int tid = threadIdx.x;
    int toc = tid >> 5, tpx = tid & 31;
    int row = tpx >> 1, col0 = (tpx & 1) * 8;

    __shared__ float ins[2][2][18][19];
    __shared__ float ws [2][2][64][9];

    float acc[8][8];
#pragma unroll
    for (int i = 0; i < 8; i++)
#pragma unroll
        for (int j = 0; j < 8; j++) acc[i][j] = 0.f;

    const float* inb = g_xh + (n * 2 * CT + g * 128) * HW;
    const float* Wb  = Wp + (size_t)(g * 64) * 128 * 9;

    auto fill = [&](int b, int c0) {
#pragma unroll
        for (int cb = 0; cb < 2; cb++) {
            const float* src_ch = inb + (c0 + cb) * HW;
            for (int i = tid; i < 324; i += 256) {
                int rr = i / 18, cl = i - rr * 18;
                int iy = oy0 + rr - pad, ix = ox0 + cl - pad;
                bool p = ((unsigned)iy < 48u) && ((unsigned)ix < 48u);
                const float* s = p ? (src_ch + iy * 48 + ix) : src_ch;
                cpa4(s2u(&ins[b][cb][rr][cl]), s, p);
            }
            for (int i = tid; i < 576; i += 256) {
                int oc = i / 9, tap = i - oc * 9;
                cpa4(s2u(&ws[b][cb][oc][tap]),
                     Wb + ((size_t)oc * 128 + c0 + cb) * 9 + tap, true);
            }
        }
    };

    fill(0, 0);
    CP_COMMIT();
    for (int r = 0; r < 64; r++) {
        if (r + 1 < 64) fill((r + 1) & 1, (r + 1) * 2);
        CP_COMMIT();
        CP_WAIT1();
        __syncthreads();
        int b = r & 1;
#pragma unroll
        for (int cb = 0; cb < 2; cb++) {
            float iv[3][10];
#pragma unroll
            for (int r2 = 0; r2 < 3; r2++)
#pragma unroll
                for (int j = 0; j < 10; j++)
                    iv[r2][j] = ins[b][cb][row + r2][col0 + j];
#pragma unroll
            for (int i = 0; i < 8; i++) {
#pragma unroll
                for (int ky = 0; ky < 3; ky++)
#pragma unroll
                    for (int kx = 0; kx < 3; kx++) {
                        float wv = ws[b][cb][toc * 8 + i][ky * 3 + kx];
#pragma unroll
                        for (int j = 0; j < 8; j++)
                            acc[i][j] += wv * iv[ky][kx + j];
                    }
            }
        }
        __syncthreads();
    }

    int oy = oy0 + row;
    if (z == 0) {
        // q: [head][c][q] layout, 48x48, tiles exact
#pragma unroll
        for (int i = 0; i < 8; i++) {
            int oc = toc * 8 + i;
            float* dst = g_q + ((size_t)head * 64 + oc) * HW + oy * 48;
#pragma unroll
            for (int j = 0; j < 8; j++) dst[ox0 + col0 + j] = acc[i][j];
        }
    } else {
        // k/v: transposed [head][d][c] layout, 46x46
        float* outp = (z == 1) ? g_kT : g_vT;
        if (oy < 46) {
#pragma unroll
            for (int j = 0; j < 8; j++) {
                int ox = ox0 + col0 + j;
                if (ox < 46) {
                    float* dst = outp + ((size_t)head * DS + oy * 46 + ox) * 64 + toc * 8;
#pragma unroll
                    for (int i = 0; i < 8; i++) dst[i] = acc[i][j];
                }
            }
        }
    }
}

// ------------------------------------------------------------------
// Kernel 3: fused attention (flash-style), 32-d chunks double-buffered
// grid (18 q-tiles, 16 heads), 128 threads; 1 query per thread
// ------------------------------------------------------------------
template <bool FULL>
__device__ __forceinline__ void attn_chunk(
    int dc, const float (&qr)[64], float (&o)[64], float& m, float& l,
    const float (*ks)[68], const float (*vs)[68])
{
    for (int db = 0; db < (FULL ? 32 : dc); db += 16) {
        float s[16];
        float mx = m;
#pragma unroll
        for (int j = 0; j < 16; j++) {
            if (FULL || db + j < dc) {
                const float4* kr = (const float4*)&ks[db + j][0];
                float a0 = 0.f, a1 = 0.f, a2 = 0.f, a3 = 0.f;
#pragma unroll
                for (int c4 = 0; c4 < 16; c4++) {
                    float4 kk = kr[c4];
                    a0 += qr[4 * c4 + 0] * kk.x;
                    a1 += qr[4 * c4 + 1] * kk.y;
                    a2 += qr[4 * c4 + 2] * kk.z;
                    a3 += qr[4 * c4 + 3] * kk.w;
                }
                float sv = (a0 + a1) + (a2 + a3);
                s[j] = sv;
                mx = fmaxf(mx, sv);
            }
        }
        float alpha = __expf(m - mx);
        m = mx;
        l *= alpha;
#pragma unroll
        for (int c = 0; c < 64; c++) o[c] *= alpha;
#pragma unroll
        for (int j = 0; j < 16; j++) {
            if (FULL || db + j < dc) {
                float w = __expf(s[j] - m);
                l += w;
                const float4* vr = (const float4*)&vs[db + j][0];
#pragma unroll
                for (int c4 = 0; c4 < 16; c4++) {
                    float4 vv = vr[c4];
                    o[4 * c4 + 0] += w * vv.x;
                    o[4 * c4 + 1] += w * vv.y;
                    o[4 * c4 + 2] += w * vv.z;
                    o[4 * c4 + 3] += w * vv.w;
                }
            }
        }
    }
}

__global__ __launch_bounds__(128) void attn_kernel(const float* __restrict__ tau)
{
    int head = blockIdx.y;
    int g = head & 7;
    int qi = blockIdx.x * 128 + threadIdx.x;

    const float* qg = g_q + (size_t)head * 64 * HW;
    const float* kT = g_kT + (size_t)head * DS * 64;
    const float* vT = g_vT + (size_t)head * DS * 64;
    float tv = tau[g];

    float qr[64];
#pragma unroll
    for (int c = 0; c < 64; c++) qr[c] = tv * qg[c * HW + qi];

    float o[64];
#pragma unroll
    for (int c = 0; c < 64; c++) o[c] = 0.f;
    float m = -1e30f, l = 0.f;

    __shared__ float ks[2][32][68];
    __shared__ float vs[2][32][68];

    const int NCH = (DS + 31) / 32;  // 67

    auto fill = [&](int b, int d0) {
        for (int i = threadIdx.x; i < 512; i += 128) {
            int dd = i >> 4, c4 = i & 15;
            bool p = (d0 + dd) < DS;
            const float* sk = p ? (kT + (size_t)(d0 + dd) * 64 + c4 * 4) : kT;
            const float* sv = p ? (vT + (size_t)(d0 + dd) * 64 + c4 * 4) : vT;
            cpa16(s2u(&ks[b][dd][c4 * 4]), sk, p);
            cpa16(s2u(&vs[b][dd][c4 * 4]), sv, p);
        }
    };

    fill(0, 0);
    CP_COMMIT();
    for (int ch = 0; ch < NCH; ch++) {
        if (ch + 1 < NCH) fill((ch + 1) & 1, (ch + 1) * 32);
        CP_COMMIT();
        CP_WAIT1();
        __syncthreads();
        int dc = min(32, DS - ch * 32);
        int b = ch & 1;
        if (dc == 32) attn_chunk<true >(dc, qr, o, m, l, ks[b], vs[b]);
        else          attn_chunk<false>(dc, qr, o, m, l, ks[b], vs[b]);
        __syncthreads();
    }

    float inv = 1.f / l;
    float* ag = g_a + (size_t)head * 64 * HW;
#pragma unroll
    for (int c = 0; c < 64; c++) ag[c * HW + qi] = o[c] * inv;
}

// ------------------------------------------------------------------
// Kernel 4: gate pre-activations: grouped 3x3 on xh (pad1, pipelined) +
//           grouped 1x1 on a (8-ch batched) + bias. grid (9, 16, 4)
// ------------------------------------------------------------------
__global__ __launch_bounds__(256) void gate_kernel(
    const float* __restrict__ Wia, const float* __restrict__ Wix, const float* __restrict__ bi,
    const float* __restrict__ Wfa, const float* __restrict__ Wfx, const float* __restrict__ bf,
    const float* __restrict__ Wga, const float* __restrict__ Wgx, const float* __restrict__ bg,
    const float* __restrict__ Woa, const float* __restrict__ Wox, const float* __restrict__ bo)
{
    int z = blockIdx.z;
    const float* Wa = (z == 0) ? Wia : (z == 1) ? Wfa : (z == 2) ? Wga : Woa;
    const float* Wp = (z == 0) ? Wix : (z == 1) ? Wfx : (z == 2) ? Wgx : Wox;
    const float* bb = (z == 0) ? bi  : (z == 1) ? bf  : (z == 2) ? bg  : bo;
    float* outp = g_gates[z];

    int head = blockIdx.y;
    int n = head >> 3, g = head & 7;
    int ty = blockIdx.x / 3, tx = blockIdx.x % 3;
    int oy0 = ty * 16, ox0 = tx * 16;
    int tid = threadIdx.x;
    int toc = tid >> 5, tpx = tid & 31;
    int row = tpx >> 1, col0 = (tpx & 1) * 8;

    __shared__ float ins[2][2][18][19];
    __shared__ float ws [2][2][64][9];
    __shared__ float as_[8][16][17];
    __shared__ float wa [8][64];

    float acc[8][8];
#pragma unroll
    for (int i = 0; i < 8; i++)
#pragma unroll
        for (int j = 0; j < 8; j++) acc[i][j] = 0.f;

    const float* inb = g_xh + (n * 2 * CT + g * 128) * HW;
    const float* Wb  = Wp + (size_t)(g * 64) * 128 * 9;

    auto fill = [&](int b, int c0) {
#pragma unroll
        for (int cb = 0; cb < 2; cb++) {
            const float* src_ch = inb + (c0 + cb) * HW;
            for (int i = tid; i < 324; i += 256) {
                int rr = i / 18, cl = i - rr * 18;
                int iy = oy0 + rr - 1, ix = ox0 + cl - 1;
                bool p = ((unsigned)iy < 48u) && ((unsigned)ix < 48u);
                const float* s = p ? (src_ch + iy * 48 + ix) : src_ch;
                cpa4(s2u(&ins[b][cb][rr][cl]), s, p);
            }
            for (int i = tid; i < 576; i += 256) {
                int oc = i / 9, tap = i - oc * 9;
                cpa4(s2u(&ws[b][cb][oc][tap]),
                     Wb + ((size_t)oc * 128 + c0 + cb) * 9 + tap, true);
            }
        }
    };

    fill(0, 0);
    CP_COMMIT();
    for (int r = 0; r < 64; r++) {
        if (r + 1 < 64) fill((r + 1) & 1, (r + 1) * 2);
        CP_COMMIT();
        CP_WAIT1();
        __syncthreads();
        int b = r & 1;
#pragma unroll
        for (int cb = 0; cb < 2; cb++) {
            float iv[3][10];
#pragma unroll
            for (int r2 = 0; r2 < 3; r2++)
#pragma unroll
                for (int j = 0; j < 10; j++)
                    iv[r2][j] = ins[b][cb][row + r2][col0 + j];
#pragma unroll
            for (int i = 0; i < 8; i++) {
#pragma unroll
                for (int ky = 0; ky < 3; ky++)
#pragma unroll
                    for (int kx = 0; kx < 3; kx++) {
                        float wv = ws[b][cb][toc * 8 + i][ky * 3 + kx];
#pragma unroll
                        for (int j = 0; j < 8; j++)
                            acc[i][j] += wv * iv[ky][kx + j];
                    }
            }
        }
        __syncthreads();
    }

    // grouped 1x1 on a: 8 rounds of 8 channels
    for (int r = 0; r < 8; r++) {
        __syncthreads();
        for (int i = tid; i < 2048; i += 256) {
            int cb = i >> 8, rem = i & 255, rr = rem >> 4, cl = rem & 15;
            as_[cb][rr][cl] = g_a[((size_t)head * 64 + r * 8 + cb) * HW
                                  + (oy0 + rr) * 48 + ox0 + cl];
        }
        for (int i = tid; i < 512; i += 256) {
            int cb = i >> 6, oc = i & 63;
            wa[cb][oc] = Wa[(g * 64 + oc) * 64 + r * 8 + cb];
        }
        __syncthreads();
#pragma unroll
        for (int cb = 0; cb < 8; cb++) {
            float iv[8];
#pragma unroll
            for (int j = 0; j < 8; j++) iv[j] = as_[cb][row][col0 + j];
#pragma unroll
            for (int i = 0; i < 8; i++) {
                float wv = wa[cb][toc * 8 + i];
#pragma unroll
                for (int j = 0; j < 8; j++) acc[i][j] += wv * iv[j];
            }
        }
    }

    // epilogue with bias (48x48 tiles exact)
    int oy = oy0 + row;
#pragma unroll
    for (int i = 0; i < 8; i++) {
        int oc = toc * 8 + i;
        float bv = bb[g * 64 + oc];
        float* dst = outp + ((size_t)head * 64 + oc) * HW + oy * 48;
#pragma unroll
        for (int j = 0; j < 8; j++) dst[ox0 + col0 + j] = acc[i][j] + bv;
    }
}

// ------------------------------------------------------------------
// Kernel 5: LSTM pointwise update
// ------------------------------------------------------------------
__global__ void final_kernel(const float* __restrict__ cold, float* __restrict__ out)
{
    int idx = blockIdx.x * 256 + threadIdx.x;
    if (idx >= TOT) return;
    float pi = g_gates[0][idx];
    float pf = g_gates[1][idx];
    float pg = g_gates[2][idx];
    float po = g_gates[3][idx];
    float ig = 1.f / (1.f + __expf(-pi));
    float fg = 1.f / (1.f + __expf(-pf));
    float gg = tanhf(pg);
    float og = 1.f / (1.f + __expf(-po));
    float cn = fg * cold[idx] + ig * gg;
    out[idx] = og * tanhf(cn);
}

// ------------------------------------------------------------------
extern "C" void kernel_launch(void* const* d_in, const int* in_sizes, int n_in,
                              void* d_out, int out_size)
{
    const float* x_in = (const float*)d_in[0];
    const float* h    = (const float*)d_in[1];
    const float* c    = (const float*)d_in[2];
    const float* tau  = (const float*)d_in[3];
    const float* Wx   = (const float*)d_in[4];
    const float* Wig  = (const float*)d_in[5];
    const float* Wq   = (const float*)d_in[6];
    const float* Wk   = (const float*)d_in[7];
    const float* Wv   = (const float*)d_in[8];
    const float* Wia  = (const float*)d_in[9];
    const float* Wix  = (const float*)d_in[10];
    const float* bi   = (const float*)d_in[11];
    const float* Wfa  = (const float*)d_in[12];
    const float* Wfx  = (const float*)d_in[13];
    const float* bf   = (const float*)d_in[14];
    const float* Wga  = (const float*)d_in[15];
    const float* Wgx  = (const float*)d_in[16];
    const float* bg   = (const float*)d_in[17];
    const float* Woa  = (const float*)d_in[18];
    const float* Wox  = (const float*)d_in[19];
    const float* bo   = (const float*)d_in[20];
    float* out = (float*)d_out;

    proj_kernel<<<dim3(18, 8, 2), 256>>>(x_in, h, Wx, Wig);
    qkv_kernel<<<dim3(9, 16, 3), 256>>>(Wq, Wk, Wv);
    attn_kernel<<<dim3(18, 16), 128>>>(tau);
    gate_kernel<<<dim3(9, 16, 4), 256>>>(Wia, Wix, bi, Wfa, Wfx, bf,
                                         Wga, Wgx, bg, Woa, Wox, bo);
    final_kernel<<<(TOT + 255) / 256, 256>>>(c, out);
}

// round 3
// speedup vs baseline: 1.4154x; 1.0874x over previous
#include <cuda_runtime.h>
#include <math.h>
#include <stdint.h>

// Problem constants
#define NB   2
#define CINC 256
#define CT   512
#define GR   8
#define CGC  64
#define HH   48
#define HW   2304      // 48*48
#define HOUT 46
#define DS   2116      // 46*46
#define TOT  (NB*CT*HW)

typedef unsigned long long u64;

// ------------------------------------------------------------------
// packed f32x2 helpers
// ------------------------------------------------------------------
__device__ __forceinline__ u64 pack2(float lo, float hi) {
    u64 r; asm("mov.b64 %0, {%1,%2};" : "=l"(r) : "f"(lo), "f"(hi)); return r;
}
__device__ __forceinline__ u64 dup2(float x) {
    u64 r; asm("mov.b64 %0, {%1,%1};" : "=l"(r) : "f"(x)); return r;
}
__device__ __forceinline__ void unpack2(u64 x, float& a, float& b) {
    asm("mov.b64 {%0,%1}, %2;" : "=f"(a), "=f"(b) : "l"(x));
}
__device__ __forceinline__ void fma2(u64& d, u64 a, u64 b) {
    asm("fma.rn.f32x2 %0, %1, %2, %0;" : "+l"(d) : "l"(a), "l"(b));
}
__device__ __forceinline__ void mul2(u64& d, u64 a, u64 b) {
    asm("mul.rn.f32x2 %0, %1, %2;" : "=l"(d) : "l"(a), "l"(b));
}
__device__ __forceinline__ void add2(u64& d, u64 a, u64 b) {
    asm("add.rn.f32x2 %0, %1, %2;" : "=l"(d) : "l"(a), "l"(b));
}

// ------------------------------------------------------------------
// Scratch (device globals: allocation-free)
// ------------------------------------------------------------------
__device__ float g_xh[NB * 2 * CT * HW];    // interleaved [n, 2C, H, W]
__device__ float g_q [NB * CT * HW];        // [head, c, q]
__device__ float g_kT[NB * CT * DS];        // [head, d, c]  (transposed)
__device__ float g_vT[NB * CT * DS];        // [head, d, c]
__device__ float g_a [NB * CT * HW];        // attention output [head, c, q]
__device__ float g_gates[4][NB * CT * HW];  // i,f,g,o pre-activations

// ------------------------------------------------------------------
// cp.async helpers
// ------------------------------------------------------------------
__device__ __forceinline__ uint32_t s2u(const void* p) {
    return (uint32_t)__cvta_generic_to_shared(p);
}
__device__ __forceinline__ void cpa4(uint32_t dst, const void* src, bool pred) {
    int sz = pred ? 4 : 0;
    asm volatile("cp.async.ca.shared.global [%0], [%1], 4, %2;\n"
                 :: "r"(dst), "l"(src), "r"(sz) : "memory");
}
__device__ __forceinline__ void cpa16(uint32_t dst, const void* src, bool pred) {
    int sz = pred ? 16 : 0;
    asm volatile("cp.async.cg.shared.global [%0], [%1], 16, %2;\n"
                 :: "r"(dst), "l"(src), "r"(sz) : "memory");
}
#define CP_COMMIT() asm volatile("cp.async.commit_group;\n" ::: "memory")
#define CP_WAIT0()  asm volatile("cp.async.wait_group 0;\n" ::: "memory")
#define CP_WAIT1()  asm volatile("cp.async.wait_group 1;\n" ::: "memory")

// ------------------------------------------------------------------
// Kernel 1: proj_x (two 1x1 convs as GEMM) + build interleaved xh
// grid (18 px-tiles, 8 groups, 2 batch), 256 threads
// 3-stage cp.async pipeline, one sync/round, f32x2 math (pack over oc)
// ------------------------------------------------------------------
__global__ __launch_bounds__(256) void proj_kernel(
    const float* __restrict__ x_in, const float* __restrict__ h,
    const float* __restrict__ Wx,  const float* __restrict__ Wig)
{
    int px0 = blockIdx.x * 128;
    int g   = blockIdx.y;
    int n   = blockIdx.z;
    int tid = threadIdx.x;
    int toc = tid >> 5;
    int tp  = tid & 31;

    __shared__ float As[3][16][68];
    __shared__ float Bs[3][16][128];

    u64 acc2[4][4];
#pragma unroll
    for (int i = 0; i < 4; i++)
#pragma unroll
        for (int j = 0; j < 4; j++) acc2[i][j] = 0ull;

    const float* inp0 = x_in + n * CINC * HW;
    const float* inp1 = h + n * CT * HW;

    const int ROUNDS = 48;  // 16 (W_x) + 32 (W_ig)

    auto fill = [&](int s, int r) {
        const float* Wp;
        const float* inp;
        int Kd, k0;
        if (r < 16) { Wp = Wx;  inp = inp0; Kd = CINC; k0 = r * 16; }
        else        { Wp = Wig; inp = inp1; Kd = CT;   k0 = (r - 16) * 16; }
        for (int i = tid; i < 1024; i += 256) {
            int kk = i & 15, co = i >> 4;
            cpa4(s2u(&As[s][kk][co]), Wp + (g * 64 + co) * Kd + k0 + kk, true);
        }
        for (int i = tid; i < 512; i += 256) {
            int kk = i >> 5, p4 = i & 31;
            cpa16(s2u(&Bs[s][kk][p4 * 4]), inp + (k0 + kk) * HW + px0 + p4 * 4, true);
        }
    };

    fill(0, 0); CP_COMMIT();
    fill(1, 1); CP_COMMIT();
    for (int r = 0; r < ROUNDS; r++) {
        CP_WAIT1();
        __syncthreads();
        if (r + 2 < ROUNDS) fill((r + 2) % 3, r + 2);
        CP_COMMIT();
        int b = r % 3;
#pragma unroll
        for (int kk = 0; kk < 16; kk++) {
            const u64* ap = (const u64*)&As[b][kk][toc * 8];
            u64 a2[4];
#pragma unroll
            for (int i2 = 0; i2 < 4; i2++) a2[i2] = ap[i2];
            float4 bv4 = *(const float4*)&Bs[b][kk][tp * 4];
            u64 bd[4] = {dup2(bv4.x), dup2(bv4.y), dup2(bv4.z), dup2(bv4.w)};
#pragma unroll
            for (int i2 = 0; i2 < 4; i2++)
#pragma unroll
                for (int j = 0; j < 4; j++) fma2(acc2[i2][j], a2[i2], bd[j]);
        }
    }

    // epilogue: unpack, write x half + copy h half
#pragma unroll
    for (int i2 = 0; i2 < 4; i2++) {
        float lo[4], hi[4];
#pragma unroll
        for (int j = 0; j < 4; j++) unpack2(acc2[i2][j], lo[j], hi[j]);
        int oc = toc * 8 + 2 * i2;
        float4 v0 = {lo[0], lo[1], lo[2], lo[3]};
        float4 v1 = {hi[0], hi[1], hi[2], hi[3]};
        *(float4*)(g_xh + ((size_t)(n * 2 * CT + g * 128 + oc)) * HW + px0 + tp * 4) = v0;
        *(float4*)(g_xh + ((size_t)(n * 2 * CT + g * 128 + oc + 1)) * HW + px0 + tp * 4) = v1;
    }
#pragma unroll
    for (int i = 0; i < 8; i++) {
        int oc = toc * 8 + i;
        const float4* hs = (const float4*)(h + ((size_t)(n * CT + g * 64 + oc)) * HW + px0 + tp * 4);
        float4* dsth = (float4*)(g_xh + ((size_t)(n * 2 * CT + g * 128 + 64 + oc)) * HW + px0 + tp * 4);
        *dsth = *hs;
    }
}

// ------------------------------------------------------------------
// Kernel 2: grouped 3x3 convs for q (pad1), k/v (pad0, transposed out)
// grid (9 tiles, 16 heads, 3 which), 256 threads
// 3-stage pipeline, 2 channels/round, one sync/round, f32x2 over oc
// ------------------------------------------------------------------
__global__ __launch_bounds__(256) void qkv_kernel(
    const float* __restrict__ Wq, const float* __restrict__ Wk,
    const float* __restrict__ Wv)
{
    int z = blockIdx.z;
    const float* Wp = (z == 0) ? Wq : (z == 1) ? Wk : Wv;
    const int pad   = (z == 0) ? 1 : 0;

    int head = blockIdx.y;
    int n = head >> 3, g = head & 7;
    int ty = blockIdx.x / 3, tx = blockIdx.x % 3;
    int oy0 = ty * 16, ox0 = tx * 16;
    int tid = threadIdx.x;
    int toc = tid >> 5, tpx = tid & 31;
    int row = tpx >> 1, col0 = (tpx & 1) * 8;

    __shared__ float ins[3][2][18][19];
    __shared__ float ws [3][2][9][64];   // [tap][oc] -> oc-pairs contiguous

    u64 acc2[4][8];
#pragma unroll
    for (int i = 0; i < 4; i++)
#pragma unroll
        for (int j = 0; j < 8; j++) acc2[i][j] = 0ull;

    const float* inb = g_xh + (n * 2 * CT + g * 128) * HW;
    const float* Wb  = Wp + (size_t)(g * 64) * 128 * 9;

    auto fill = [&](int s, int r) {
        int c0 = r * 2;
#pragma unroll
        for (int cb = 0; cb < 2; cb++) {
            const float* src_ch = inb + (c0 + cb) * HW;
            for (int i = tid; i < 324; i += 256) {
                int rr = i / 18, cl = i - rr * 18;
                int iy = oy0 + rr - pad, ix = ox0 + cl - pad;
                bool p = ((unsigned)iy < 48u) && ((unsigned)ix < 48u);
                const float* sp = p ? (src_ch + iy * 48 + ix) : src_ch;
                cpa4(s2u(&ins[s][cb][rr][cl]), sp, p);
            }
            for (int i = tid; i < 576; i += 256) {
                int tap = i >> 6, oc = i & 63;
                cpa4(s2u(&ws[s][cb][tap][oc]),
                     Wb + ((size_t)oc * 128 + c0 + cb) * 9 + tap, true);
            }
        }
    };

    fill(0, 0); CP_COMMIT();
    fill(1, 1); CP_COMMIT();
    for (int r = 0; r < 64; r++) {
        CP_WAIT1();
        __syncthreads();
        if (r + 2 < 64) fill((r + 2) % 3, r + 2);
        CP_COMMIT();
        int b = r % 3;
#pragma unroll
        for (int cb = 0; cb < 2; cb++) {
#pragma unroll
            for (int ky = 0; ky < 3; ky++) {
                u64 rowd[10];
#pragma unroll
                for (int t = 0; t < 10; t++)
                    rowd[t] = dup2(ins[b][cb][row + ky][col0 + t]);
#pragma unroll
                for (int kx = 0; kx < 3; kx++) {
                    const u64* wp = (const u64*)&ws[b][cb][ky * 3 + kx][toc * 8];
#pragma unroll
                    for (int i2 = 0; i2 < 4; i2++) {
                        u64 w2 = wp[i2];
#pragma unroll
                        for (int j = 0; j < 8; j++)
                            fma2(acc2[i2][j], w2, rowd[kx + j]);
                    }
                }
            }
        }
    }

    int oy = oy0 + row;
    if (z == 0) {
        // q: [head][c][q] layout, 48x48, tiles exact
#pragma unroll
        for (int i2 = 0; i2 < 4; i2++) {
            int oc = toc * 8 + 2 * i2;
            float* d0 = g_q + ((size_t)head * 64 + oc) * HW + oy * 48 + ox0 + col0;
            float* d1 = d0 + HW;
#pragma unroll
            for (int j = 0; j < 8; j++) {
                float v0, v1;
                unpack2(acc2[i2][j], v0, v1);
                d0[j] = v0; d1[j] = v1;
            }
        }
    } else {
        // k/v transposed: [head][d][c], oc-pairs contiguous -> u64 stores
        float* outp = (z == 1) ? g_kT : g_vT;
        if (oy < 46) {
#pragma unroll
            for (int j = 0; j < 8; j++) {
                int ox = ox0 + col0 + j;
                if (ox < 46) {
                    u64* dst = (u64*)(outp + ((size_t)head * DS + oy * 46 + ox) * 64 + toc * 8);
#pragma unroll
                    for (int i2 = 0; i2 < 4; i2++) dst[i2] = acc2[i2][j];
                }
            }
        }
    }
}

// ------------------------------------------------------------------
// Kernel 3: fused attention (flash-style), f32x2 packed over channels
// grid (18 q-tiles, 16 heads), 128 threads; 1 query per thread
// ------------------------------------------------------------------
template <bool FULL>
__device__ __forceinline__ void attn_chunk(
    int dc, const u64 (&q2)[32], u64 (&o2)[32], float& m, float& l,
    const float (*ks)[68], const float (*vs)[68])
{
    for (int db = 0; db < (FULL ? 32 : dc); db += 16) {
        float s[16];
        float mx = m;
#pragma unroll
        for (int j = 0; j < 16; j++) {
            if (FULL || db + j < dc) {
                const u64* kr = (const u64*)&ks[db + j][0];
                u64 t0 = 0ull, t1 = 0ull, t2 = 0ull, t3 = 0ull;
#pragma unroll
                for (int c2 = 0; c2 < 32; c2 += 4) {
                    fma2(t0, q2[c2 + 0], kr[c2 + 0]);
                    fma2(t1, q2[c2 + 1], kr[c2 + 1]);
                    fma2(t2, q2[c2 + 2], kr[c2 + 2]);
                    fma2(t3, q2[c2 + 3], kr[c2 + 3]);
                }
                add2(t0, t0, t1);
                add2(t2, t2, t3);
                add2(t0, t0, t2);
                float a, b;
                unpack2(t0, a, b);
                float sv = a + b;
                s[j] = sv;
                mx = fmaxf(mx, sv);
            }
        }
        float alpha = __expf(m - mx);
        m = mx;
        l *= alpha;
        u64 ad = dup2(alpha);
#pragma unroll
        for (int c2 = 0; c2 < 32; c2++) mul2(o2[c2], o2[c2], ad);
#pragma unroll
        for (int j = 0; j < 16; j++) {
            if (FULL || db + j < dc) {
                float w = __expf(s[j] - m);
                l += w;
                u64 wd = dup2(w);
                const u64* vr = (const u64*)&vs[db + j][0];
#pragma unroll
                for (int c2 = 0; c2 < 32; c2++) fma2(o2[c2], wd, vr[c2]);
            }
        }
    }
}

__global__ __launch_bounds__(128) void attn_kernel(const float* __restrict__ tau)
{
    int head = blockIdx.y;
    int g = head & 7;
    int qi = blockIdx.x * 128 + threadIdx.x;

    const float* qg = g_q + (size_t)head * 64 * HW;
    const float* kT = g_kT + (size_t)head * DS * 64;
    const float* vT = g_vT + (size_t)head * DS * 64;
    float tv = tau[g];

    u64 q2[32];
#pragma unroll
    for (int c2 = 0; c2 < 32; c2++)
        q2[c2] = pack2(tv * qg[(2 * c2) * HW + qi], tv * qg[(2 * c2 + 1) * HW + qi]);

    u64 o2[32];
#pragma unroll
    for (int c2 = 0; c2 < 32; c2++) o2[c2] = 0ull;
    float m = -1e30f, l = 0.f;

    __shared__ float ks[2][32][68];
    __shared__ float vs[2][32][68];

    const int NCH = (DS + 31) / 32;  // 67

    auto fill = [&](int b, int d0) {
        for (int i = threadIdx.x; i < 512; i += 128) {
            int dd = i >> 4, c4 = i & 15;
            bool p = (d0 + dd) < DS;
            const float* sk = p ? (kT + (size_t)(d0 + dd) * 64 + c4 * 4) : kT;
            const float* sv = p ? (vT + (size_t)(d0 + dd) * 64 + c4 * 4) : vT;
            cpa16(s2u(&ks[b][dd][c4 * 4]), sk, p);
            cpa16(s2u(&vs[b][dd][c4 * 4]), sv, p);
        }
    };

    fill(0, 0);
    CP_COMMIT();
    for (int ch = 0; ch < NCH; ch++) {
        if (ch + 1 < NCH) fill((ch + 1) & 1, (ch + 1) * 32);
        CP_COMMIT();
        CP_WAIT1();
        __syncthreads();
        int dc = min(32, DS - ch * 32);
        int b = ch & 1;
        if (dc == 32) attn_chunk<true >(dc, q2, o2, m, l, ks[b], vs[b]);
        else          attn_chunk<false>(dc, q2, o2, m, l, ks[b], vs[b]);
        __syncthreads();
    }

    float inv = 1.f / l;
    float* ag = g_a + (size_t)head * 64 * HW;
#pragma unroll
    for (int c2 = 0; c2 < 32; c2++) {
        float a, b;
        unpack2(o2[c2], a, b);
        ag[(2 * c2) * HW + qi] = a * inv;
        ag[(2 * c2 + 1) * HW + qi] = b * inv;
    }
}

// ------------------------------------------------------------------
// Kernel 4: gate pre-activations: grouped 3x3 on xh (pad1, pipelined) +
//           grouped 1x1 on a (pipelined) + bias. grid (9, 16, 4)
// ------------------------------------------------------------------
__global__ __launch_bounds__(256) void gate_kernel(
    const float* __restrict__ Wia, const float* __restrict__ Wix, const float* __restrict__ bi,
    const float* __restrict__ Wfa, const float* __restrict__ Wfx, const float* __restrict__ bf,
    const float* __restrict__ Wga, const float* __restrict__ Wgx, const float* __restrict__ bg,
    const float* __restrict__ Woa, const float* __restrict__ Wox, const float* __restrict__ bo)
{
    int z = blockIdx.z;
    const float* Wa = (z == 0) ? Wia : (z == 1) ? Wfa : (z == 2) ? Wga : Woa;
    const float* Wp = (z == 0) ? Wix : (z == 1) ? Wfx : (z == 2) ? Wgx : Wox;
    const float* bb = (z == 0) ? bi  : (z == 1) ? bf  : (z == 2) ? bg  : bo;
    float* outp = g_gates[z];

    int head = blockIdx.y;
    int n = head >> 3, g = head & 7;
    int ty = blockIdx.x / 3, tx = blockIdx.x % 3;
    int oy0 = ty * 16, ox0 = tx * 16;
    int tid = threadIdx.x;
    int toc = tid >> 5, tpx = tid & 31;
    int row = tpx >> 1, col0 = (tpx & 1) * 8;

    __shared__ float ins[3][2][18][19];
    __shared__ float ws [3][2][9][64];
    __shared__ float as_[2][8][16][20];   // pitch 20 -> 16B-aligned rows
    __shared__ float wa [2][8][64];

    u64 acc2[4][8];
#pragma unroll
    for (int i = 0; i < 4; i++)
#pragma unroll
        for (int j = 0; j < 8; j++) acc2[i][j] = 0ull;

    const float* inb = g_xh + (n * 2 * CT + g * 128) * HW;
    const float* Wb  = Wp + (size_t)(g * 64) * 128 * 9;

    auto fill = [&](int s, int r) {
        int c0 = r * 2;
#pragma unroll
        for (int cb = 0; cb < 2; cb++) {
            const float* src_ch = inb + (c0 + cb) * HW;
            for (int i = tid; i < 324; i += 256) {
                int rr = i / 18, cl = i - rr * 18;
                int iy = oy0 + rr - 1, ix = ox0 + cl - 1;
                bool p = ((unsigned)iy < 48u) && ((unsigned)ix < 48u);
                const float* sp = p ? (src_ch + iy * 48 + ix) : src_ch;
                cpa4(s2u(&ins[s][cb][rr][cl]), sp, p);
            }
            for (int i = tid; i < 576; i += 256) {
                int tap = i >> 6, oc = i & 63;
                cpa4(s2u(&ws[s][cb][tap][oc]),
                     Wb + ((size_t)oc * 128 + c0 + cb) * 9 + tap, true);
            }
        }
    };

    fill(0, 0); CP_COMMIT();
    fill(1, 1); CP_COMMIT();
    for (int r = 0; r < 64; r++) {
        CP_WAIT1();
        __syncthreads();
        if (r + 2 < 64) fill((r + 2) % 3, r + 2);
        CP_COMMIT();
        int b = r % 3;
#pragma unroll
        for (int cb = 0; cb < 2; cb++) {
#pragma unroll
            for (int ky = 0; ky < 3; ky++) {
                u64 rowd[10];
#pragma unroll
                for (int t = 0; t < 10; t++)
                    rowd[t] = dup2(ins[b][cb][row + ky][col0 + t]);
#pragma unroll
                for (int kx = 0; kx < 3; kx++) {
                    const u64* wp = (const u64*)&ws[b][cb][ky * 3 + kx][toc * 8];
#pragma unroll
                    for (int i2 = 0; i2 < 4; i2++) {
                        u64 w2 = wp[i2];
#pragma unroll
                        for (int j = 0; j < 8; j++)
                            fma2(acc2[i2][j], w2, rowd[kx + j]);
                    }
                }
            }
        }
    }

    // grouped 1x1 on a: 8 rounds of 8 channels, 2-stage cp.async
    auto filla = [&](int s, int r8) {
        for (int i = tid; i < 512; i += 256) {
            int cb = i >> 6, rem = i & 63, rr = rem >> 2, c4 = rem & 3;
            cpa16(s2u(&as_[s][cb][rr][c4 * 4]),
                  g_a + ((size_t)head * 64 + r8 * 8 + cb) * HW
                      + (oy0 + rr) * 48 + ox0 + c4 * 4, true);
        }
        for (int i = tid; i < 512; i += 256) {
            int cb = i >> 6, oc = i & 63;
            cpa4(s2u(&wa[s][cb][oc]), Wa + (g * 64 + oc) * 64 + r8 * 8 + cb, true);
        }
    };

    // drain conv pipeline groups before reusing the cp.async group counter
    CP_WAIT0();
    __syncthreads();
    filla(0, 0); CP_COMMIT();
    for (int r8 = 0; r8 < 8; r8++) {
        CP_WAIT0();
        __syncthreads();
        if (r8 + 1 < 8) filla((r8 + 1) & 1, r8 + 1);
        CP_COMMIT();
        int s = r8 & 1;
#pragma unroll
        for (int cb = 0; cb < 8; cb++) {
            const u64* wp = (const u64*)&wa[s][cb][toc * 8];
            u64 w2[4] = {wp[0], wp[1], wp[2], wp[3]};
#pragma unroll
            for (int j = 0; j < 8; j++) {
                u64 ad = dup2(as_[s][cb][row][col0 + j]);
#pragma unroll
                for (int i2 = 0; i2 < 4; i2++) fma2(acc2[i2][j], w2[i2], ad);
            }
        }
    }

    // epilogue with bias (48x48 tiles exact)
    int oy = oy0 + row;
#pragma unroll
    for (int i2 = 0; i2 < 4; i2++) {
        int oc = toc * 8 + 2 * i2;
        float bv0 = bb[g * 64 + oc];
        float bv1 = bb[g * 64 + oc + 1];
        float* d0 = outp + ((size_t)head * 64 + oc) * HW + oy * 48 + ox0 + col0;
        float* d1 = d0 + HW;
#pragma unroll
        for (int j = 0; j < 8; j++) {
            float v0, v1;
            unpack2(acc2[i2][j], v0, v1);
            d0[j] = v0 + bv0;
            d1[j] = v1 + bv1;
        }
    }
}

// ------------------------------------------------------------------
// Kernel 5: LSTM pointwise update
// ------------------------------------------------------------------
__global__ void final_kernel(const float* __restrict__ cold, float* __restrict__ out)
{
    int idx = blockIdx.x * 256 + threadIdx.x;
    if (idx >= TOT) return;
    float pi = g_gates[0][idx];
    float pf = g_gates[1][idx];
    float pg = g_gates[2][idx];
    float po = g_gates[3][idx];
    float ig = 1.f / (1.f + __expf(-pi));
    float fg = 1.f / (1.f + __expf(-pf));
    float gg = tanhf(pg);
    float og = 1.f / (1.f + __expf(-po));
    float cn = fg * cold[idx] + ig * gg;
    out[idx] = og * tanhf(cn);
}

// ------------------------------------------------------------------
extern "C" void kernel_launch(void* const* d_in, const int* in_sizes, int n_in,
                              void* d_out, int out_size)
{
    const float* x_in = (const float*)d_in[0];
    const float* h    = (const float*)d_in[1];
    const float* c    = (const float*)d_in[2];
    const float* tau  = (const float*)d_in[3];
    const float* Wx   = (const float*)d_in[4];
    const float* Wig  = (const float*)d_in[5];
    const float* Wq   = (const float*)d_in[6];
    const float* Wk   = (const float*)d_in[7];
    const float* Wv   = (const float*)d_in[8];
    const float* Wia  = (const float*)d_in[9];
    const float* Wix  = (const float*)d_in[10];
    const float* bi   = (const float*)d_in[11];
    const float* Wfa  = (const float*)d_in[12];
    const float* Wfx  = (const float*)d_in[13];
    const float* bf   = (const float*)d_in[14];
    const float* Wga  = (const float*)d_in[15];
    const float* Wgx  = (const float*)d_in[16];
    const float* bg   = (const float*)d_in[17];
    const float* Woa  = (const float*)d_in[18];
    const float* Wox  = (const float*)d_in[19];
    const float* bo   = (const float*)d_in[20];
    float* out = (float*)d_out;

    proj_kernel<<<dim3(18, 8, 2), 256>>>(x_in, h, Wx, Wig);
    qkv_kernel<<<dim3(9, 16, 3), 256>>>(Wq, Wk, Wv);
    attn_kernel<<<dim3(18, 16), 128>>>(tau);
    gate_kernel<<<dim3(9, 16, 4), 256>>>(Wia, Wix, bi, Wfa, Wfx, bf,
                                         Wga, Wgx, bg, Woa, Wox, bo);
    final_kernel<<<(TOT + 255) / 256, 256>>>(c, out);
}

// round 4
// speedup vs baseline: 1.4179x; 1.0018x over previous
#include <cuda_runtime.h>
#include <math.h>
#include <stdint.h>

// Problem constants
#define NB   2
#define CINC 256
#define CT   512
#define GR   8
#define CGC  64
#define HH   48
#define HW   2304      // 48*48
#define HOUT 46
#define DS   2116      // 46*46
#define TOT  (NB*CT*HW)

typedef unsigned long long u64;

// ------------------------------------------------------------------
// packed f32x2 helpers
// ------------------------------------------------------------------
__device__ __forceinline__ u64 pack2(float lo, float hi) {
    u64 r; asm("mov.b64 %0, {%1,%2};" : "=l"(r) : "f"(lo), "f"(hi)); return r;
}
__device__ __forceinline__ u64 dup2(float x) {
    u64 r; asm("mov.b64 %0, {%1,%1};" : "=l"(r) : "f"(x)); return r;
}
__device__ __forceinline__ void unpack2(u64 x, float& a, float& b) {
    asm("mov.b64 {%0,%1}, %2;" : "=f"(a), "=f"(b) : "l"(x));
}
__device__ __forceinline__ void fma2(u64& d, u64 a, u64 b) {
    asm("fma.rn.f32x2 %0, %1, %2, %0;" : "+l"(d) : "l"(a), "l"(b));
}
__device__ __forceinline__ void mul2(u64& d, u64 a, u64 b) {
    asm("mul.rn.f32x2 %0, %1, %2;" : "=l"(d) : "l"(a), "l"(b));
}
__device__ __forceinline__ void add2(u64& d, u64 a, u64 b) {
    asm("add.rn.f32x2 %0, %1, %2;" : "=l"(d) : "l"(a), "l"(b));
}

// ------------------------------------------------------------------
// Scratch (device globals: allocation-free)
// ------------------------------------------------------------------
__device__ float g_xh[NB * 2 * CT * HW];    // interleaved [n, 2C, H, W]
__device__ float g_q [NB * CT * HW];        // [head, c, q]
__device__ float g_kT[NB * CT * DS];        // [head, d, c]  (transposed)
__device__ float g_vT[NB * CT * DS];        // [head, d, c]
__device__ float g_a [NB * CT * HW];        // attention output [head, c, q]
__device__ float g_gates[4][NB * CT * HW];  // i,f,g,o pre-activations

// ------------------------------------------------------------------
// cp.async helpers
// ------------------------------------------------------------------
__device__ __forceinline__ uint32_t s2u(const void* p) {
    return (uint32_t)__cvta_generic_to_shared(p);
}
__device__ __forceinline__ void cpa4(uint32_t dst, const void* src, bool pred) {
    int sz = pred ? 4 : 0;
    asm volatile("cp.async.ca.shared.global [%0], [%1], 4, %2;\n"
                 :: "r"(dst), "l"(src), "r"(sz) : "memory");
}
__device__ __forceinline__ void cpa16(uint32_t dst, const void* src, bool pred) {
    int sz = pred ? 16 : 0;
    asm volatile("cp.async.cg.shared.global [%0], [%1], 16, %2;\n"
                 :: "r"(dst), "l"(src), "r"(sz) : "memory");
}
#define CP_COMMIT() asm volatile("cp.async.commit_group;\n" ::: "memory")
#define CP_WAIT0()  asm volatile("cp.async.wait_group 0;\n" ::: "memory")
#define CP_WAIT1()  asm volatile("cp.async.wait_group 1;\n" ::: "memory")

// ------------------------------------------------------------------
// Kernel 1: proj_x (two 1x1 convs as GEMM) + build interleaved xh
// grid (18 px-tiles, 8 groups, 2 batch), 256 threads
// 3-stage cp.async pipeline, one sync/round, f32x2 math (pack over oc)
// ------------------------------------------------------------------
__global__ __launch_bounds__(256) void proj_kernel(
    const float* __restrict__ x_in, const float* __restrict__ h,
    const float* __restrict__ Wx,  const float* __restrict__ Wig)
{
    int px0 = blockIdx.x * 128;
    int g   = blockIdx.y;
    int n   = blockIdx.z;
    int tid = threadIdx.x;
    int toc = tid >> 5;
    int tp  = tid & 31;

    __shared__ float As[3][16][68];
    __shared__ float Bs[3][16][128];

    u64 acc2[4][4];
#pragma unroll
    for (int i = 0; i < 4; i++)
#pragma unroll
        for (int j = 0; j < 4; j++) acc2[i][j] = 0ull;

    const float* inp0 = x_in + n * CINC * HW;
    const float* inp1 = h + n * CT * HW;

    const int ROUNDS = 48;  // 16 (W_x) + 32 (W_ig)

    auto fill = [&](int s, int r) {
        const float* Wp;
        const float* inp;
        int Kd, k0;
        if (r < 16) { Wp = Wx;  inp = inp0; Kd = CINC; k0 = r * 16; }
        else        { Wp = Wig; inp = inp1; Kd = CT;   k0 = (r - 16) * 16; }
        for (int i = tid; i < 1024; i += 256) {
            int kk = i & 15, co = i >> 4;
            cpa4(s2u(&As[s][kk][co]), Wp + (g * 64 + co) * Kd + k0 + kk, true);
        }
        for (int i = tid; i < 512; i += 256) {
            int kk = i >> 5, p4 = i & 31;
            cpa16(s2u(&Bs[s][kk][p4 * 4]), inp + (k0 + kk) * HW + px0 + p4 * 4, true);
        }
    };

    fill(0, 0); CP_COMMIT();
    fill(1, 1); CP_COMMIT();
    for (int r = 0; r < ROUNDS; r++) {
        CP_WAIT1();
        __syncthreads();
        if (r + 2 < ROUNDS) fill((r + 2) % 3, r + 2);
        CP_COMMIT();
        int b = r % 3;
#pragma unroll
        for (int kk = 0; kk < 16; kk++) {
            const u64* ap = (const u64*)&As[b][kk][toc * 8];
            u64 a2[4];
#pragma unroll
            for (int i2 = 0; i2 < 4; i2++) a2[i2] = ap[i2];
            float4 bv4 = *(const float4*)&Bs[b][kk][tp * 4];
            u64 bd[4] = {dup2(bv4.x), dup2(bv4.y), dup2(bv4.z), dup2(bv4.w)};
#pragma unroll
            for (int i2 = 0; i2 < 4; i2++)
#pragma unroll
                for (int j = 0; j < 4; j++) fma2(acc2[i2][j], a2[i2], bd[j]);
        }
    }

    // epilogue: unpack, write x half + copy h half
#pragma unroll
    for (int i2 = 0; i2 < 4; i2++) {
        float lo[4], hi[4];
#pragma unroll
        for (int j = 0; j < 4; j++) unpack2(acc2[i2][j], lo[j], hi[j]);
        int oc = toc * 8 + 2 * i2;
        float4 v0 = {lo[0], lo[1], lo[2], lo[3]};
        float4 v1 = {hi[0], hi[1], hi[2], hi[3]};
        *(float4*)(g_xh + ((size_t)(n * 2 * CT + g * 128 + oc)) * HW + px0 + tp * 4) = v0;
        *(float4*)(g_xh + ((size_t)(n * 2 * CT + g * 128 + oc + 1)) * HW + px0 + tp * 4) = v1;
    }
#pragma unroll
    for (int i = 0; i < 8; i++) {
        int oc = toc * 8 + i;
        const float4* hs = (const float4*)(h + ((size_t)(n * CT + g * 64 + oc)) * HW + px0 + tp * 4);
        float4* dsth = (float4*)(g_xh + ((size_t)(n * 2 * CT + g * 128 + 64 + oc)) * HW + px0 + tp * 4);
        *dsth = *hs;
    }
}

// ------------------------------------------------------------------
// Kernel 2: grouped 3x3 convs for q (pad1), k/v (pad0, transposed out)
// grid (9 tiles, 16 heads, 3 which), 256 threads
// 3-stage pipeline, 2 channels/round, one sync/round, f32x2 over oc
// ------------------------------------------------------------------
__global__ __launch_bounds__(256) void qkv_kernel(
    const float* __restrict__ Wq, const float* __restrict__ Wk,
    const float* __restrict__ Wv)
{
    int z = blockIdx.z;
    const float* Wp = (z == 0) ? Wq : (z == 1) ? Wk : Wv;
    const int pad   = (z == 0) ? 1 : 0;

    int head = blockIdx.y;
    int n = head >> 3, g = head & 7;
    int ty = blockIdx.x / 3, tx = blockIdx.x % 3;
    int oy0 = ty * 16, ox0 = tx * 16;
    int tid = threadIdx.x;
    int toc = tid >> 5, tpx = tid & 31;
    int row = tpx >> 1, col0 = (tpx & 1) * 8;

    __shared__ float ins[3][2][18][19];
    __shared__ float ws [3][2][9][64];   // [tap][oc] -> oc-pairs contiguous

    u64 acc2[4][8];
#pragma unroll
    for (int i = 0; i < 4; i++)
#pragma unroll
        for (int j = 0; j < 8; j++) acc2[i][j] = 0ull;

    const float* inb = g_xh + (n * 2 * CT + g * 128) * HW;
    const float* Wb  = Wp + (size_t)(g * 64) * 128 * 9;

    auto fill = [&](int s, int r) {
        int c0 = r * 2;
#pragma unroll
        for (int cb = 0; cb < 2; cb++) {
            const float* src_ch = inb + (c0 + cb) * HW;
            for (int i = tid; i < 324; i += 256) {
                int rr = i / 18, cl = i - rr * 18;
                int iy = oy0 + rr - pad, ix = ox0 + cl - pad;
                bool p = ((unsigned)iy < 48u) && ((unsigned)ix < 48u);
                const float* sp = p ? (src_ch + iy * 48 + ix) : src_ch;
                cpa4(s2u(&ins[s][cb][rr][cl]), sp, p);
            }
            for (int i = tid; i < 576; i += 256) {
                int tap = i >> 6, oc = i & 63;
                cpa4(s2u(&ws[s][cb][tap][oc]),
                     Wb + ((size_t)oc * 128 + c0 + cb) * 9 + tap, true);
            }
        }
    };

    fill(0, 0); CP_COMMIT();
    fill(1, 1); CP_COMMIT();
    for (int r = 0; r < 64; r++) {
        CP_WAIT1();
        __syncthreads();
        if (r + 2 < 64) fill((r + 2) % 3, r + 2);
        CP_COMMIT();
        int b = r % 3;
#pragma unroll
        for (int cb = 0; cb < 2; cb++) {
#pragma unroll
            for (int ky = 0; ky < 3; ky++) {
                u64 rowd[10];
#pragma unroll
                for (int t = 0; t < 10; t++)
                    rowd[t] = dup2(ins[b][cb][row + ky][col0 + t]);
#pragma unroll
                for (int kx = 0; kx < 3; kx++) {
                    const u64* wp = (const u64*)&ws[b][cb][ky * 3 + kx][toc * 8];
#pragma unroll
                    for (int i2 = 0; i2 < 4; i2++) {
                        u64 w2 = wp[i2];
#pragma unroll
                        for (int j = 0; j < 8; j++)
                            fma2(acc2[i2][j], w2, rowd[kx + j]);
                    }
                }
            }
        }
    }

    int oy = oy0 + row;
    if (z == 0) {
        // q: [head][c][q] layout, 48x48, tiles exact
#pragma unroll
        for (int i2 = 0; i2 < 4; i2++) {
            int oc = toc * 8 + 2 * i2;
            float* d0 = g_q + ((size_t)head * 64 + oc) * HW + oy * 48 + ox0 + col0;
            float* d1 = d0 + HW;
#pragma unroll
            for (int j = 0; j < 8; j++) {
                float v0, v1;
                unpack2(acc2[i2][j], v0, v1);
                d0[j] = v0; d1[j] = v1;
            }
        }
    } else {
        // k/v transposed: [head][d][c], oc-pairs contiguous -> u64 stores
        float* outp = (z == 1) ? g_kT : g_vT;
        if (oy < 46) {
#pragma unroll
            for (int j = 0; j < 8; j++) {
                int ox = ox0 + col0 + j;
                if (ox < 46) {
                    u64* dst = (u64*)(outp + ((size_t)head * DS + oy * 46 + ox) * 64 + toc * 8);
#pragma unroll
                    for (int i2 = 0; i2 < 4; i2++) dst[i2] = acc2[i2][j];
                }
            }
        }
    }
}

// ------------------------------------------------------------------
// Kernel 3: fused attention (flash-style), f32x2 packed over channels
// grid (18 q-tiles, 16 heads), 128 threads; 1 query per thread
// ------------------------------------------------------------------
template <bool FULL>
__device__ __forceinline__ void attn_chunk(
    int dc, const u64 (&q2)[32], u64 (&o2)[32], float& m, float& l,
    const float (*ks)[68], const float (*vs)[68])
{
    for (int db = 0; db < (FULL ? 32 : dc); db += 16) {
        float s[16];
        float mx = m;
#pragma unroll
        for (int j = 0; j < 16; j++) {
            if (FULL || db + j < dc) {
                const u64* kr = (const u64*)&ks[db + j][0];
                u64 t0 = 0ull, t1 = 0ull, t2 = 0ull, t3 = 0ull;
#pragma unroll
                for (int c2 = 0; c2 < 32; c2 += 4) {
                    fma2(t0, q2[c2 + 0], kr[c2 + 0]);
                    fma2(t1, q2[c2 + 1], kr[c2 + 1]);
                    fma2(t2, q2[c2 + 2], kr[c2 + 2]);
                    fma2(t3, q2[c2 + 3], kr[c2 + 3]);
                }
                add2(t0, t0, t1);
                add2(t2, t2, t3);
                add2(t0, t0, t2);
                float a, b;
                unpack2(t0, a, b);
                float sv = a + b;
                s[j] = sv;
                mx = fmaxf(mx, sv);
            }
        }
        float alpha = __expf(m - mx);
        m = mx;
        l *= alpha;
        u64 ad = dup2(alpha);
#pragma unroll
        for (int c2 = 0; c2 < 32; c2++) mul2(o2[c2], o2[c2], ad);
#pragma unroll
        for (int j = 0; j < 16; j++) {
            if (FULL || db + j < dc) {
                float w = __expf(s[j] - m);
                l += w;
                u64 wd = dup2(w);
                const u64* vr = (const u64*)&vs[db + j][0];
#pragma unroll
                for (int c2 = 0; c2 < 32; c2++) fma2(o2[c2], wd, vr[c2]);
            }
        }
    }
}

__global__ __launch_bounds__(128) void attn_kernel(const float* __restrict__ tau)
{
    int head = blockIdx.y;
    int g = head & 7;
    int qi = blockIdx.x * 128 + threadIdx.x;

    const float* qg = g_q + (size_t)head * 64 * HW;
    const float* kT = g_kT + (size_t)head * DS * 64;
    const float* vT = g_vT + (size_t)head * DS * 64;
    float tv = tau[g];

    u64 q2[32];
#pragma unroll
    for (int c2 = 0; c2 < 32; c2++)
        q2[c2] = pack2(tv * qg[(2 * c2) * HW + qi], tv * qg[(2 * c2 + 1) * HW + qi]);

    u64 o2[32];
#pragma unroll
    for (int c2 = 0; c2 < 32; c2++) o2[c2] = 0ull;
    float m = -1e30f, l = 0.f;

    __shared__ float ks[2][32][68];
    __shared__ float vs[2][32][68];

    const int NCH = (DS + 31) / 32;  // 67

    auto fill = [&](int b, int d0) {
        for (int i = threadIdx.x; i < 512; i += 128) {
            int dd = i >> 4, c4 = i & 15;
            bool p = (d0 + dd) < DS;
            const float* sk = p ? (kT + (size_t)(d0 + dd) * 64 + c4 * 4) : kT;
            const float* sv = p ? (vT + (size_t)(d0 + dd) * 64 + c4 * 4) : vT;
            cpa16(s2u(&ks[b][dd][c4 * 4]), sk, p);
            cpa16(s2u(&vs[b][dd][c4 * 4]), sv, p);
        }
    };

    fill(0, 0);
    CP_COMMIT();
    for (int ch = 0; ch < NCH; ch++) {
        if (ch + 1 < NCH) fill((ch + 1) & 1, (ch + 1) * 32);
        CP_COMMIT();
        CP_WAIT1();
        __syncthreads();
        int dc = min(32, DS - ch * 32);
        int b = ch & 1;
        if (dc == 32) attn_chunk<true >(dc, q2, o2, m, l, ks[b], vs[b]);
        else          attn_chunk<false>(dc, q2, o2, m, l, ks[b], vs[b]);
        __syncthreads();
    }

    float inv = 1.f / l;
    float* ag = g_a + (size_t)head * 64 * HW;
#pragma unroll
    for (int c2 = 0; c2 < 32; c2++) {
        float a, b;
        unpack2(o2[c2], a, b);
        ag[(2 * c2) * HW + qi] = a * inv;
        ag[(2 * c2 + 1) * HW + qi] = b * inv;
    }
}

// ------------------------------------------------------------------
// Kernel 4: gate pre-activations: grouped 3x3 on xh (pad1, pipelined) +
//           grouped 1x1 on a (pipelined) + bias. grid (9, 16, 4)
// ------------------------------------------------------------------
__global__ __launch_bounds__(256) void gate_kernel(
    const float* __restrict__ Wia, const float* __restrict__ Wix, const float* __restrict__ bi,
    const float* __restrict__ Wfa, const float* __restrict__ Wfx, const float* __restrict__ bf,
    const float* __restrict__ Wga, const float* __restrict__ Wgx, const float* __restrict__ bg,
    const float* __restrict__ Woa, const float* __restrict__ Wox, const float* __restrict__ bo)
{
    int z = blockIdx.z;
    const float* Wa = (z == 0) ? Wia : (z == 1) ? Wfa : (z == 2) ? Wga : Woa;
    const float* Wp = (z == 0) ? Wix : (z == 1) ? Wfx : (z == 2) ? Wgx : Wox;
    const float* bb = (z == 0) ? bi  : (z == 1) ? bf  : (z == 2) ? bg  : bo;
    float* outp = g_gates[z];

    int head = blockIdx.y;
    int n = head >> 3, g = head & 7;
    int ty = blockIdx.x / 3, tx = blockIdx.x % 3;
    int oy0 = ty * 16, ox0 = tx * 16;
    int tid = threadIdx.x;
    int toc = tid >> 5, tpx = tid & 31;
    int row = tpx >> 1, col0 = (tpx & 1) * 8;

    __shared__ float ins[3][2][18][19];
    __shared__ float ws [3][2][9][64];
    __shared__ float as_[2][8][16][20];   // pitch 20 -> 16B-aligned rows
    __shared__ float wa [2][8][64];

    u64 acc2[4][8];
#pragma unroll
    for (int i = 0; i < 4; i++)
#pragma unroll
        for (int j = 0; j < 8; j++) acc2[i][j] = 0ull;

    const float* inb = g_xh + (n * 2 * CT + g * 128) * HW;
    const float* Wb  = Wp + (size_t)(g * 64) * 128 * 9;

    auto fill = [&](int s, int r) {
        int c0 = r * 2;
#pragma unroll
        for (int cb = 0; cb < 2; cb++) {
            const float* src_ch = inb + (c0 + cb) * HW;
            for (int i = tid; i < 324; i += 256) {
                int rr = i / 18, cl = i - rr * 18;
                int iy = oy0 + rr - 1, ix = ox0 + cl - 1;
                bool p = ((unsigned)iy < 48u) && ((unsigned)ix < 48u);
                const float* sp = p ? (src_ch + iy * 48 + ix) : src_ch;
                cpa4(s2u(&ins[s][cb][rr][cl]), sp, p);
            }
            for (int i = tid; i < 576; i += 256) {
                int tap = i >> 6, oc = i & 63;
                cpa4(s2u(&ws[s][cb][tap][oc]),
                     Wb + ((size_t)oc * 128 + c0 + cb) * 9 + tap, true);
            }
        }
    };

    fill(0, 0); CP_COMMIT();
    fill(1, 1); CP_COMMIT();
    for (int r = 0; r < 64; r++) {
        CP_WAIT1();
        __syncthreads();
        if (r + 2 < 64) fill((r + 2) % 3, r + 2);
        CP_COMMIT();
        int b = r % 3;
#pragma unroll
        for (int cb = 0; cb < 2; cb++) {
#pragma unroll
            for (int ky = 0; ky < 3; ky++) {
                u64 rowd[10];
#pragma unroll
                for (int t = 0; t < 10; t++)
                    rowd[t] = dup2(ins[b][cb][row + ky][col0 + t]);
#pragma unroll
                for (int kx = 0; kx < 3; kx++) {
                    const u64* wp = (const u64*)&ws[b][cb][ky * 3 + kx][toc * 8];
#pragma unroll
                    for (int i2 = 0; i2 < 4; i2++) {
                        u64 w2 = wp[i2];
#pragma unroll
                        for (int j = 0; j < 8; j++)
                            fma2(acc2[i2][j], w2, rowd[kx + j]);
                    }
                }
            }
        }
    }

    // grouped 1x1 on a: 8 rounds of 8 channels, 2-stage cp.async
    auto filla = [&](int s, int r8) {
        for (int i = tid; i < 512; i += 256) {
            int cb = i >> 6, rem = i & 63, rr = rem >> 2, c4 = rem & 3;
            cpa16(s2u(&as_[s][cb][rr][c4 * 4]),
                  g_a + ((size_t)head * 64 + r8 * 8 + cb) * HW
                      + (oy0 + rr) * 48 + ox0 + c4 * 4, true);
        }
        for (int i = tid; i < 512; i += 256) {
            int cb = i >> 6, oc = i & 63;
            cpa4(s2u(&wa[s][cb][oc]), Wa + (g * 64 + oc) * 64 + r8 * 8 + cb, true);
        }
    };

    // drain conv pipeline groups before reusing the cp.async group counter
    CP_WAIT0();
    __syncthreads();
    filla(0, 0); CP_COMMIT();
    for (int r8 = 0; r8 < 8; r8++) {
        CP_WAIT0();
        __syncthreads();
        if (r8 + 1 < 8) filla((r8 + 1) & 1, r8 + 1);
        CP_COMMIT();
        int s = r8 & 1;
#pragma unroll
        for (int cb = 0; cb < 8; cb++) {
            const u64* wp = (const u64*)&wa[s][cb][toc * 8];
            u64 w2[4] = {wp[0], wp[1], wp[2], wp[3]};
#pragma unroll
            for (int j = 0; j < 8; j++) {
                u64 ad = dup2(as_[s][cb][row][col0 + j]);
#pragma unroll
                for (int i2 = 0; i2 < 4; i2++) fma2(acc2[i2][j], w2[i2], ad);
            }
        }
    }

    // epilogue with bias (48x48 tiles exact)
    int oy = oy0 + row;
#pragma unroll
    for (int i2 = 0; i2 < 4; i2++) {
        int oc = toc * 8 + 2 * i2;
        float bv0 = bb[g * 64 + oc];
        float bv1 = bb[g * 64 + oc + 1];
        float* d0 = outp + ((size_t)head * 64 + oc) * HW + oy * 48 + ox0 + col0;
        float* d1 = d0 + HW;
#pragma unroll
        for (int j = 0; j < 8; j++) {
            float v0, v1;
            unpack2(acc2[i2][j], v0, v1);
            d0[j] = v0 + bv0;
            d1[j] = v1 + bv1;
        }
    }
}

// ------------------------------------------------------------------
// Kernel 5: LSTM pointwise update
// ------------------------------------------------------------------
__global__ void final_kernel(const float* __restrict__ cold, float* __restrict__ out)
{
    int idx = blockIdx.x * 256 + threadIdx.x;
    if (idx >= TOT) return;
    float pi = g_gates[0][idx];
    float pf = g_gates[1][idx];
    float pg = g_gates[2][idx];
    float po = g_gates[3][idx];
    float ig = 1.f / (1.f + __expf(-pi));
    float fg = 1.f / (1.f + __expf(-pf));
    float gg = tanhf(pg);
    float og = 1.f / (1.f + __expf(-po));
    float cn = fg * cold[idx] + ig * gg;
    out[idx] = og * tanhf(cn);
}

// ------------------------------------------------------------------
extern "C" void kernel_launch(void* const* d_in, const int* in_sizes, int n_in,
                              void* d_out, int out_size)
{
    const float* x_in = (const float*)d_in[0];
    const float* h    = (const float*)d_in[1];
    const float* c    = (const float*)d_in[2];
    const float* tau  = (const float*)d_in[3];
    const float* Wx   = (const float*)d_in[4];
    const float* Wig  = (const float*)d_in[5];
    const float* Wq   = (const float*)d_in[6];
    const float* Wk   = (const float*)d_in[7];
    const float* Wv   = (const float*)d_in[8];
    const float* Wia  = (const float*)d_in[9];
    const float* Wix  = (const float*)d_in[10];
    const float* bi   = (const float*)d_in[11];
    const float* Wfa  = (const float*)d_in[12];
    const float* Wfx  = (const float*)d_in[13];
    const float* bf   = (const float*)d_in[14];
    const float* Wga  = (const float*)d_in[15];
    const float* Wgx  = (const float*)d_in[16];
    const float* bg   = (const float*)d_in[17];
    const float* Woa  = (const float*)d_in[18];
    const float* Wox  = (const float*)d_in[19];
    const float* bo   = (const float*)d_in[20];
    float* out = (float*)d_out;

    proj_kernel<<<dim3(18, 8, 2), 256>>>(x_in, h, Wx, Wig);
    qkv_kernel<<<dim3(9, 16, 3), 256>>>(Wq, Wk, Wv);
    attn_kernel<<<dim3(18, 16), 128>>>(tau);
    gate_kernel<<<dim3(9, 16, 4), 256>>>(Wia, Wix, bi, Wfa, Wfx, bf,
                                         Wga, Wgx, bg, Woa, Wox, bo);
    final_kernel<<<(TOT + 255) / 256, 256>>>(c, out);
}

// round 6
// speedup vs baseline: 2.0039x; 1.4133x over previous
#include <cuda_runtime.h>
#include <cuda_bf16.h>
#include <math.h>
#include <stdint.h>

#define NB   2
#define CINC 256
#define CT   512
#define HH   48
#define HW   2304
#define DS   2116
#define TOT  (NB*CT*HW)

typedef unsigned long long u64;

// ---------------- packed f32x2 helpers ----------------
__device__ __forceinline__ u64 pack2(float lo, float hi) {
    u64 r; asm("mov.b64 %0, {%1,%2};" : "=l"(r) : "f"(lo), "f"(hi)); return r;
}
__device__ __forceinline__ u64 dup2(float x) {
    u64 r; asm("mov.b64 %0, {%1,%1};" : "=l"(r) : "f"(x)); return r;
}
__device__ __forceinline__ void unpack2(u64 x, float& a, float& b) {
    asm("mov.b64 {%0,%1}, %2;" : "=f"(a), "=f"(b) : "l"(x));
}
__device__ __forceinline__ void fma2(u64& d, u64 a, u64 b) {
    asm("fma.rn.f32x2 %0, %1, %2, %0;" : "+l"(d) : "l"(a), "l"(b));
}
__device__ __forceinline__ void mul2(u64& d, u64 a, u64 b) {
    asm("mul.rn.f32x2 %0, %1, %2;" : "=l"(d) : "l"(a), "l"(b));
}
__device__ __forceinline__ void add2(u64& d, u64 a, u64 b) {
    asm("add.rn.f32x2 %0, %1, %2;" : "=l"(d) : "l"(a), "l"(b));
}

// bf16 2-term split: v ~= hi + lo
__device__ __forceinline__ void bsplit(float v, uint32_t& h16, uint32_t& l16) {
    __nv_bfloat16 bh = __float2bfloat16(v);
    __nv_bfloat16 bl = __float2bfloat16(v - __bfloat162float(bh));
    h16 = (uint32_t)__bfloat16_as_ushort(bh);
    l16 = (uint32_t)__bfloat16_as_ushort(bl);
}

// ---------------- scratch ----------------
#define XHPS (16 * HW * 128)
__device__ __align__(256) __nv_bfloat16 g_xhp[2 * XHPS];       // [split][hd][px][128]
__device__ __align__(256) uint32_t g_wb32[7 * 8 * 19 * 4096];   // weight imgs hi/lo
__device__ __align__(256) __nv_bfloat16 g_ah[16 * HW * 64];     // a hi [hd][px][64]
__device__ __align__(256) __nv_bfloat16 g_al[16 * HW * 64];     // a lo
__device__ __align__(256) float g_q [16 * 64 * HW];
__device__ __align__(256) float g_kT[16 * DS * 64];
__device__ __align__(256) float g_vT[16 * DS * 64];
__device__ __align__(256) float g_gates[4][TOT];

// ---------------- cp.async ----------------
__device__ __forceinline__ uint32_t s2u(const void* p) {
    return (uint32_t)__cvta_generic_to_shared(p);
}
__device__ __forceinline__ void cpa4(uint32_t dst, const void* src, bool pred) {
    int sz = pred ? 4 : 0;
    asm volatile("cp.async.ca.shared.global [%0], [%1], 4, %2;\n"
                 :: "r"(dst), "l"(src), "r"(sz) : "memory");
}
__device__ __forceinline__ void cpa16(uint32_t dst, const void* src, bool pred) {
    int sz = pred ? 16 : 0;
    asm volatile("cp.async.cg.shared.global [%0], [%1], 16, %2;\n"
                 :: "r"(dst), "l"(src), "r"(sz) : "memory");
}
#define CP_COMMIT() asm volatile("cp.async.commit_group;\n" ::: "memory")
#define CP_WAIT0()  asm volatile("cp.async.wait_group 0;\n" ::: "memory")
#define CP_WAIT1()  asm volatile("cp.async.wait_group 1;\n" ::: "memory")

// ---------------- mma.sync helpers (plain sm_80+ PTX) ----------------
#define LDSM4(r, a) \
    asm volatile("ldmatrix.sync.aligned.m8n8.x4.shared.b16 {%0,%1,%2,%3}, [%4];" \
                 : "=r"((r)[0]), "=r"((r)[1]), "=r"((r)[2]), "=r"((r)[3]) : "r"(a))

__device__ __forceinline__ void mma16816(float* d, const uint32_t* a,
                                         uint32_t b0, uint32_t b1) {
    asm volatile(
        "mma.sync.aligned.m16n8k16.row.col.f32.bf16.bf16.f32 "
        "{%0,%1,%2,%3}, {%4,%5,%6,%7}, {%8,%9}, {%0,%1,%2,%3};"
        : "+f"(d[0]), "+f"(d[1]), "+f"(d[2]), "+f"(d[3])
        : "r"(a[0]), "r"(a[1]), "r"(a[2]), "r"(a[3]), "r"(b0), "r"(b1));
}

// ------------------------------------------------------------------
// Kernel 0: weight prep -> g_wb32 per (type,g,chunk):
// hi image (2048 u32 = 64oc x 64ch bf16) then lo image, plain [oc][ch].
// chunk<18: tap=chunk>>1, half=chunk&1.  chunk 18 (types>=3): 1x1 Wa.
// ------------------------------------------------------------------
__global__ void prep_w(const float* __restrict__ Wq, const float* __restrict__ Wk,
                       const float* __restrict__ Wv,
                       const float* __restrict__ Wix, const float* __restrict__ Wfx,
                       const float* __restrict__ Wgx, const float* __restrict__ Wox,
                       const float* __restrict__ Wia, const float* __restrict__ Wfa,
                       const float* __restrict__ Wga, const float* __restrict__ Woa)
{
    int idx = blockIdx.x * 256 + threadIdx.x;
    if (idx >= 7 * 8 * 19 * 64 * 32) return;
    int c2    = idx & 31;
    int oc    = (idx >> 5) & 63;
    int rem   = idx >> 11;
    int chunk = rem % 19;
    int g     = (rem / 19) & 7;
    int type  = rem / 152;
    if (type < 3 && chunk == 18) return;

    float w0, w1;
    if (chunk < 18) {
        const float* W3 = (type == 0) ? Wq : (type == 1) ? Wk : (type == 2) ? Wv :
                          (type == 3) ? Wix : (type == 4) ? Wfx : (type == 5) ? Wgx : Wox;
        int t9 = chunk >> 1, cb = chunk & 1;
        size_t b = ((size_t)(g * 64 + oc) * 128 + cb * 64 + c2 * 2) * 9 + t9;
        w0 = W3[b]; w1 = W3[b + 9];
    } else {
        const float* Wa = (type == 3) ? Wia : (type == 4) ? Wfa : (type == 5) ? Wga : Woa;
        size_t b = (size_t)(g * 64 + oc) * 64 + c2 * 2;
        w0 = Wa[b]; w1 = Wa[b + 1];
    }
    uint32_t h0, l0, h1, l1;
    bsplit(w0, h0, l0); bsplit(w1, h1, l1);
    size_t tb = (size_t)rem * 4096;
    g_wb32[tb + oc * 32 + c2]        = h0 | (h1 << 16);
    g_wb32[tb + 2048 + oc * 32 + c2] = l0 | (l1 << 16);
}

// ------------------------------------------------------------------
// Kernel 1: proj_x GEMM (FFMA2) -> emit xh bf16 hi/lo pixel-major
// ------------------------------------------------------------------
__global__ __launch_bounds__(256) void proj_kernel(
    const float* __restrict__ x_in, const float* __restrict__ h,
    const float* __restrict__ Wx,  const float* __restrict__ Wig)
{
    int px0 = blockIdx.x * 128;
    int g   = blockIdx.y;
    int n   = blockIdx.z;
    int tid = threadIdx.x;
    int toc = tid >> 5;
    int tp  = tid & 31;

    __shared__ float As[3][16][68];
    __shared__ float Bs[3][16][128];

    u64 acc2[4][4];
#pragma unroll
    for (int i = 0; i < 4; i++)
#pragma unroll
        for (int j = 0; j < 4; j++) acc2[i][j] = 0ull;

    const float* inp0 = x_in + n * CINC * HW;
    const float* inp1 = h + n * CT * HW;
    const int ROUNDS = 48;

    auto fill = [&](int s, int r) {
        const float* Wp; const float* inp; int Kd, k0;
        if (r < 16) { Wp = Wx;  inp = inp0; Kd = CINC; k0 = r * 16; }
        else        { Wp = Wig; inp = inp1; Kd = CT;   k0 = (r - 16) * 16; }
        for (int i = tid; i < 1024; i += 256) {
            int kk = i & 15, co = i >> 4;
            cpa4(s2u(&As[s][kk][co]), Wp + (g * 64 + co) * Kd + k0 + kk, true);
        }
        for (int i = tid; i < 512; i += 256) {
            int kk = i >> 5, p4 = i & 31;
            cpa16(s2u(&Bs[s][kk][p4 * 4]), inp + (k0 + kk) * HW + px0 + p4 * 4, true);
        }
    };

    fill(0, 0); CP_COMMIT();
    fill(1, 1); CP_COMMIT();
    for (int r = 0; r < ROUNDS; r++) {
        CP_WAIT1();
        __syncthreads();
        if (r + 2 < ROUNDS) fill((r + 2) % 3, r + 2);
        CP_COMMIT();
        int b = r % 3;
#pragma unroll
        for (int kk = 0; kk < 16; kk++) {
            const u64* ap = (const u64*)&As[b][kk][toc * 8];
            u64 a2[4] = {ap[0], ap[1], ap[2], ap[3]};
            float4 bv4 = *(const float4*)&Bs[b][kk][tp * 4];
            u64 bd[4] = {dup2(bv4.x), dup2(bv4.y), dup2(bv4.z), dup2(bv4.w)};
#pragma unroll
            for (int i2 = 0; i2 < 4; i2++)
#pragma unroll
                for (int j = 0; j < 4; j++) fma2(acc2[i2][j], a2[i2], bd[j]);
        }
    }

    int hd = n * 8 + g;
    uint32_t* xhh = (uint32_t*)g_xhp;
    uint32_t* xhl = (uint32_t*)(g_xhp + XHPS);
#pragma unroll
    for (int i2 = 0; i2 < 4; i2++) {
#pragma unroll
        for (int j = 0; j < 4; j++) {
            float v0, v1; unpack2(acc2[i2][j], v0, v1);
            uint32_t h0, l0, h1, l1;
            bsplit(v0, h0, l0); bsplit(v1, h1, l1);
            size_t of = ((size_t)hd * HW + px0 + tp * 4 + j) * 64 + toc * 4 + i2;
            xhh[of] = h0 | (h1 << 16);
            xhl[of] = l0 | (l1 << 16);
        }
    }
#pragma unroll
    for (int i2 = 0; i2 < 4; i2++) {
        int oc = toc * 8 + 2 * i2;
        const float* h0p = h + ((size_t)(n * CT + g * 64 + oc)) * HW + px0 + tp * 4;
        const float* h1p = h0p + HW;
#pragma unroll
        for (int j = 0; j < 4; j++) {
            uint32_t a0, b0, a1, b1;
            bsplit(h0p[j], a0, b0); bsplit(h1p[j], a1, b1);
            size_t of = ((size_t)hd * HW + px0 + tp * 4 + j) * 64 + 32 + toc * 4 + i2;
            xhh[of] = a0 | (a1 << 16);
            xhl[of] = b0 | (b1 << 16);
        }
    }
}

// ------------------------------------------------------------------
// Kernel 2: mma.sync conv GEMM.  grid (18 px-tiles, 16 heads, types)
// CTA = 128 px x 64 oc; 4 warps, each 32px x 64oc.
// K chunks: 18 (tap,half) for 3x3 convs, +1 (1x1 on a) for gates.
// bf16 split: passes Ah*Bh + Ah*Bl + Al*Bh, fp32 accum.
// SMEM per stage: Ahi 16K | Alo 16K | Bhi 8K | Blo 8K = 48K, 2 stages.
// type: 0=q 1=k 2=v 3..6=gates(i,f,g,o)
// ------------------------------------------------------------------
__global__ __launch_bounds__(128) void conv_kernel(
    int base_type,
    const float* __restrict__ bbi, const float* __restrict__ bbf,
    const float* __restrict__ bbg, const float* __restrict__ bbo)
{
    extern __shared__ char smem[];
    uint32_t sb = s2u(smem);
    const int tid = threadIdx.x, wid = tid >> 5, lane = tid & 31;
    const int type = base_type + blockIdx.z;
    const int hd = blockIdx.y, g = hd & 7;
    const int tile = blockIdx.x;
    const int NCH = (type < 3) ? 18 : 19;

    const int px = tile * 128 + tid;
    const int py = px / 48, pxx = px - py * 48;
    const size_t wtb = (size_t)((type * 8 + g) * 19) * 4096;

    auto fill = [&](int s, int k) {
        uint32_t base = sb + s * 49152;
        const char *sh, *sl; bool in;
        if (k < 18) {
            int t9 = k >> 1, cb = k & 1, ky = t9 / 3, kx = t9 - ky * 3;
            int iy = py + ky - 1, ix = pxx + kx - 1;
            in = ((unsigned)iy < 48u) && ((unsigned)ix < 48u);
            const __nv_bfloat16* r =
                g_xhp + (((size_t)hd * HW + iy * 48 + ix) * 128 + cb * 64);
            if (!in) r = g_xhp;
            sh = (const char*)r;
            sl = (const char*)(r + XHPS);
        } else {
            in = true;
            sh = (const char*)(g_ah + ((size_t)hd * HW + px) * 64);
            sl = (const char*)(g_al + ((size_t)hd * HW + px) * 64);
        }
        uint32_t arow = base + tid * 128;
        uint32_t sw = (tid & 7) << 4;
#pragma unroll
        for (int gc = 0; gc < 8; gc++) {
            uint32_t off = (gc * 16) ^ sw;
            cpa16(arow + off, sh + gc * 16, in);
            cpa16(arow + 16384 + off, sl + gc * 16, in);
        }
        const uint32_t* wsrc = g_wb32 + wtb + (size_t)k * 4096;
#pragma unroll
        for (int i = 0; i < 4; i++) {
            int p = tid + i * 128;            // granule 0..511
            int oc = p >> 3, gr = p & 7;
            uint32_t off = oc * 128 + ((gr * 16) ^ ((oc & 7) << 4));
            cpa16(base + 32768 + off, wsrc + p * 4, true);
            cpa16(base + 40960 + off, wsrc + 2048 + p * 4, true);
        }
    };

    float acc[2][8][4];
#pragma unroll
    for (int mt = 0; mt < 2; mt++)
#pragma unroll
        for (int nt = 0; nt < 8; nt++)
#pragma unroll
            for (int i = 0; i < 4; i++) acc[mt][nt][i] = 0.f;

    fill(0, 0); CP_COMMIT();
    fill(1, 1); CP_COMMIT();

    const int lsub  = lane >> 3;             // 0..3 address group
    const int lrow  = lane & 7;

    for (int k = 0; k < NCH; k++) {
        int s = k & 1;
        if (k + 1 < NCH) { CP_WAIT1(); } else { CP_WAIT0(); }
        __syncthreads();
        uint32_t Ab = sb + s * 49152;
        uint32_t Bb = Ab + 32768;
#pragma unroll
        for (int ks = 0; ks < 4; ks++) {
            uint32_t ah[2][4], al[2][4];
#pragma unroll
            for (int mt = 0; mt < 2; mt++) {
                int r = wid * 32 + mt * 16 + (lsub & 1) * 8 + lrow;
                uint32_t gran = ks * 2 + (lsub >> 1);
                uint32_t addr = Ab + r * 128 + ((gran * 16) ^ ((r & 7) << 4));
                LDSM4(ah[mt], addr);
                LDSM4(al[mt], addr + 16384);
            }
            uint32_t bh[4][4], bl[4][4];
#pragma unroll
            for (int p = 0; p < 4; p++) {
                int n = p * 16 + (lsub >> 1) * 8 + lrow;
                uint32_t gran = ks * 2 + (lsub & 1);
                uint32_t addr = Bb + n * 128 + ((gran * 16) ^ ((n & 7) << 4));
                LDSM4(bh[p], addr);
                LDSM4(bl[p], addr + 8192);
            }
#pragma unroll
            for (int mt = 0; mt < 2; mt++) {
#pragma unroll
                for (int p = 0; p < 4; p++) {
                    mma16816(acc[mt][2 * p],     ah[mt], bh[p][0], bh[p][1]);
                    mma16816(acc[mt][2 * p + 1], ah[mt], bh[p][2], bh[p][3]);
                    mma16816(acc[mt][2 * p],     ah[mt], bl[p][0], bl[p][1]);
                    mma16816(acc[mt][2 * p + 1], ah[mt], bl[p][2], bl[p][3]);
                    mma16816(acc[mt][2 * p],     al[mt], bh[p][0], bh[p][1]);
                    mma16816(acc[mt][2 * p + 1], al[mt], bh[p][2], bh[p][3]);
                }
            }
        }
        __syncthreads();
        if (k + 2 < NCH) fill(s, k + 2);
        CP_COMMIT();
    }

    // epilogue: D fragment (row = lane/4 (+8), col = (lane&3)*2 (+1))
#pragma unroll
    for (int mt = 0; mt < 2; mt++) {
#pragma unroll
        for (int half = 0; half < 2; half++) {
            int m = tile * 128 + wid * 32 + mt * 16 + (lane >> 2) + half * 8;
            if (type == 0) {
                float* dst = g_q + (size_t)hd * 64 * HW + m;
#pragma unroll
                for (int nt = 0; nt < 8; nt++) {
                    int oc = nt * 8 + (lane & 3) * 2;
                    dst[(size_t)oc * HW]       = acc[mt][nt][half * 2];
                    dst[(size_t)(oc + 1) * HW] = acc[mt][nt][half * 2 + 1];
                }
            } else if (type < 3) {
                int oy = m / 48, ox = m - oy * 48;
                if (oy >= 1 && oy <= 46 && ox >= 1 && ox <= 46) {
                    float* dst = ((type == 1) ? g_kT : g_vT)
                                 + ((size_t)hd * DS + (oy - 1) * 46 + (ox - 1)) * 64;
#pragma unroll
                    for (int nt = 0; nt < 8; nt++) {
                        int oc = nt * 8 + (lane & 3) * 2;
                        *(float2*)(dst + oc) =
                            make_float2(acc[mt][nt][half * 2], acc[mt][nt][half * 2 + 1]);
                    }
                }
            } else {
                int z = type - 3;
                const float* bb = (z == 0) ? bbi : (z == 1) ? bbf
                                : (z == 2) ? bbg : bbo;
                float* dst = g_gates[z] + (size_t)hd * 64 * HW + m;
#pragma unroll
                for (int nt = 0; nt < 8; nt++) {
                    int oc = nt * 8 + (lane & 3) * 2;
                    dst[(size_t)oc * HW]       = acc[mt][nt][half * 2]     + bb[g * 64 + oc];
                    dst[(size_t)(oc + 1) * HW] = acc[mt][nt][half * 2 + 1] + bb[g * 64 + oc + 1];
                }
            }
        }
    }
}

// ------------------------------------------------------------------
// Kernel 3: fused attention (FFMA2 flash) -> emits a as bf16 hi/lo
// ------------------------------------------------------------------
template <bool FULL>
__device__ __forceinline__ void attn_chunk(
    int dc, const u64 (&q2)[32], u64 (&o2)[32], float& m, float& l,
    const float (*ks)[68], const float (*vs)[68])
{
    for (int db = 0; db < (FULL ? 32 : dc); db += 16) {
        float s[16];
        float mx = m;
#pragma unroll
        for (int j = 0; j < 16; j++) {
            if (FULL || db + j < dc) {
                const u64* kr = (const u64*)&ks[db + j][0];
                u64 t0 = 0ull, t1 = 0ull, t2 = 0ull, t3 = 0ull;
#pragma unroll
                for (int c2 = 0; c2 < 32; c2 += 4) {
                    fma2(t0, q2[c2 + 0], kr[c2 + 0]);
                    fma2(t1, q2[c2 + 1], kr[c2 + 1]);
                    fma2(t2, q2[c2 + 2], kr[c2 + 2]);
                    fma2(t3, q2[c2 + 3], kr[c2 + 3]);
                }
                add2(t0, t0, t1); add2(t2, t2, t3); add2(t0, t0, t2);
                float a, b; unpack2(t0, a, b);
                float sv = a + b;
                s[j] = sv;
                mx = fmaxf(mx, sv);
            }
        }
        float alpha = __expf(m - mx);
        m = mx;
        l *= alpha;
        u64 ad = dup2(alpha);
#pragma unroll
        for (int c2 = 0; c2 < 32; c2++) mul2(o2[c2], o2[c2], ad);
#pragma unroll
        for (int j = 0; j < 16; j++) {
            if (FULL || db + j < dc) {
                float w = __expf(s[j] - m);
                l += w;
                u64 wd = dup2(w);
                const u64* vr = (const u64*)&vs[db + j][0];
#pragma unroll
                for (int c2 = 0; c2 < 32; c2++) fma2(o2[c2], wd, vr[c2]);
            }
        }
    }
}

__global__ __launch_bounds__(128) void attn_kernel(const float* __restrict__ tau)
{
    int head = blockIdx.y;
    int g = head & 7;
    int qi = blockIdx.x * 128 + threadIdx.x;

    const float* qg = g_q + (size_t)head * 64 * HW;
    const float* kT = g_kT + (size_t)head * DS * 64;
    const float* vT = g_vT + (size_t)head * DS * 64;
    float tv = tau[g];

    u64 q2[32];
#pragma unroll
    for (int c2 = 0; c2 < 32; c2++)
        q2[c2] = pack2(tv * qg[(2 * c2) * HW + qi], tv * qg[(2 * c2 + 1) * HW + qi]);

    u64 o2[32];
#pragma unroll
    for (int c2 = 0; c2 < 32; c2++) o2[c2] = 0ull;
    float m = -1e30f, l = 0.f;

    __shared__ float ks[2][32][68];
    __shared__ float vs[2][32][68];
    const int NCH = (DS + 31) / 32;

    auto fill = [&](int b, int d0) {
        for (int i = threadIdx.x; i < 512; i += 128) {
            int dd = i >> 4, c4 = i & 15;
            bool p = (d0 + dd) < DS;
            const float* sk = p ? (kT + (size_t)(d0 + dd) * 64 + c4 * 4) : kT;
            const float* sv = p ? (vT + (size_t)(d0 + dd) * 64 + c4 * 4) : vT;
            cpa16(s2u(&ks[b][dd][c4 * 4]), sk, p);
            cpa16(s2u(&vs[b][dd][c4 * 4]), sv, p);
        }
    };

    fill(0, 0);
    CP_COMMIT();
    for (int ch = 0; ch < NCH; ch++) {
        if (ch + 1 < NCH) fill((ch + 1) & 1, (ch + 1) * 32);
        CP_COMMIT();
        CP_WAIT1();
        __syncthreads();
        int dc = min(32, DS - ch * 32);
        int b = ch & 1;
        if (dc == 32) attn_chunk<true >(dc, q2, o2, m, l, ks[b], vs[b]);
        else          attn_chunk<false>(dc, q2, o2, m, l, ks[b], vs[b]);
        __syncthreads();
    }

    float inv = 1.f / l;
    uint32_t* ah = (uint32_t*)g_ah + ((size_t)head * HW + qi) * 32;
    uint32_t* al = (uint32_t*)g_al + ((size_t)head * HW + qi) * 32;
#pragma unroll
    for (int c2 = 0; c2 < 32; c2++) {
        float a, b;
        unpack2(o2[c2], a, b);
        a *= inv; b *= inv;
        uint32_t ha, la, hb, lb;
        bsplit(a, ha, la); bsplit(b, hb, lb);
        ah[c2] = ha | (hb << 16);
        al[c2] = la | (lb << 16);
    }
}

// ------------------------------------------------------------------
// Kernel 4: LSTM pointwise update
// ------------------------------------------------------------------
__global__ void final_kernel(const float* __restrict__ cold, float* __restrict__ out)
{
    int idx = blockIdx.x * 256 + threadIdx.x;
    if (idx >= TOT) return;
    float pi = g_gates[0][idx];
    float pf = g_gates[1][idx];
    float pg = g_gates[2][idx];
    float po = g_gates[3][idx];
    float ig = 1.f / (1.f + __expf(-pi));
    float fg = 1.f / (1.f + __expf(-pf));
    float gg = tanhf(pg);
    float og = 1.f / (1.f + __expf(-po));
    float cn = fg * cold[idx] + ig * gg;
    out[idx] = og * tanhf(cn);
}

// ------------------------------------------------------------------
extern "C" void kernel_launch(void* const* d_in, const int* in_sizes, int n_in,
                              void* d_out, int out_size)
{
    const float* x_in = (const float*)d_in[0];
    const float* h    = (const float*)d_in[1];
    const float* c    = (const float*)d_in[2];
    const float* tau  = (const float*)d_in[3];
    const float* Wx   = (const float*)d_in[4];
    const float* Wig  = (const float*)d_in[5];
    const float* Wq   = (const float*)d_in[6];
    const float* Wk   = (const float*)d_in[7];
    const float* Wv   = (const float*)d_in[8];
    const float* Wia  = (const float*)d_in[9];
    const float* Wix  = (const float*)d_in[10];
    const float* bi   = (const float*)d_in[11];
    const float* Wfa  = (const float*)d_in[12];
    const float* Wfx  = (const float*)d_in[13];
    const float* bf   = (const float*)d_in[14];
    const float* Wga  = (const float*)d_in[15];
    const float* Wgx  = (const float*)d_in[16];
    const float* bg   = (const float*)d_in[17];
    const float* Woa  = (const float*)d_in[18];
    const float* Wox  = (const float*)d_in[19];
    const float* bo   = (const float*)d_in[20];
    float* out = (float*)d_out;

    const int SMEM = 2 * 49152;   // 96 KB dynamic
    static int smem_set = -1;
    if (smem_set < 0) {
        cudaFuncSetAttribute(conv_kernel,
                             cudaFuncAttributeMaxDynamicSharedMemorySize, SMEM);
        smem_set = 1;
    }

    prep_w<<<8512, 256>>>(Wq, Wk, Wv, Wix, Wfx, Wgx, Wox, Wia, Wfa, Wga, Woa);
    proj_kernel<<<dim3(18, 8, 2), 256>>>(x_in, h, Wx, Wig);
    conv_kernel<<<dim3(18, 16, 3), 128, SMEM>>>(0, nullptr, nullptr, nullptr, nullptr);
    attn_kernel<<<dim3(18, 16), 128>>>(tau);
    conv_kernel<<<dim3(18, 16, 4), 128, SMEM>>>(3, bi, bf, bg, bo);
    final_kernel<<<(TOT + 255) / 256, 256>>>(c, out);
}

// round 7
// speedup vs baseline: 3.1730x; 1.5834x over previous
#include <cuda_runtime.h>
#include <cuda_bf16.h>
#include <math.h>
#include <stdint.h>

#define NB   2
#define CINC 256
#define CT   512
#define HH   48
#define HW   2304
#define DS   2116
#define DPAD 2176
#define TOT  (NB*CT*HW)

typedef unsigned long long u64;

// ---------------- packed f32x2 helpers ----------------
__device__ __forceinline__ u64 dup2(float x) {
    u64 r; asm("mov.b64 %0, {%1,%1};" : "=l"(r) : "f"(x)); return r;
}
__device__ __forceinline__ void unpack2(u64 x, float& a, float& b) {
    asm("mov.b64 {%0,%1}, %2;" : "=f"(a), "=f"(b) : "l"(x));
}
__device__ __forceinline__ void fma2(u64& d, u64 a, u64 b) {
    asm("fma.rn.f32x2 %0, %1, %2, %0;" : "+l"(d) : "l"(a), "l"(b));
}

// bf16 2-term split: v ~= hi + lo
__device__ __forceinline__ void bsplit(float v, uint32_t& h16, uint32_t& l16) {
    __nv_bfloat16 bh = __float2bfloat16(v);
    __nv_bfloat16 bl = __float2bfloat16(v - __bfloat162float(bh));
    h16 = (uint32_t)__bfloat16_as_ushort(bh);
    l16 = (uint32_t)__bfloat16_as_ushort(bl);
}
// pack 2 fp32 -> bf16x2 (lo in low half)
__device__ __forceinline__ uint32_t packbf(float lo, float hi) {
    uint32_t r;
    asm("cvt.rn.bf16x2.f32 %0, %1, %2;" : "=r"(r) : "f"(hi), "f"(lo));
    return r;
}

// ---------------- scratch ----------------
#define XHPS (16 * HW * 128)
__device__ __align__(256) __nv_bfloat16 g_xhp[2 * XHPS];       // [split][hd][px][128]
__device__ __align__(256) uint32_t g_wb32[7 * 8 * 19 * 4096];   // weight imgs hi/lo
__device__ __align__(256) __nv_bfloat16 g_qh[16 * HW * 64];     // q hi [hd][px][64]
__device__ __align__(256) __nv_bfloat16 g_ql[16 * HW * 64];
__device__ __align__(256) __nv_bfloat16 g_kh[16 * DPAD * 64];   // k hi [hd][d][64]
__device__ __align__(256) __nv_bfloat16 g_kl[16 * DPAD * 64];
__device__ __align__(256) __nv_bfloat16 g_vh[16 * DPAD * 64];
__device__ __align__(256) __nv_bfloat16 g_vl[16 * DPAD * 64];
__device__ __align__(256) __nv_bfloat16 g_ah[16 * HW * 64];     // a hi [hd][px][64]
__device__ __align__(256) __nv_bfloat16 g_al[16 * HW * 64];
__device__ __align__(256) float g_gates[4][TOT];

// ---------------- cp.async ----------------
__device__ __forceinline__ uint32_t s2u(const void* p) {
    return (uint32_t)__cvta_generic_to_shared(p);
}
__device__ __forceinline__ void cpa4(uint32_t dst, const void* src, bool pred) {
    int sz = pred ? 4 : 0;
    asm volatile("cp.async.ca.shared.global [%0], [%1], 4, %2;\n"
                 :: "r"(dst), "l"(src), "r"(sz) : "memory");
}
__device__ __forceinline__ void cpa16(uint32_t dst, const void* src, bool pred) {
    int sz = pred ? 16 : 0;
    asm volatile("cp.async.cg.shared.global [%0], [%1], 16, %2;\n"
                 :: "r"(dst), "l"(src), "r"(sz) : "memory");
}
#define CP_COMMIT() asm volatile("cp.async.commit_group;\n" ::: "memory")
#define CP_WAIT0()  asm volatile("cp.async.wait_group 0;\n" ::: "memory")
#define CP_WAIT1()  asm volatile("cp.async.wait_group 1;\n" ::: "memory")

// ---------------- mma.sync helpers ----------------
#define LDSM4(r, a) \
    asm volatile("ldmatrix.sync.aligned.m8n8.x4.shared.b16 {%0,%1,%2,%3}, [%4];" \
                 : "=r"((r)[0]), "=r"((r)[1]), "=r"((r)[2]), "=r"((r)[3]) : "r"(a))
#define LDSM4T(r, a) \
    asm volatile("ldmatrix.sync.aligned.m8n8.x4.trans.shared.b16 {%0,%1,%2,%3}, [%4];" \
                 : "=r"((r)[0]), "=r"((r)[1]), "=r"((r)[2]), "=r"((r)[3]) : "r"(a))

__device__ __forceinline__ void mma16816(float* d, const uint32_t* a,
                                         uint32_t b0, uint32_t b1) {
    asm volatile(
        "mma.sync.aligned.m16n8k16.row.col.f32.bf16.bf16.f32 "
        "{%0,%1,%2,%3}, {%4,%5,%6,%7}, {%8,%9}, {%0,%1,%2,%3};"
        : "+f"(d[0]), "+f"(d[1]), "+f"(d[2]), "+f"(d[3])
        : "r"(a[0]), "r"(a[1]), "r"(a[2]), "r"(a[3]), "r"(b0), "r"(b1));
}

// ------------------------------------------------------------------
// Kernel 0: weight prep (unchanged)
// ------------------------------------------------------------------
__global__ void prep_w(const float* __restrict__ Wq, const float* __restrict__ Wk,
                       const float* __restrict__ Wv,
                       const float* __restrict__ Wix, const float* __restrict__ Wfx,
                       const float* __restrict__ Wgx, const float* __restrict__ Wox,
                       const float* __restrict__ Wia, const float* __restrict__ Wfa,
                       const float* __restrict__ Wga, const float* __restrict__ Woa)
{
    int idx = blockIdx.x * 256 + threadIdx.x;
    if (idx >= 7 * 8 * 19 * 64 * 32) return;
    int c2    = idx & 31;
    int oc    = (idx >> 5) & 63;
    int rem   = idx >> 11;
    int chunk = rem % 19;
    int g     = (rem / 19) & 7;
    int type  = rem / 152;
    if (type < 3 && chunk == 18) return;

    float w0, w1;
    if (chunk < 18) {
        const float* W3 = (type == 0) ? Wq : (type == 1) ? Wk : (type == 2) ? Wv :
                          (type == 3) ? Wix : (type == 4) ? Wfx : (type == 5) ? Wgx : Wox;
        int t9 = chunk >> 1, cb = chunk & 1;
        size_t b = ((size_t)(g * 64 + oc) * 128 + cb * 64 + c2 * 2) * 9 + t9;
        w0 = W3[b]; w1 = W3[b + 9];
    } else {
        const float* Wa = (type == 3) ? Wia : (type == 4) ? Wfa : (type == 5) ? Wga : Woa;
        size_t b = (size_t)(g * 64 + oc) * 64 + c2 * 2;
        w0 = Wa[b]; w1 = Wa[b + 1];
    }
    uint32_t h0, l0, h1, l1;
    bsplit(w0, h0, l0); bsplit(w1, h1, l1);
    size_t tb = (size_t)rem * 4096;
    g_wb32[tb + oc * 32 + c2]        = h0 | (h1 << 16);
    g_wb32[tb + 2048 + oc * 32 + c2] = l0 | (l1 << 16);
}

// ------------------------------------------------------------------
// Kernel 1: proj_x GEMM (FFMA2) -> emit xh bf16 hi/lo pixel-major
// ------------------------------------------------------------------
__global__ __launch_bounds__(256) void proj_kernel(
    const float* __restrict__ x_in, const float* __restrict__ h,
    const float* __restrict__ Wx,  const float* __restrict__ Wig)
{
    int px0 = blockIdx.x * 128;
    int g   = blockIdx.y;
    int n   = blockIdx.z;
    int tid = threadIdx.x;
    int toc = tid >> 5;
    int tp  = tid & 31;

    __shared__ float As[3][16][68];
    __shared__ float Bs[3][16][128];

    u64 acc2[4][4];
#pragma unroll
    for (int i = 0; i < 4; i++)
#pragma unroll
        for (int j = 0; j < 4; j++) acc2[i][j] = 0ull;

    const float* inp0 = x_in + n * CINC * HW;
    const float* inp1 = h + n * CT * HW;
    const int ROUNDS = 48;

    auto fill = [&](int s, int r) {
        const float* Wp; const float* inp; int Kd, k0;
        if (r < 16) { Wp = Wx;  inp = inp0; Kd = CINC; k0 = r * 16; }
        else        { Wp = Wig; inp = inp1; Kd = CT;   k0 = (r - 16) * 16; }
        for (int i = tid; i < 1024; i += 256) {
            int kk = i & 15, co = i >> 4;
            cpa4(s2u(&As[s][kk][co]), Wp + (g * 64 + co) * Kd + k0 + kk, true);
        }
        for (int i = tid; i < 512; i += 256) {
            int kk = i >> 5, p4 = i & 31;
            cpa16(s2u(&Bs[s][kk][p4 * 4]), inp + (k0 + kk) * HW + px0 + p4 * 4, true);
        }
    };

    fill(0, 0); CP_COMMIT();
    fill(1, 1); CP_COMMIT();
    for (int r = 0; r < ROUNDS; r++) {
        CP_WAIT1();
        __syncthreads();
        if (r + 2 < ROUNDS) fill((r + 2) % 3, r + 2);
        CP_COMMIT();
        int b = r % 3;
#pragma unroll
        for (int kk = 0; kk < 16; kk++) {
            const u64* ap = (const u64*)&As[b][kk][toc * 8];
            u64 a2[4] = {ap[0], ap[1], ap[2], ap[3]};
            float4 bv4 = *(const float4*)&Bs[b][kk][tp * 4];
            u64 bd[4] = {dup2(bv4.x), dup2(bv4.y), dup2(bv4.z), dup2(bv4.w)};
#pragma unroll
            for (int i2 = 0; i2 < 4; i2++)
#pragma unroll
                for (int j = 0; j < 4; j++) fma2(acc2[i2][j], a2[i2], bd[j]);
        }
    }

    int hd = n * 8 + g;
    uint32_t* xhh = (uint32_t*)g_xhp;
    uint32_t* xhl = (uint32_t*)(g_xhp + XHPS);
#pragma unroll
    for (int i2 = 0; i2 < 4; i2++) {
#pragma unroll
        for (int j = 0; j < 4; j++) {
            float v0, v1; unpack2(acc2[i2][j], v0, v1);
            uint32_t h0, l0, h1, l1;
            bsplit(v0, h0, l0); bsplit(v1, h1, l1);
            size_t of = ((size_t)hd * HW + px0 + tp * 4 + j) * 64 + toc * 4 + i2;
            xhh[of] = h0 | (h1 << 16);
            xhl[of] = l0 | (l1 << 16);
        }
    }
#pragma unroll
    for (int i2 = 0; i2 < 4; i2++) {
        int oc = toc * 8 + 2 * i2;
        const float* h0p = h + ((size_t)(n * CT + g * 64 + oc)) * HW + px0 + tp * 4;
        const float* h1p = h0p + HW;
#pragma unroll
        for (int j = 0; j < 4; j++) {
            uint32_t a0, b0, a1, b1;
            bsplit(h0p[j], a0, b0); bsplit(h1p[j], a1, b1);
            size_t of = ((size_t)hd * HW + px0 + tp * 4 + j) * 64 + 32 + toc * 4 + i2;
            xhh[of] = a0 | (a1 << 16);
            xhl[of] = b0 | (b1 << 16);
        }
    }
}

// ------------------------------------------------------------------
// Kernel 2: mma.sync conv GEMM (q/k/v emit bf16 hi/lo; gates fp32+bias)
// ------------------------------------------------------------------
__global__ __launch_bounds__(128) void conv_kernel(
    int base_type,
    const float* __restrict__ bbi, const float* __restrict__ bbf,
    const float* __restrict__ bbg, const float* __restrict__ bbo)
{
    extern __shared__ char smem[];
    uint32_t sb = s2u(smem);
    const int tid = threadIdx.x, wid = tid >> 5, lane = tid & 31;
    const int type = base_type + blockIdx.z;
    const int hd = blockIdx.y, g = hd & 7;
    const int tile = blockIdx.x;
    const int NCH = (type < 3) ? 18 : 19;

    const int px = tile * 128 + tid;
    const int py = px / 48, pxx = px - py * 48;
    const size_t wtb = (size_t)((type * 8 + g) * 19) * 4096;

    auto fill = [&](int s, int k) {
        uint32_t base = sb + s * 49152;
        const char *sh, *sl; bool in;
        if (k < 18) {
            int t9 = k >> 1, cb = k & 1, ky = t9 / 3, kx = t9 - ky * 3;
            int iy = py + ky - 1, ix = pxx + kx - 1;
            in = ((unsigned)iy < 48u) && ((unsigned)ix < 48u);
            const __nv_bfloat16* r =
                g_xhp + (((size_t)hd * HW + iy * 48 + ix) * 128 + cb * 64);
            if (!in) r = g_xhp;
            sh = (const char*)r;
            sl = (const char*)(r + XHPS);
        } else {
            in = true;
            sh = (const char*)(g_ah + ((size_t)hd * HW + px) * 64);
            sl = (const char*)(g_al + ((size_t)hd * HW + px) * 64);
        }
        uint32_t arow = base + tid * 128;
        uint32_t sw = (tid & 7) << 4;
#pragma unroll
        for (int gc = 0; gc < 8; gc++) {
            uint32_t off = (gc * 16) ^ sw;
            cpa16(arow + off, sh + gc * 16, in);
            cpa16(arow + 16384 + off, sl + gc * 16, in);
        }
        const uint32_t* wsrc = g_wb32 + wtb + (size_t)k * 4096;
#pragma unroll
        for (int i = 0; i < 4; i++) {
            int p = tid + i * 128;
            int oc = p >> 3, gr = p & 7;
            uint32_t off = oc * 128 + ((gr * 16) ^ ((oc & 7) << 4));
            cpa16(base + 32768 + off, wsrc + p * 4, true);
            cpa16(base + 40960 + off, wsrc + 2048 + p * 4, true);
        }
    };

    float acc[2][8][4];
#pragma unroll
    for (int mt = 0; mt < 2; mt++)
#pragma unroll
        for (int nt = 0; nt < 8; nt++)
#pragma unroll
            for (int i = 0; i < 4; i++) acc[mt][nt][i] = 0.f;

    fill(0, 0); CP_COMMIT();
    fill(1, 1); CP_COMMIT();

    const int lsub = lane >> 3;
    const int lrow = lane & 7;

    for (int k = 0; k < NCH; k++) {
        int s = k & 1;
        if (k + 1 < NCH) { CP_WAIT1(); } else { CP_WAIT0(); }
        __syncthreads();
        uint32_t Ab = sb + s * 49152;
        uint32_t Bb = Ab + 32768;
#pragma unroll
        for (int ks = 0; ks < 4; ks++) {
            uint32_t ah[2][4], al[2][4];
#pragma unroll
            for (int mt = 0; mt < 2; mt++) {
                int r = wid * 32 + mt * 16 + (lsub & 1) * 8 + lrow;
                uint32_t gran = ks * 2 + (lsub >> 1);
                uint32_t addr = Ab + r * 128 + ((gran * 16) ^ ((r & 7) << 4));
                LDSM4(ah[mt], addr);
                LDSM4(al[mt], addr + 16384);
            }
            uint32_t bh[4][4], bl[4][4];
#pragma unroll
            for (int p = 0; p < 4; p++) {
                int n = p * 16 + (lsub >> 1) * 8 + lrow;
                uint32_t gran = ks * 2 + (lsub & 1);
                uint32_t addr = Bb + n * 128 + ((gran * 16) ^ ((n & 7) << 4));
                LDSM4(bh[p], addr);
                LDSM4(bl[p], addr + 8192);
            }
#pragma unroll
            for (int mt = 0; mt < 2; mt++) {
#pragma unroll
                for (int p = 0; p < 4; p++) {
                    mma16816(acc[mt][2 * p],     ah[mt], bh[p][0], bh[p][1]);
                    mma16816(acc[mt][2 * p + 1], ah[mt], bh[p][2], bh[p][3]);
                    mma16816(acc[mt][2 * p],     ah[mt], bl[p][0], bl[p][1]);
                    mma16816(acc[mt][2 * p + 1], ah[mt], bl[p][2], bl[p][3]);
                    mma16816(acc[mt][2 * p],     al[mt], bh[p][0], bh[p][1]);
                    mma16816(acc[mt][2 * p + 1], al[mt], bh[p][2], bh[p][3]);
                }
            }
        }
        __syncthreads();
        if (k + 2 < NCH) fill(s, k + 2);
        CP_COMMIT();
    }

    // epilogue
    uint32_t* qh32 = (uint32_t*)g_qh;
    uint32_t* ql32 = (uint32_t*)g_ql;
#pragma unroll
    for (int mt = 0; mt < 2; mt++) {
#pragma unroll
        for (int half = 0; half < 2; half++) {
            int m = tile * 128 + wid * 32 + mt * 16 + (lane >> 2) + half * 8;
            if (type == 0) {
                size_t rb = ((size_t)hd * HW + m) * 32;
#pragma unroll
                for (int nt = 0; nt < 8; nt++) {
                    int ocp = nt * 4 + (lane & 3);
                    uint32_t h0, l0, h1, l1;
                    bsplit(acc[mt][nt][half * 2],     h0, l0);
                    bsplit(acc[mt][nt][half * 2 + 1], h1, l1);
                    qh32[rb + ocp] = h0 | (h1 << 16);
                    ql32[rb + ocp] = l0 | (l1 << 16);
                }
            } else if (type < 3) {
                int oy = m / 48, ox = m - oy * 48;
                if (oy >= 1 && oy <= 46 && ox >= 1 && ox <= 46) {
                    int d = (oy - 1) * 46 + (ox - 1);
                    size_t rb = ((size_t)hd * DPAD + d) * 32;
                    uint32_t* dh = (uint32_t*)((type == 1) ? g_kh : g_vh);
                    uint32_t* dl = (uint32_t*)((type == 1) ? g_kl : g_vl);
#pragma unroll
                    for (int nt = 0; nt < 8; nt++) {
                        int ocp = nt * 4 + (lane & 3);
                        uint32_t h0, l0, h1, l1;
                        bsplit(acc[mt][nt][half * 2],     h0, l0);
                        bsplit(acc[mt][nt][half * 2 + 1], h1, l1);
                        dh[rb + ocp] = h0 | (h1 << 16);
                        dl[rb + ocp] = l0 | (l1 << 16);
                    }
                }
            } else {
                int z = type - 3;
                const float* bb = (z == 0) ? bbi : (z == 1) ? bbf
                                : (z == 2) ? bbg : bbo;
                float* dst = g_gates[z] + (size_t)hd * 64 * HW + m;
#pragma unroll
                for (int nt = 0; nt < 8; nt++) {
                    int oc = nt * 8 + (lane & 3) * 2;
                    dst[(size_t)oc * HW]       = acc[mt][nt][half * 2]     + bb[g * 64 + oc];
                    dst[(size_t)(oc + 1) * HW] = acc[mt][nt][half * 2 + 1] + bb[g * 64 + oc + 1];
                }
            }
        }
    }
}

// ------------------------------------------------------------------
// Kernel 3: flash attention on mma.sync.  grid (18 q-tiles, 16 heads),
// 128 threads.  Q[128x64] resident in smem (hi/lo); K/V in 64-key
// chunks (hi/lo), double-buffered.  S and O in register fragments.
// SMEM: Qh 16K | Ql 16K | 2 x (Kh 8K | Kl 8K | Vh 8K | Vl 8K) = 96K.
// ------------------------------------------------------------------
__global__ __launch_bounds__(128) void attn_kernel(const float* __restrict__ tau)
{
    extern __shared__ char smem[];
    uint32_t sb = s2u(smem);
    const int tid = threadIdx.x, wid = tid >> 5, lane = tid & 31;
    const int hd = blockIdx.y, g = hd & 7;
    const int tile = blockIdx.x;
    const int lsub = lane >> 3, lrow = lane & 7;
    const float tv = tau[g];
    const int NCHK = (DS + 63) / 64;   // 34

    // ---- fill Q (once) ----
    {
        int r = tid;
        const char* qh = (const char*)g_qh + ((size_t)hd * HW + tile * 128 + r) * 128;
        const char* ql = (const char*)g_ql + ((size_t)hd * HW + tile * 128 + r) * 128;
        uint32_t sw = (r & 7) << 4;
#pragma unroll
        for (int gc = 0; gc < 8; gc++) {
            uint32_t off = r * 128 + ((gc * 16) ^ sw);
            cpa16(sb + off, qh + gc * 16, true);
            cpa16(sb + 16384 + off, ql + gc * 16, true);
        }
    }
    // ---- K/V chunk fill ----
    auto fillkv = [&](int s, int c) {
        uint32_t base = sb + 32768 + s * 32768;
        int r = tid >> 1;
        int g4 = (tid & 1) * 4;
        int d = c * 64 + r;
        bool ok = d < DS;
        size_t rb = ((size_t)hd * DPAD + (ok ? d : 0)) * 128;
        const char* kh = (const char*)g_kh + rb;
        const char* kl = (const char*)g_kl + rb;
        const char* vh = (const char*)g_vh + rb;
        const char* vl = (const char*)g_vl + rb;
        uint32_t sw = (r & 7) << 4;
#pragma unroll
        for (int gg = 0; gg < 4; gg++) {
            int gran = g4 + gg;
            uint32_t off = r * 128 + ((gran * 16) ^ sw);
            cpa16(base + off,         kh + gran * 16, ok);
            cpa16(base + 8192 + off,  kl + gran * 16, ok);
            cpa16(base + 16384 + off, vh + gran * 16, ok);
            cpa16(base + 24576 + off, vl + gran * 16, ok);
        }
    };

    fillkv(0, 0); CP_COMMIT();
    fillkv(1, 1); CP_COMMIT();

    float o[2][8][4];
#pragma unroll
    for (int mt = 0; mt < 2; mt++)
#pragma unroll
        for (int nt = 0; nt < 8; nt++)
#pragma unroll
            for (int i = 0; i < 4; i++) o[mt][nt][i] = 0.f;
    float mrow[2][2] = {{-1e30f, -1e30f}, {-1e30f, -1e30f}};
    float lrow_[2][2] = {{0.f, 0.f}, {0.f, 0.f}};

    for (int c = 0; c < NCHK; c++) {
        int s = c & 1;
        if (c + 1 < NCHK) { CP_WAIT1(); } else { CP_WAIT0(); }
        __syncthreads();
        uint32_t Qb = sb;
        uint32_t Kb = sb + 32768 + s * 32768;
        uint32_t Vb = Kb + 16384;

        // ---- S = Q K^T (3-pass bf16 split) ----
        float sf[2][8][4];
#pragma unroll
        for (int mt = 0; mt < 2; mt++)
#pragma unroll
            for (int nt = 0; nt < 8; nt++)
#pragma unroll
                for (int i = 0; i < 4; i++) sf[mt][nt][i] = 0.f;
#pragma unroll
        for (int ks = 0; ks < 4; ks++) {
            uint32_t ah[2][4], al[2][4];
#pragma unroll
            for (int mt = 0; mt < 2; mt++) {
                int r = wid * 32 + mt * 16 + (lsub & 1) * 8 + lrow;
                uint32_t gran = ks * 2 + (lsub >> 1);
                uint32_t addr = Qb + r * 128 + ((gran * 16) ^ ((r & 7) << 4));
                LDSM4(ah[mt], addr);
                LDSM4(al[mt], addr + 16384);
            }
            uint32_t bh[4][4], bl[4][4];
#pragma unroll
            for (int p = 0; p < 4; p++) {
                int n = p * 16 + (lsub >> 1) * 8 + lrow;
                uint32_t gran = ks * 2 + (lsub & 1);
                uint32_t addr = Kb + n * 128 + ((gran * 16) ^ ((n & 7) << 4));
                LDSM4(bh[p], addr);
                LDSM4(bl[p], addr + 8192);
            }
#pragma unroll
            for (int mt = 0; mt < 2; mt++) {
#pragma unroll
                for (int p = 0; p < 4; p++) {
                    mma16816(sf[mt][2 * p],     ah[mt], bh[p][0], bh[p][1]);
                    mma16816(sf[mt][2 * p + 1], ah[mt], bh[p][2], bh[p][3]);
                    mma16816(sf[mt][2 * p],     ah[mt], bl[p][0], bl[p][1]);
                    mma16816(sf[mt][2 * p + 1], ah[mt], bl[p][2], bl[p][3]);
                    mma16816(sf[mt][2 * p],     al[mt], bh[p][0], bh[p][1]);
                    mma16816(sf[mt][2 * p + 1], al[mt], bh[p][2], bh[p][3]);
                }
            }
        }

        // ---- online softmax on fragments ----
        int dbase = c * 64 + (lane & 3) * 2;
        float alpha[2][2];
#pragma unroll
        for (int mt = 0; mt < 2; mt++) {
#pragma unroll
            for (int h = 0; h < 2; h++) {
                float mx = mrow[mt][h];
#pragma unroll
                for (int nt = 0; nt < 8; nt++) {
#pragma unroll
                    for (int e = 0; e < 2; e++) {
                        int d = dbase + nt * 8 + e;
                        float v = (d < DS) ? tv * sf[mt][nt][h * 2 + e] : -1e30f;
                        sf[mt][nt][h * 2 + e] = v;
                        mx = fmaxf(mx, v);
                    }
                }
                mx = fmaxf(mx, __shfl_xor_sync(0xffffffffu, mx, 1));
                mx = fmaxf(mx, __shfl_xor_sync(0xffffffffu, mx, 2));
                float al_ = __expf(mrow[mt][h] - mx);
                mrow[mt][h] = mx;
                alpha[mt][h] = al_;
                float ls = lrow_[mt][h] * al_;
#pragma unroll
                for (int nt = 0; nt < 8; nt++) {
#pragma unroll
                    for (int e = 0; e < 2; e++) {
                        float p = __expf(sf[mt][nt][h * 2 + e] - mx);
                        sf[mt][nt][h * 2 + e] = p;
                        ls += p;
                    }
                }
                lrow_[mt][h] = ls;
            }
        }
        // rescale O
#pragma unroll
        for (int mt = 0; mt < 2; mt++)
#pragma unroll
            for (int nt = 0; nt < 8; nt++) {
                o[mt][nt][0] *= alpha[mt][0];
                o[mt][nt][1] *= alpha[mt][0];
                o[mt][nt][2] *= alpha[mt][1];
                o[mt][nt][3] *= alpha[mt][1];
            }

        // ---- O += P V (3-pass) ----
#pragma unroll
        for (int kt = 0; kt < 4; kt++) {
            uint32_t vh[4][4], vl[4][4];
#pragma unroll
            for (int np = 0; np < 4; np++) {
                int rr = kt * 16 + (lane & 15);
                uint32_t gran = np * 2 + (lane >> 4);
                uint32_t addr = Vb + rr * 128 + ((gran * 16) ^ ((rr & 7) << 4));
                LDSM4T(vh[np], addr);
                LDSM4T(vl[np], addr + 8192);
            }
#pragma unroll
            for (int mt = 0; mt < 2; mt++) {
                uint32_t pah[4], pal[4];
#pragma unroll
                for (int i = 0; i < 4; i++) {
                    int nt = 2 * kt + (i >> 1);
                    float p0 = sf[mt][nt][(i & 1) * 2];
                    float p1 = sf[mt][nt][(i & 1) * 2 + 1];
                    uint32_t ph = packbf(p0, p1);
                    float r0 = p0 - __uint_as_float(ph << 16);
                    float r1 = p1 - __uint_as_float(ph & 0xffff0000u);
                    pah[i] = ph;
                    pal[i] = packbf(r0, r1);
                }
#pragma unroll
                for (int np = 0; np < 4; np++) {
                    mma16816(o[mt][2 * np],     pah, vh[np][0], vh[np][1]);
                    mma16816(o[mt][2 * np + 1], pah, vh[np][2], vh[np][3]);
                    mma16816(o[mt][2 * np],     pal, vh[np][0], vh[np][1]);
                    mma16816(o[mt][2 * np + 1], pal, vh[np][2], vh[np][3]);
                    mma16816(o[mt][2 * np],     pah, vl[np][0], vl[np][1]);
                    mma16816(o[mt][2 * np + 1], pah, vl[np][2], vl[np][3]);
                }
            }
        }
        __syncthreads();
        if (c + 2 < NCHK) fillkv(s, c + 2);
        CP_COMMIT();
    }

    // ---- finalize: reduce l across quad, normalize, emit bf16 hi/lo ----
    uint32_t* ah32 = (uint32_t*)g_ah;
    uint32_t* al32 = (uint32_t*)g_al;
#pragma unroll
    for (int mt = 0; mt < 2; mt++) {
#pragma unroll
        for (int h = 0; h < 2; h++) {
            float l = lrow_[mt][h];
            l += __shfl_xor_sync(0xffffffffu, l, 1);
            l += __shfl_xor_sync(0xffffffffu, l, 2);
            float inv = 1.f / l;
            int m = tile * 128 + wid * 32 + mt * 16 + (lane >> 2) + h * 8;
            size_t rb = ((size_t)hd * HW + m) * 32;
#pragma unroll
            for (int nt = 0; nt < 8; nt++) {
                int ocp = nt * 4 + (lane & 3);
                float v0 = o[mt][nt][h * 2] * inv;
                float v1 = o[mt][nt][h * 2 + 1] * inv;
                uint32_t h0, l0, h1, l1;
                bsplit(v0, h0, l0); bsplit(v1, h1, l1);
                ah32[rb + ocp] = h0 | (h1 << 16);
                al32[rb + ocp] = l0 | (l1 << 16);
            }
        }
    }
}

// ------------------------------------------------------------------
// Kernel 4: LSTM pointwise update
// ------------------------------------------------------------------
__global__ void final_kernel(const float* __restrict__ cold, float* __restrict__ out)
{
    int idx = blockIdx.x * 256 + threadIdx.x;
    if (idx >= TOT) return;
    float pi = g_gates[0][idx];
    float pf = g_gates[1][idx];
    float pg = g_gates[2][idx];
    float po = g_gates[3][idx];
    float ig = 1.f / (1.f + __expf(-pi));
    float fg = 1.f / (1.f + __expf(-pf));
    float gg = tanhf(pg);
    float og = 1.f / (1.f + __expf(-po));
    float cn = fg * cold[idx] + ig * gg;
    out[idx] = og * tanhf(cn);
}

// ------------------------------------------------------------------
extern "C" void kernel_launch(void* const* d_in, const int* in_sizes, int n_in,
                              void* d_out, int out_size)
{
    const float* x_in = (const float*)d_in[0];
    const float* h    = (const float*)d_in[1];
    const float* c    = (const float*)d_in[2];
    const float* tau  = (const float*)d_in[3];
    const float* Wx   = (const float*)d_in[4];
    const float* Wig  = (const float*)d_in[5];
    const float* Wq   = (const float*)d_in[6];
    const float* Wk   = (const float*)d_in[7];
    const float* Wv   = (const float*)d_in[8];
    const float* Wia  = (const float*)d_in[9];
    const float* Wix  = (const float*)d_in[10];
    const float* bi   = (const float*)d_in[11];
    const float* Wfa  = (const float*)d_in[12];
    const float* Wfx  = (const float*)d_in[13];
    const float* bf   = (const float*)d_in[14];
    const float* Wga  = (const float*)d_in[15];
    const float* Wgx  = (const float*)d_in[16];
    const float* bg   = (const float*)d_in[17];
    const float* Woa  = (const float*)d_in[18];
    const float* Wox  = (const float*)d_in[19];
    const float* bo   = (const float*)d_in[20];
    float* out = (float*)d_out;

    const int CSMEM = 2 * 49152;   // conv: 96 KB
    const int ASMEM = 32768 + 2 * 32768;  // attn: 96 KB
    cudaFuncSetAttribute(conv_kernel,
                         cudaFuncAttributeMaxDynamicSharedMemorySize, CSMEM);
    cudaFuncSetAttribute(attn_kernel,
                         cudaFuncAttributeMaxDynamicSharedMemorySize, ASMEM);

    prep_w<<<8512, 256>>>(Wq, Wk, Wv, Wix, Wfx, Wgx, Wox, Wia, Wfa, Wga, Woa);
    proj_kernel<<<dim3(18, 8, 2), 256>>>(x_in, h, Wx, Wig);
    conv_kernel<<<dim3(18, 16, 3), 128, CSMEM>>>(0, nullptr, nullptr, nullptr, nullptr);
    attn_kernel<<<dim3(18, 16), 128, ASMEM>>>(tau);
    conv_kernel<<<dim3(18, 16, 4), 128, CSMEM>>>(3, bi, bf, bg, bo);
    final_kernel<<<(TOT + 255) / 256, 256>>>(c, out);
}

// round 8
// speedup vs baseline: 4.0656x; 1.2813x over previous
#include <cuda_runtime.h>
#include <cuda_bf16.h>
#include <math.h>
#include <stdint.h>

#define NB   2
#define CINC 256
#define CT   512
#define HH   48
#define HW   2304
#define DS   2116
#define DPAD 2176
#define TOT  (NB*CT*HW)

// bf16 2-term split: v ~= hi + lo
__device__ __forceinline__ void bsplit(float v, uint32_t& h16, uint32_t& l16) {
    __nv_bfloat16 bh = __float2bfloat16(v);
    __nv_bfloat16 bl = __float2bfloat16(v - __bfloat162float(bh));
    h16 = (uint32_t)__bfloat16_as_ushort(bh);
    l16 = (uint32_t)__bfloat16_as_ushort(bl);
}
__device__ __forceinline__ uint32_t packbf(float lo, float hi) {
    uint32_t r;
    asm("cvt.rn.bf16x2.f32 %0, %1, %2;" : "=r"(r) : "f"(hi), "f"(lo));
    return r;
}

// ---------------- scratch ----------------
#define XHPS (16 * HW * 128)
__device__ __align__(256) __nv_bfloat16 g_xhp[2 * XHPS];        // [split][hd][px][128]
__device__ __align__(256) uint32_t g_wb32[7 * 8 * 19 * 4096];   // conv weight imgs
__device__ __align__(256) uint32_t g_wpb32[8 * 12 * 4096];      // proj weight imgs
__device__ __align__(256) uint32_t g_apm_h[NB * HW * 384];      // proj A hi [n][px][768ch]
__device__ __align__(256) uint32_t g_apm_l[NB * HW * 384];
__device__ __align__(256) __nv_bfloat16 g_qh[16 * HW * 64];
__device__ __align__(256) __nv_bfloat16 g_ql[16 * HW * 64];
__device__ __align__(256) __nv_bfloat16 g_kh[16 * DPAD * 64];
__device__ __align__(256) __nv_bfloat16 g_kl[16 * DPAD * 64];
__device__ __align__(256) __nv_bfloat16 g_vh[16 * DPAD * 64];
__device__ __align__(256) __nv_bfloat16 g_vl[16 * DPAD * 64];
__device__ __align__(256) __nv_bfloat16 g_ah[16 * HW * 64];
__device__ __align__(256) __nv_bfloat16 g_al[16 * HW * 64];

// ---------------- cp.async ----------------
__device__ __forceinline__ uint32_t s2u(const void* p) {
    return (uint32_t)__cvta_generic_to_shared(p);
}
__device__ __forceinline__ void cpa16(uint32_t dst, const void* src, bool pred) {
    int sz = pred ? 16 : 0;
    asm volatile("cp.async.cg.shared.global [%0], [%1], 16, %2;\n"
                 :: "r"(dst), "l"(src), "r"(sz) : "memory");
}
#define CP_COMMIT() asm volatile("cp.async.commit_group;\n" ::: "memory")
#define CP_WAIT0()  asm volatile("cp.async.wait_group 0;\n" ::: "memory")
#define CP_WAIT1()  asm volatile("cp.async.wait_group 1;\n" ::: "memory")

// ---------------- mma.sync helpers ----------------
#define LDSM4(r, a) \
    asm volatile("ldmatrix.sync.aligned.m8n8.x4.shared.b16 {%0,%1,%2,%3}, [%4];" \
                 : "=r"((r)[0]), "=r"((r)[1]), "=r"((r)[2]), "=r"((r)[3]) : "r"(a))
#define LDSM4T(r, a) \
    asm volatile("ldmatrix.sync.aligned.m8n8.x4.trans.shared.b16 {%0,%1,%2,%3}, [%4];" \
                 : "=r"((r)[0]), "=r"((r)[1]), "=r"((r)[2]), "=r"((r)[3]) : "r"(a))

__device__ __forceinline__ void mma16816(float* d, const uint32_t* a,
                                         uint32_t b0, uint32_t b1) {
    asm volatile(
        "mma.sync.aligned.m16n8k16.row.col.f32.bf16.bf16.f32 "
        "{%0,%1,%2,%3}, {%4,%5,%6,%7}, {%8,%9}, {%0,%1,%2,%3};"
        : "+f"(d[0]), "+f"(d[1]), "+f"(d[2]), "+f"(d[3])
        : "r"(a[0]), "r"(a[1]), "r"(a[2]), "r"(a[3]), "r"(b0), "r"(b1));
}

// ------------------------------------------------------------------
// prep_w: conv weights -> g_wb32 (64oc x 64ch bf16 hi then lo images)
// ------------------------------------------------------------------
__global__ void prep_w(const float* __restrict__ Wq, const float* __restrict__ Wk,
                       const float* __restrict__ Wv,
                       const float* __restrict__ Wix, const float* __restrict__ Wfx,
                       const float* __restrict__ Wgx, const float* __restrict__ Wox,
                       const float* __restrict__ Wia, const float* __restrict__ Wfa,
                       const float* __restrict__ Wga, const float* __restrict__ Woa)
{
    int idx = blockIdx.x * 256 + threadIdx.x;
    if (idx >= 7 * 8 * 19 * 64 * 32) return;
    int c2    = idx & 31;
    int oc    = (idx >> 5) & 63;
    int rem   = idx >> 11;
    int chunk = rem % 19;
    int g     = (rem / 19) & 7;
    int type  = rem / 152;
    if (type < 3 && chunk == 18) return;

    float w0, w1;
    if (chunk < 18) {
        const float* W3 = (type == 0) ? Wq : (type == 1) ? Wk : (type == 2) ? Wv :
                          (type == 3) ? Wix : (type == 4) ? Wfx : (type == 5) ? Wgx : Wox;
        int t9 = chunk >> 1, cb = chunk & 1;
        size_t b = ((size_t)(g * 64 + oc) * 128 + cb * 64 + c2 * 2) * 9 + t9;
        w0 = W3[b]; w1 = W3[b + 9];
    } else {
        const float* Wa = (type == 3) ? Wia : (type == 4) ? Wfa : (type == 5) ? Wga : Woa;
        size_t b = (size_t)(g * 64 + oc) * 64 + c2 * 2;
        w0 = Wa[b]; w1 = Wa[b + 1];
    }
    uint32_t h0, l0, h1, l1;
    bsplit(w0, h0, l0); bsplit(w1, h1, l1);
    size_t tb = (size_t)rem * 4096;
    g_wb32[tb + oc * 32 + c2]        = h0 | (h1 << 16);
    g_wb32[tb + 2048 + oc * 32 + c2] = l0 | (l1 << 16);
}

// ------------------------------------------------------------------
// prep_pw: proj weights (W_x 512x256, W_ig 512x512) -> g_wpb32
// chunk 0..3 = W_x 64ch blocks, 4..11 = W_ig 64ch blocks
// ------------------------------------------------------------------
__global__ void prep_pw(const float* __restrict__ Wx, const float* __restrict__ Wig)
{
    int idx = blockIdx.x * 256 + threadIdx.x;
    if (idx >= 8 * 12 * 64 * 32) return;
    int c2    = idx & 31;
    int oc    = (idx >> 5) & 63;
    int rem   = idx >> 11;          // g*12 + chunk
    int chunk = rem % 12;
    int g     = rem / 12;

    float w0, w1;
    if (chunk < 4) {
        size_t b = (size_t)(g * 64 + oc) * 256 + chunk * 64 + c2 * 2;
        w0 = Wx[b]; w1 = Wx[b + 1];
    } else {
        size_t b = (size_t)(g * 64 + oc) * 512 + (chunk - 4) * 64 + c2 * 2;
        w0 = Wig[b]; w1 = Wig[b + 1];
    }
    uint32_t h0, l0, h1, l1;
    bsplit(w0, h0, l0); bsplit(w1, h1, l1);
    size_t tb = (size_t)rem * 4096;
    g_wpb32[tb + oc * 32 + c2]        = h0 | (h1 << 16);
    g_wpb32[tb + 2048 + oc * 32 + c2] = l0 | (l1 << 16);
}

// ------------------------------------------------------------------
// prep_x: transpose x_in(256ch)+h(512ch) -> pixel-major bf16 hi/lo
// [n][px][768] (g_apm), and write xh h-half [hd][px][32..64)u32.
// grid (18 px-blocks, 12 ch-blocks, 2 n), 256 threads.
// ------------------------------------------------------------------
__global__ __launch_bounds__(256) void prep_x(
    const float* __restrict__ x_in, const float* __restrict__ h)
{
    __shared__ float t[64][129];
    int px0 = blockIdx.x * 128;
    int chb = blockIdx.y;
    int n   = blockIdx.z;
    int tid = threadIdx.x;

    for (int i = tid; i < 64 * 128; i += 256) {
        int cl = i >> 7, p = i & 127;
        int ch = chb * 64 + cl;
        float v = (ch < 256)
            ? x_in[((size_t)n * 256 + ch) * HW + px0 + p]
            : h[((size_t)n * 512 + (ch - 256)) * HW + px0 + p];
        t[cl][p] = v;
    }
    __syncthreads();

    for (int i = tid; i < 128 * 32; i += 256) {
        int p = i >> 5, c2 = i & 31;
        float v0 = t[c2 * 2][p], v1 = t[c2 * 2 + 1][p];
        uint32_t h0, l0, h1, l1;
        bsplit(v0, h0, l0); bsplit(v1, h1, l1);
        uint32_t hv = h0 | (h1 << 16), lv = l0 | (l1 << 16);
        size_t of = ((size_t)n * HW + px0 + p) * 384 + chb * 32 + c2;
        g_apm_h[of] = hv;
        g_apm_l[of] = lv;
        if (chb >= 4) {
            int g = chb - 4;
            size_t of2 = ((size_t)(n * 8 + g) * HW + px0 + p) * 64 + 32 + c2;
            ((uint32_t*)g_xhp)[of2] = hv;
            ((uint32_t*)(g_xhp + XHPS))[of2] = lv;
        }
    }
}

// ------------------------------------------------------------------
// proj_mma: D[128px x 64oc] over K=768 (12 chunks), writes xh x-half.
// grid (18, 8 g, 2 n), 128 threads. Same recipe as round-7 conv.
// ------------------------------------------------------------------
__global__ __launch_bounds__(128) void proj_mma()
{
    extern __shared__ char smem[];
    uint32_t sb = s2u(smem);
    const int tid = threadIdx.x, wid = tid >> 5, lane = tid & 31;
    const int g = blockIdx.y, n = blockIdx.z;
    const int hd = n * 8 + g;
    const int tile = blockIdx.x;
    const int NCH = 12;
    const int px = tile * 128 + tid;

    auto fill = [&](int s, int k) {
        uint32_t base = sb + s * 49152;
        const char* sh = (const char*)(g_apm_h + ((size_t)n * HW + px) * 384 + k * 32);
        const char* sl = (const char*)(g_apm_l + ((size_t)n * HW + px) * 384 + k * 32);
        uint32_t arow = base + tid * 128;
        uint32_t sw = (tid & 7) << 4;
#pragma unroll
        for (int gc = 0; gc < 8; gc++) {
            uint32_t off = (gc * 16) ^ sw;
            cpa16(arow + off, sh + gc * 16, true);
            cpa16(arow + 16384 + off, sl + gc * 16, true);
        }
        const uint32_t* wsrc = g_wpb32 + ((size_t)(g * 12 + k)) * 4096;
#pragma unroll
        for (int i = 0; i < 4; i++) {
            int p = tid + i * 128;
            int oc = p >> 3, gr = p & 7;
            uint32_t off = oc * 128 + ((gr * 16) ^ ((oc & 7) << 4));
            cpa16(base + 32768 + off, wsrc + p * 4, true);
            cpa16(base + 40960 + off, wsrc + 2048 + p * 4, true);
        }
    };

    float acc[2][8][4];
#pragma unroll
    for (int mt = 0; mt < 2; mt++)
#pragma unroll
        for (int nt = 0; nt < 8; nt++)
#pragma unroll
            for (int i = 0; i < 4; i++) acc[mt][nt][i] = 0.f;

    fill(0, 0); CP_COMMIT();
    fill(1, 1); CP_COMMIT();
    const int lsub = lane >> 3, lrow = lane & 7;

    for (int k = 0; k < NCH; k++) {
        int s = k & 1;
        if (k + 1 < NCH) { CP_WAIT1(); } else { CP_WAIT0(); }
        __syncthreads();
        uint32_t Ab = sb + s * 49152;
        uint32_t Bb = Ab + 32768;
#pragma unroll
        for (int ks = 0; ks < 4; ks++) {
            uint32_t ah[2][4], al[2][4];
#pragma unroll
            for (int mt = 0; mt < 2; mt++) {
                int r = wid * 32 + mt * 16 + (lsub & 1) * 8 + lrow;
                uint32_t gran = ks * 2 + (lsub >> 1);
                uint32_t addr = Ab + r * 128 + ((gran * 16) ^ ((r & 7) << 4));
                LDSM4(ah[mt], addr);
                LDSM4(al[mt], addr + 16384);
            }
            uint32_t bh[4][4], bl[4][4];
#pragma unroll
            for (int p = 0; p < 4; p++) {
                int nn = p * 16 + (lsub >> 1) * 8 + lrow;
                uint32_t gran = ks * 2 + (lsub & 1);
                uint32_t addr = Bb + nn * 128 + ((gran * 16) ^ ((nn & 7) << 4));
                LDSM4(bh[p], addr);
                LDSM4(bl[p], addr + 8192);
            }
#pragma unroll
            for (int mt = 0; mt < 2; mt++) {
#pragma unroll
                for (int p = 0; p < 4; p++) {
                    mma16816(acc[mt][2 * p],     ah[mt], bh[p][0], bh[p][1]);
                    mma16816(acc[mt][2 * p + 1], ah[mt], bh[p][2], bh[p][3]);
                    mma16816(acc[mt][2 * p],     ah[mt], bl[p][0], bl[p][1]);
                    mma16816(acc[mt][2 * p + 1], ah[mt], bl[p][2], bl[p][3]);
                    mma16816(acc[mt][2 * p],     al[mt], bh[p][0], bh[p][1]);
                    mma16816(acc[mt][2 * p + 1], al[mt], bh[p][2], bh[p][3]);
                }
            }
        }
        __syncthreads();
        if (k + 2 < NCH) fill(s, k + 2);
        CP_COMMIT();
    }

    uint32_t* xhh = (uint32_t*)g_xhp;
    uint32_t* xhl = (uint32_t*)(g_xhp + XHPS);
#pragma unroll
    for (int mt = 0; mt < 2; mt++) {
#pragma unroll
        for (int half = 0; half < 2; half++) {
            int m = tile * 128 + wid * 32 + mt * 16 + (lane >> 2) + half * 8;
            size_t rb = ((size_t)hd * HW + m) * 64;
#pragma unroll
            for (int nt = 0; nt < 8; nt++) {
                int ocp = nt * 4 + (lane & 3);
                uint32_t h0, l0, h1, l1;
                bsplit(acc[mt][nt][half * 2],     h0, l0);
                bsplit(acc[mt][nt][half * 2 + 1], h1, l1);
                xhh[rb + ocp] = h0 | (h1 << 16);
                xhl[rb + ocp] = l0 | (l1 << 16);
            }
        }
    }
}

// ------------------------------------------------------------------
// qkv_kernel (merged): one CTA = 128px x (q|k|v) 192 oc, 256 threads.
// 8 warps, warp = 16 px rows, all 192 n.  18 K chunks.
// SMEM/stage: A 32K + 3 x (Bh 8K | Bl 8K) = 80K, 2 stages = 160K.
// ------------------------------------------------------------------
__global__ __launch_bounds__(256) void qkv_kernel()
{
    extern __shared__ char smem[];
    const int STAGE = 81920;
    uint32_t sb = s2u(smem);
    const int tid = threadIdx.x, wid = tid >> 5, lane = tid & 31;
    const int hd = blockIdx.y, g = hd & 7;
    const int tile = blockIdx.x;
    const int NCH = 18;

    auto fill = [&](int s, int k) {
        uint32_t base = sb + s * STAGE;
        int r = tid >> 1;
        int px_ = tile * 128 + r;
        int py_ = px_ / 48, pxx_ = px_ - py_ * 48;
        int t9 = k >> 1, cb = k & 1, ky = t9 / 3, kx = t9 - ky * 3;
        int iy = py_ + ky - 1, ix = pxx_ + kx - 1;
        bool in = ((unsigned)iy < 48u) && ((unsigned)ix < 48u);
        const __nv_bfloat16* rp =
            g_xhp + (((size_t)hd * HW + iy * 48 + ix) * 128 + cb * 64);
        if (!in) rp = g_xhp;
        const char* sh = (const char*)rp;
        const char* sl = (const char*)(rp + XHPS);
        uint32_t sw = (r & 7) << 4;
        int g0 = (tid & 1) * 4;
#pragma unroll
        for (int gc = 0; gc < 4; gc++) {
            uint32_t off = r * 128 + (((g0 + gc) * 16) ^ sw);
            cpa16(base + off, sh + (g0 + gc) * 16, in);
            cpa16(base + 16384 + off, sl + (g0 + gc) * 16, in);
        }
        for (int i = tid; i < 3 * 1024; i += 256) {
            int zz = i >> 10, rem = i & 1023, half = rem >> 9, p = rem & 511;
            int oc = p >> 3, gr = p & 7;
            uint32_t off = oc * 128 + ((gr * 16) ^ ((oc & 7) << 4));
            const uint32_t* wsrc =
                g_wb32 + ((size_t)(zz * 8 + g) * 19 + k) * 4096 + half * 2048;
            cpa16(base + 32768 + zz * 16384 + half * 8192 + off, wsrc + p * 4, true);
        }
    };

    float acc[3][8][4];
#pragma unroll
    for (int zz = 0; zz < 3; zz++)
#pragma unroll
        for (int nt = 0; nt < 8; nt++)
#pragma unroll
            for (int i = 0; i < 4; i++) acc[zz][nt][i] = 0.f;

    fill(0, 0); CP_COMMIT();
    fill(1, 1); CP_COMMIT();
    const int lsub = lane >> 3, lrow = lane & 7;

    for (int k = 0; k < NCH; k++) {
        int s = k & 1;
        if (k + 1 < NCH) { CP_WAIT1(); } else { CP_WAIT0(); }
        __syncthreads();
        uint32_t Ab = sb + s * STAGE;
#pragma unroll
        for (int ks = 0; ks < 4; ks++) {
            uint32_t ah[4], al[4];
            {
                int r = wid * 16 + (lsub & 1) * 8 + lrow;
                uint32_t gran = ks * 2 + (lsub >> 1);
                uint32_t addr = Ab + r * 128 + ((gran * 16) ^ ((r & 7) << 4));
                LDSM4(ah, addr);
                LDSM4(al, addr + 16384);
            }
#pragma unroll
            for (int zz = 0; zz < 3; zz++) {
                uint32_t Bb = Ab + 32768 + zz * 16384;
                uint32_t bh[4][4], bl[4][4];
#pragma unroll
                for (int p = 0; p < 4; p++) {
                    int nn = p * 16 + (lsub >> 1) * 8 + lrow;
                    uint32_t gran = ks * 2 + (lsub & 1);
                    uint32_t addr = Bb + nn * 128 + ((gran * 16) ^ ((nn & 7) << 4));
                    LDSM4(bh[p], addr);
                    LDSM4(bl[p], addr + 8192);
                }
#pragma unroll
                for (int p = 0; p < 4; p++) {
                    mma16816(acc[zz][2 * p],     ah, bh[p][0], bh[p][1]);
                    mma16816(acc[zz][2 * p + 1], ah, bh[p][2], bh[p][3]);
                    mma16816(acc[zz][2 * p],     ah, bl[p][0], bl[p][1]);
                    mma16816(acc[zz][2 * p + 1], ah, bl[p][2], bl[p][3]);
                    mma16816(acc[zz][2 * p],     al, bh[p][0], bh[p][1]);
                    mma16816(acc[zz][2 * p + 1], al, bh[p][2], bh[p][3]);
                }
            }
        }
        __syncthreads();
        if (k + 2 < NCH) fill(s, k + 2);
        CP_COMMIT();
    }

    // epilogue
    uint32_t* qh32 = (uint32_t*)g_qh;
    uint32_t* ql32 = (uint32_t*)g_ql;
#pragma unroll
    for (int half = 0; half < 2; half++) {
        int m = tile * 128 + wid * 16 + (lane >> 2) + half * 8;
        // q
        {
            size_t rb = ((size_t)hd * HW + m) * 32;
#pragma unroll
            for (int nt = 0; nt < 8; nt++) {
                int ocp = nt * 4 + (lane & 3);
                uint32_t h0, l0, h1, l1;
                bsplit(acc[0][nt][half * 2],     h0, l0);
                bsplit(acc[0][nt][half * 2 + 1], h1, l1);
                qh32[rb + ocp] = h0 | (h1 << 16);
                ql32[rb + ocp] = l0 | (l1 << 16);
            }
        }
        // k, v
        int oy = m / 48, ox = m - oy * 48;
        if (oy >= 1 && oy <= 46 && ox >= 1 && ox <= 46) {
            int d = (oy - 1) * 46 + (ox - 1);
            size_t rb = ((size_t)hd * DPAD + d) * 32;
#pragma unroll
            for (int zz = 1; zz < 3; zz++) {
                uint32_t* dh = (uint32_t*)((zz == 1) ? g_kh : g_vh);
                uint32_t* dl = (uint32_t*)((zz == 1) ? g_kl : g_vl);
#pragma unroll
                for (int nt = 0; nt < 8; nt++) {
                    int ocp = nt * 4 + (lane & 3);
                    uint32_t h0, l0, h1, l1;
                    bsplit(acc[zz][nt][half * 2],     h0, l0);
                    bsplit(acc[zz][nt][half * 2 + 1], h1, l1);
                    dh[rb + ocp] = h0 | (h1 << 16);
                    dl[rb + ocp] = l0 | (l1 << 16);
                }
            }
        }
    }
}

// ------------------------------------------------------------------
// gate_kernel (merged, LSTM fused): one CTA = 128px x 4 gates x 64oc.
// 256 threads; warp = 16px rows, N=256.  19 K chunks (incl. 1x1 on a).
// SMEM/stage: A 32K + 4 x 16K = 96K, 2 stages = 192K.
// Epilogue computes i,f,g,o -> c_new -> h_new directly into out.
// ------------------------------------------------------------------
__global__ __launch_bounds__(256) void gate_kernel(
    const float* __restrict__ bbi, const float* __restrict__ bbf,
    const float* __restrict__ bbg, const float* __restrict__ bbo,
    const float* __restrict__ cold, float* __restrict__ out)
{
    extern __shared__ char smem[];
    const int STAGE = 98304;
    uint32_t sb = s2u(smem);
    const int tid = threadIdx.x, wid = tid >> 5, lane = tid & 31;
    const int hd = blockIdx.y, g = hd & 7;
    const int tile = blockIdx.x;
    const int NCH = 19;

    auto fill = [&](int s, int k) {
        uint32_t base = sb + s * STAGE;
        int r = tid >> 1;
        int px_ = tile * 128 + r;
        const char *sh, *sl; bool in;
        if (k < 18) {
            int py_ = px_ / 48, pxx_ = px_ - py_ * 48;
            int t9 = k >> 1, cb = k & 1, ky = t9 / 3, kx = t9 - ky * 3;
            int iy = py_ + ky - 1, ix = pxx_ + kx - 1;
            in = ((unsigned)iy < 48u) && ((unsigned)ix < 48u);
            const __nv_bfloat16* rp =
                g_xhp + (((size_t)hd * HW + iy * 48 + ix) * 128 + cb * 64);
            if (!in) rp = g_xhp;
            sh = (const char*)rp;
            sl = (const char*)(rp + XHPS);
        } else {
            in = true;
            sh = (const char*)(g_ah + ((size_t)hd * HW + px_) * 64);
            sl = (const char*)(g_al + ((size_t)hd * HW + px_) * 64);
        }
        uint32_t sw = (r & 7) << 4;
        int g0 = (tid & 1) * 4;
#pragma unroll
        for (int gc = 0; gc < 4; gc++) {
            uint32_t off = r * 128 + (((g0 + gc) * 16) ^ sw);
            cpa16(base + off, sh + (g0 + gc) * 16, in);
            cpa16(base + 16384 + off, sl + (g0 + gc) * 16, in);
        }
        for (int i = tid; i < 4 * 1024; i += 256) {
            int zz = i >> 10, rem = i & 1023, half = rem >> 9, p = rem & 511;
            int oc = p >> 3, gr = p & 7;
            uint32_t off = oc * 128 + ((gr * 16) ^ ((oc & 7) << 4));
            const uint32_t* wsrc =
                g_wb32 + ((size_t)((3 + zz) * 8 + g) * 19 + k) * 4096 + half * 2048;
            cpa16(base + 32768 + zz * 16384 + half * 8192 + off, wsrc + p * 4, true);
        }
    };

    float acc[4][8][4];
#pragma unroll
    for (int zz = 0; zz < 4; zz++)
#pragma unroll
        for (int nt = 0; nt < 8; nt++)
#pragma unroll
            for (int i = 0; i < 4; i++) acc[zz][nt][i] = 0.f;

    fill(0, 0); CP_COMMIT();
    fill(1, 1); CP_COMMIT();
    const int lsub = lane >> 3, lrow = lane & 7;

    for (int k = 0; k < NCH; k++) {
        int s = k & 1;
        if (k + 1 < NCH) { CP_WAIT1(); } else { CP_WAIT0(); }
        __syncthreads();
        uint32_t Ab = sb + s * STAGE;
#pragma unroll
        for (int ks = 0; ks < 4; ks++) {
            uint32_t ah[4], al[4];
            {
                int r = wid * 16 + (lsub & 1) * 8 + lrow;
                uint32_t gran = ks * 2 + (lsub >> 1);
                uint32_t addr = Ab + r * 128 + ((gran * 16) ^ ((r & 7) << 4));
                LDSM4(ah, addr);
                LDSM4(al, addr + 16384);
            }
#pragma unroll
            for (int zz = 0; zz < 4; zz++) {
                uint32_t Bb = Ab + 32768 + zz * 16384;
                uint32_t bh[4][4], bl[4][4];
#pragma unroll
                for (int p = 0; p < 4; p++) {
                    int nn = p * 16 + (lsub >> 1) * 8 + lrow;
                    uint32_t gran = ks * 2 + (lsub & 1);
                    uint32_t addr = Bb + nn * 128 + ((gran * 16) ^ ((nn & 7) << 4));
                    LDSM4(bh[p], addr);
                    LDSM4(bl[p], addr + 8192);
                }
#pragma unroll
                for (int p = 0; p < 4; p++) {
                    mma16816(acc[zz][2 * p],     ah, bh[p][0], bh[p][1]);
                    mma16816(acc[zz][2 * p + 1], ah, bh[p][2], bh[p][3]);
                    mma16816(acc[zz][2 * p],     ah, bl[p][0], bl[p][1]);
                    mma16816(acc[zz][2 * p + 1], ah, bl[p][2], bl[p][3]);
                    mma16816(acc[zz][2 * p],     al, bh[p][0], bh[p][1]);
                    mma16816(acc[zz][2 * p + 1], al, bh[p][2], bh[p][3]);
                }
            }
        }
        __syncthreads();
        if (k + 2 < NCH) fill(s, k + 2);
        CP_COMMIT();
    }

    // epilogue: LSTM pointwise, write h_new
    int n = hd >> 3;
#pragma unroll
    for (int half = 0; half < 2; half++) {
        int m = tile * 128 + wid * 16 + (lane >> 2) + half * 8;
#pragma unroll
        for (int nt = 0; nt < 8; nt++) {
#pragma unroll
            for (int e = 0; e < 2; e++) {
                int oc = nt * 8 + (lane & 3) * 2 + e;
                float pi = acc[0][nt][half * 2 + e] + bbi[g * 64 + oc];
                float pf = acc[1][nt][half * 2 + e] + bbf[g * 64 + oc];
                float pg = acc[2][nt][half * 2 + e] + bbg[g * 64 + oc];
                float po = acc[3][nt][half * 2 + e] + bbo[g * 64 + oc];
                float ig = 1.f / (1.f + __expf(-pi));
                float fg = 1.f / (1.f + __expf(-pf));
                float gg = tanhf(pg);
                float og = 1.f / (1.f + __expf(-po));
                size_t ci = ((size_t)n * 512 + g * 64 + oc) * HW + m;
                float cn = fg * cold[ci] + ig * gg;
                out[ci] = og * tanhf(cn);
            }
        }
    }
}

// ------------------------------------------------------------------
// attn_kernel: flash attention, 256 queries per CTA, 256 threads.
// SMEM: Qh 32K | Ql 32K | 2 x (Kh 8K | Kl 8K | Vh 8K | Vl 8K) = 128K.
// grid (9, 16) = 144 CTAs = one full wave.
// ------------------------------------------------------------------
__global__ __launch_bounds__(256) void attn_kernel(const float* __restrict__ tau)
{
    extern __shared__ char smem[];
    uint32_t sb = s2u(smem);
    const int tid = threadIdx.x, wid = tid >> 5, lane = tid & 31;
    const int hd = blockIdx.y, g = hd & 7;
    const int qbase = blockIdx.x * 256;
    const int lsub = lane >> 3, lrow = lane & 7;
    const float tv = tau[g];
    const int NCHK = (DS + 63) / 64;   // 34

    // Q fill (once): 256 rows
    {
        int r = tid;
        const char* qh = (const char*)g_qh + ((size_t)hd * HW + qbase + r) * 128;
        const char* ql = (const char*)g_ql + ((size_t)hd * HW + qbase + r) * 128;
        uint32_t sw = (r & 7) << 4;
#pragma unroll
        for (int gc = 0; gc < 8; gc++) {
            uint32_t off = r * 128 + ((gc * 16) ^ sw);
            cpa16(sb + off, qh + gc * 16, true);
            cpa16(sb + 32768 + off, ql + gc * 16, true);
        }
    }
    auto fillkv = [&](int s, int c) {
        uint32_t base = sb + 65536 + s * 32768;
        int r = tid >> 2;
        int g2 = (tid & 3) * 2;
        int d = c * 64 + r;
        bool ok = d < DS;
        size_t rb = ((size_t)hd * DPAD + (ok ? d : 0)) * 128;
        const char* kh = (const char*)g_kh + rb;
        const char* kl = (const char*)g_kl + rb;
        const char* vh = (const char*)g_vh + rb;
        const char* vl = (const char*)g_vl + rb;
        uint32_t sw = (r & 7) << 4;
#pragma unroll
        for (int gg = 0; gg < 2; gg++) {
            int gran = g2 + gg;
            uint32_t off = r * 128 + ((gran * 16) ^ sw);
            cpa16(base + off,         kh + gran * 16, ok);
            cpa16(base + 8192 + off,  kl + gran * 16, ok);
            cpa16(base + 16384 + off, vh + gran * 16, ok);
            cpa16(base + 24576 + off, vl + gran * 16, ok);
        }
    };

    fillkv(0, 0); CP_COMMIT();
    fillkv(1, 1); CP_COMMIT();

    float o[2][8][4];
#pragma unroll
    for (int mt = 0; mt < 2; mt++)
#pragma unroll
        for (int nt = 0; nt < 8; nt++)
#pragma unroll
            for (int i = 0; i < 4; i++) o[mt][nt][i] = 0.f;
    float mrow[2][2] = {{-1e30f, -1e30f}, {-1e30f, -1e30f}};
    float lrow_[2][2] = {{0.f, 0.f}, {0.f, 0.f}};

    for (int c = 0; c < NCHK; c++) {
        int s = c & 1;
        if (c + 1 < NCHK) { CP_WAIT1(); } else { CP_WAIT0(); }
        __syncthreads();
        uint32_t Qb = sb;
        uint32_t Kb = sb + 65536 + s * 32768;
        uint32_t Vb = Kb + 16384;

        float sf[2][8][4];
#pragma unroll
        for (int mt = 0; mt < 2; mt++)
#pragma unroll
            for (int nt = 0; nt < 8; nt++)
#pragma unroll
                for (int i = 0; i < 4; i++) sf[mt][nt][i] = 0.f;
#pragma unroll
        for (int ks = 0; ks < 4; ks++) {
            uint32_t ah[2][4], al[2][4];
#pragma unroll
            for (int mt = 0; mt < 2; mt++) {
                int r = wid * 32 + mt * 16 + (lsub & 1) * 8 + lrow;
                uint32_t gran = ks * 2 + (lsub >> 1);
                uint32_t addr = Qb + r * 128 + ((gran * 16) ^ ((r & 7) << 4));
                LDSM4(ah[mt], addr);
                LDSM4(al[mt], addr + 32768);
            }
            uint32_t bh[4][4], bl[4][4];
#pragma unroll
            for (int p = 0; p < 4; p++) {
                int nn = p * 16 + (lsub >> 1) * 8 + lrow;
                uint32_t gran = ks * 2 + (lsub & 1);
                uint32_t addr = Kb + nn * 128 + ((gran * 16) ^ ((nn & 7) << 4));
                LDSM4(bh[p], addr);
                LDSM4(bl[p], addr + 8192);
            }
#pragma unroll
            for (int mt = 0; mt < 2; mt++) {
#pragma unroll
                for (int p = 0; p < 4; p++) {
                    mma16816(sf[mt][2 * p],     ah[mt], bh[p][0], bh[p][1]);
                    mma16816(sf[mt][2 * p + 1], ah[mt], bh[p][2], bh[p][3]);
                    mma16816(sf[mt][2 * p],     ah[mt], bl[p][0], bl[p][1]);
                    mma16816(sf[mt][2 * p + 1], ah[mt], bl[p][2], bl[p][3]);
                    mma16816(sf[mt][2 * p],     al[mt], bh[p][0], bh[p][1]);
                    mma16816(sf[mt][2 * p + 1], al[mt], bh[p][2], bh[p][3]);
                }
            }
        }

        // online softmax
        int dbase = c * 64 + (lane & 3) * 2;
        float alpha[2][2];
#pragma unroll
        for (int mt = 0; mt < 2; mt++) {
#pragma unroll
            for (int h = 0; h < 2; h++) {
                float mx = mrow[mt][h];
#pragma unroll
                for (int nt = 0; nt < 8; nt++) {
#pragma unroll
                    for (int e = 0; e < 2; e++) {
                        int d = dbase + nt * 8 + e;
                        float v = (d < DS) ? tv * sf[mt][nt][h * 2 + e] : -1e30f;
                        sf[mt][nt][h * 2 + e] = v;
                        mx = fmaxf(mx, v);
                    }
                }
                mx = fmaxf(mx, __shfl_xor_sync(0xffffffffu, mx, 1));
                mx = fmaxf(mx, __shfl_xor_sync(0xffffffffu, mx, 2));
                float al_ = __expf(mrow[mt][h] - mx);
                mrow[mt][h] = mx;
                alpha[mt][h] = al_;
                float ls = lrow_[mt][h] * al_;
#pragma unroll
                for (int nt = 0; nt < 8; nt++) {
#pragma unroll
                    for (int e = 0; e < 2; e++) {
                        float p = __expf(sf[mt][nt][h * 2 + e] - mx);
                        sf[mt][nt][h * 2 + e] = p;
                        ls += p;
                    }
                }
                lrow_[mt][h] = ls;
            }
        }
#pragma unroll
        for (int mt = 0; mt < 2; mt++)
#pragma unroll
            for (int nt = 0; nt < 8; nt++) {
                o[mt][nt][0] *= alpha[mt][0];
                o[mt][nt][1] *= alpha[mt][0];
                o[mt][nt][2] *= alpha[mt][1];
                o[mt][nt][3] *= alpha[mt][1];
            }

        // O += P V
#pragma unroll
        for (int kt = 0; kt < 4; kt++) {
            uint32_t vh[4][4], vl[4][4];
#pragma unroll
            for (int np = 0; np < 4; np++) {
                int rr = kt * 16 + (lane & 15);
                uint32_t gran = np * 2 + (lane >> 4);
                uint32_t addr = Vb + rr * 128 + ((gran * 16) ^ ((rr & 7) << 4));
                LDSM4T(vh[np], addr);
                LDSM4T(vl[np], addr + 8192);
            }
#pragma unroll
            for (int mt = 0; mt < 2; mt++) {
                uint32_t pah[4], pal[4];
#pragma unroll
                for (int i = 0; i < 4; i++) {
                    int nt = 2 * kt + (i >> 1);
                    float p0 = sf[mt][nt][(i & 1) * 2];
                    float p1 = sf[mt][nt][(i & 1) * 2 + 1];
                    uint32_t ph = packbf(p0, p1);
                    float r0 = p0 - __uint_as_float(ph << 16);
                    float r1 = p1 - __uint_as_float(ph & 0xffff0000u);
                    pah[i] = ph;
                    pal[i] = packbf(r0, r1);
                }
#pragma unroll
                for (int np = 0; np < 4; np++) {
                    mma16816(o[mt][2 * np],     pah, vh[np][0], vh[np][1]);
                    mma16816(o[mt][2 * np + 1], pah, vh[np][2], vh[np][3]);
                    mma16816(o[mt][2 * np],     pal, vh[np][0], vh[np][1]);
                    mma16816(o[mt][2 * np + 1], pal, vh[np][2], vh[np][3]);
                    mma16816(o[mt][2 * np],     pah, vl[np][0], vl[np][1]);
                    mma16816(o[mt][2 * np + 1], pah, vl[np][2], vl[np][3]);
                }
            }
        }
        __syncthreads();
        if (c + 2 < NCHK) fillkv(s, c + 2);
        CP_COMMIT();
    }

    uint32_t* ah32 = (uint32_t*)g_ah;
    uint32_t* al32 = (uint32_t*)g_al;
#pragma unroll
    for (int mt = 0; mt < 2; mt++) {
#pragma unroll
        for (int h = 0; h < 2; h++) {
            float l = lrow_[mt][h];
            l += __shfl_xor_sync(0xffffffffu, l, 1);
            l += __shfl_xor_sync(0xffffffffu, l, 2);
            float inv = 1.f / l;
            int m = qbase + wid * 32 + mt * 16 + (lane >> 2) + h * 8;
            size_t rb = ((size_t)hd * HW + m) * 32;
#pragma unroll
            for (int nt = 0; nt < 8; nt++) {
                int ocp = nt * 4 + (lane & 3);
                float v0 = o[mt][nt][h * 2] * inv;
                float v1 = o[mt][nt][h * 2 + 1] * inv;
                uint32_t h0, l0, h1, l1;
                bsplit(v0, h0, l0); bsplit(v1, h1, l1);
                ah32[rb + ocp] = h0 | (h1 << 16);
                al32[rb + ocp] = l0 | (l1 << 16);
            }
        }
    }
}

// ------------------------------------------------------------------
extern "C" void kernel_launch(void* const* d_in, const int* in_sizes, int n_in,
                              void* d_out, int out_size)
{
    const float* x_in = (const float*)d_in[0];
    const float* h    = (const float*)d_in[1];
    const float* c    = (const float*)d_in[2];
    const float* tau  = (const float*)d_in[3];
    const float* Wx   = (const float*)d_in[4];
    const float* Wig  = (const float*)d_in[5];
    const float* Wq   = (const float*)d_in[6];
    const float* Wk   = (const float*)d_in[7];
    const float* Wv   = (const float*)d_in[8];
    const float* Wia  = (const float*)d_in[9];
    const float* Wix  = (const float*)d_in[10];
    const float* bi   = (const float*)d_in[11];
    const float* Wfa  = (const float*)d_in[12];
    const float* Wfx  = (const float*)d_in[13];
    const float* bf   = (const float*)d_in[14];
    const float* Wga  = (const float*)d_in[15];
    const float* Wgx  = (const float*)d_in[16];
    const float* bg   = (const float*)d_in[17];
    const float* Woa  = (const float*)d_in[18];
    const float* Wox  = (const float*)d_in[19];
    const float* bo   = (const float*)d_in[20];
    float* out = (float*)d_out;

    const int PSMEM = 2 * 49152;            //  96 KB proj
    const int QSMEM = 2 * 81920;            // 160 KB qkv
    const int GSMEM = 2 * 98304;            // 192 KB gates
    const int ASMEM = 65536 + 2 * 32768;    // 128 KB attn
    cudaFuncSetAttribute(proj_mma,
                         cudaFuncAttributeMaxDynamicSharedMemorySize, PSMEM);
    cudaFuncSetAttribute(qkv_kernel,
                         cudaFuncAttributeMaxDynamicSharedMemorySize, QSMEM);
    cudaFuncSetAttribute(gate_kernel,
                         cudaFuncAttributeMaxDynamicSharedMemorySize, GSMEM);
    cudaFuncSetAttribute(attn_kernel,
                         cudaFuncAttributeMaxDynamicSharedMemorySize, ASMEM);

    prep_w<<<8512, 256>>>(Wq, Wk, Wv, Wix, Wfx, Wgx, Wox, Wia, Wfa, Wga, Woa);
    prep_pw<<<768, 256>>>(Wx, Wig);
    prep_x<<<dim3(18, 12, 2), 256>>>(x_in, h);
    proj_mma<<<dim3(18, 8, 2), 128, PSMEM>>>();
    qkv_kernel<<<dim3(18, 16), 256, QSMEM>>>();
    attn_kernel<<<dim3(9, 16), 256, ASMEM>>>(tau);
    gate_kernel<<<dim3(18, 16), 256, GSMEM>>>(bi, bf, bg, bo, c, out);
}

// round 10
// speedup vs baseline: 4.5570x; 1.1209x over previous
#include <cuda_runtime.h>
#include <cuda_bf16.h>
#include <math.h>
#include <stdint.h>

#define NB   2
#define CINC 256
#define CT   512
#define HH   48
#define HW   2304
#define DS   2116
#define DPAD 2176
#define TOT  (NB*CT*HW)

// bf16 2-term split: v ~= hi + lo
__device__ __forceinline__ void bsplit(float v, uint32_t& h16, uint32_t& l16) {
    __nv_bfloat16 bh = __float2bfloat16(v);
    __nv_bfloat16 bl = __float2bfloat16(v - __bfloat162float(bh));
    h16 = (uint32_t)__bfloat16_as_ushort(bh);
    l16 = (uint32_t)__bfloat16_as_ushort(bl);
}
__device__ __forceinline__ uint32_t packbf(float lo, float hi) {
    uint32_t r;
    asm("cvt.rn.bf16x2.f32 %0, %1, %2;" : "=r"(r) : "f"(hi), "f"(lo));
    return r;
}
__device__ __forceinline__ float ex2(float x) {
    float y; asm("ex2.approx.f32 %0, %1;" : "=f"(y) : "f"(x)); return y;
}

// ---------------- scratch ----------------
#define XHPS (16 * HW * 128)
__device__ __align__(256) __nv_bfloat16 g_xhp[2 * XHPS];        // [split][hd][px][128]
__device__ __align__(256) uint32_t g_wb32[7 * 8 * 19 * 4096];   // conv weight imgs
__device__ __align__(256) uint32_t g_wpb32[8 * 12 * 4096];      // proj weight imgs
__device__ __align__(256) uint32_t g_apm_h[NB * HW * 384];      // proj A hi [n][px][768ch]
__device__ __align__(256) uint32_t g_apm_l[NB * HW * 384];
__device__ __align__(256) __nv_bfloat16 g_qh[16 * HW * 64];
__device__ __align__(256) __nv_bfloat16 g_ql[16 * HW * 64];
__device__ __align__(256) __nv_bfloat16 g_kh[16 * DPAD * 64];
__device__ __align__(256) __nv_bfloat16 g_kl[16 * DPAD * 64];
__device__ __align__(256) __nv_bfloat16 g_vh[16 * DPAD * 64];
__device__ __align__(256) __nv_bfloat16 g_vl[16 * DPAD * 64];
__device__ __align__(256) __nv_bfloat16 g_ah[16 * HW * 64];
__device__ __align__(256) __nv_bfloat16 g_al[16 * HW * 64];

// ---------------- cp.async ----------------
__device__ __forceinline__ uint32_t s2u(const void* p) {
    return (uint32_t)__cvta_generic_to_shared(p);
}
__device__ __forceinline__ void cpa16(uint32_t dst, const void* src, bool pred) {
    int sz = pred ? 16 : 0;
    asm volatile("cp.async.cg.shared.global [%0], [%1], 16, %2;\n"
                 :: "r"(dst), "l"(src), "r"(sz) : "memory");
}
#define CP_COMMIT() asm volatile("cp.async.commit_group;\n" ::: "memory")
#define CP_WAIT0()  asm volatile("cp.async.wait_group 0;\n" ::: "memory")
#define CP_WAIT1()  asm volatile("cp.async.wait_group 1;\n" ::: "memory")

// ---------------- mma.sync helpers ----------------
#define LDSM4(r, a) \
    asm volatile("ldmatrix.sync.aligned.m8n8.x4.shared.b16 {%0,%1,%2,%3}, [%4];" \
                 : "=r"((r)[0]), "=r"((r)[1]), "=r"((r)[2]), "=r"((r)[3]) : "r"(a))
#define LDSM4T(r, a) \
    asm volatile("ldmatrix.sync.aligned.m8n8.x4.trans.shared.b16 {%0,%1,%2,%3}, [%4];" \
                 : "=r"((r)[0]), "=r"((r)[1]), "=r"((r)[2]), "=r"((r)[3]) : "r"(a))

__device__ __forceinline__ void mma16816(float* d, const uint32_t* a,
                                         uint32_t b0, uint32_t b1) {
    asm volatile(
        "mma.sync.aligned.m16n8k16.row.col.f32.bf16.bf16.f32 "
        "{%0,%1,%2,%3}, {%4,%5,%6,%7}, {%8,%9}, {%0,%1,%2,%3};"
        : "+f"(d[0]), "+f"(d[1]), "+f"(d[2]), "+f"(d[3])
        : "r"(a[0]), "r"(a[1]), "r"(a[2]), "r"(a[3]), "r"(b0), "r"(b1));
}

// ------------------------------------------------------------------
// prep_w: conv weights -> g_wb32 (64oc x 64ch bf16 hi/lo images)
// ------------------------------------------------------------------
__global__ void prep_w(const float* __restrict__ Wq, const float* __restrict__ Wk,
                       const float* __restrict__ Wv,
                       const float* __restrict__ Wix, const float* __restrict__ Wfx,
                       const float* __restrict__ Wgx, const float* __restrict__ Wox,
                       const float* __restrict__ Wia, const float* __restrict__ Wfa,
                       const float* __restrict__ Wga, const float* __restrict__ Woa)
{
    int idx = blockIdx.x * 256 + threadIdx.x;
    if (idx >= 7 * 8 * 19 * 64 * 32) return;
    int c2    = idx & 31;
    int oc    = (idx >> 5) & 63;
    int rem   = idx >> 11;
    int chunk = rem % 19;
    int g     = (rem / 19) & 7;
    int type  = rem / 152;
    if (type < 3 && chunk == 18) return;

    float w0, w1;
    if (chunk < 18) {
        const float* W3 = (type == 0) ? Wq : (type == 1) ? Wk : (type == 2) ? Wv :
                          (type == 3) ? Wix : (type == 4) ? Wfx : (type == 5) ? Wgx : Wox;
        int t9 = chunk >> 1, cb = chunk & 1;
        size_t b = ((size_t)(g * 64 + oc) * 128 + cb * 64 + c2 * 2) * 9 + t9;
        w0 = W3[b]; w1 = W3[b + 9];
    } else {
        const float* Wa = (type == 3) ? Wia : (type == 4) ? Wfa : (type == 5) ? Wga : Woa;
        size_t b = (size_t)(g * 64 + oc) * 64 + c2 * 2;
        w0 = Wa[b]; w1 = Wa[b + 1];
    }
    uint32_t h0, l0, h1, l1;
    bsplit(w0, h0, l0); bsplit(w1, h1, l1);
    size_t tb = (size_t)rem * 4096;
    g_wb32[tb + oc * 32 + c2]        = h0 | (h1 << 16);
    g_wb32[tb + 2048 + oc * 32 + c2] = l0 | (l1 << 16);
}

// ------------------------------------------------------------------
// prep_pw: proj weights -> g_wpb32 (per (g,chunk) 64oc x 64ch images)
// ------------------------------------------------------------------
__global__ void prep_pw(const float* __restrict__ Wx, const float* __restrict__ Wig)
{
    int idx = blockIdx.x * 256 + threadIdx.x;
    if (idx >= 8 * 12 * 64 * 32) return;
    int c2    = idx & 31;
    int oc    = (idx >> 5) & 63;
    int rem   = idx >> 11;
    int chunk = rem % 12;
    int g     = rem / 12;

    float w0, w1;
    if (chunk < 4) {
        size_t b = (size_t)(g * 64 + oc) * 256 + chunk * 64 + c2 * 2;
        w0 = Wx[b]; w1 = Wx[b + 1];
    } else {
        size_t b = (size_t)(g * 64 + oc) * 512 + (chunk - 4) * 64 + c2 * 2;
        w0 = Wig[b]; w1 = Wig[b + 1];
    }
    uint32_t h0, l0, h1, l1;
    bsplit(w0, h0, l0); bsplit(w1, h1, l1);
    size_t tb = (size_t)rem * 4096;
    g_wpb32[tb + oc * 32 + c2]        = h0 | (h1 << 16);
    g_wpb32[tb + 2048 + oc * 32 + c2] = l0 | (l1 << 16);
}

// ------------------------------------------------------------------
// prep_x: transpose x_in+h -> pixel-major bf16 hi/lo + xh h-half
// ------------------------------------------------------------------
__global__ __launch_bounds__(256) void prep_x(
    const float* __restrict__ x_in, const float* __restrict__ h)
{
    __shared__ float t[64][129];
    int px0 = blockIdx.x * 128;
    int chb = blockIdx.y;
    int n   = blockIdx.z;
    int tid = threadIdx.x;

    for (int i = tid; i < 64 * 128; i += 256) {
        int cl = i >> 7, p = i & 127;
        int ch = chb * 64 + cl;
        float v = (ch < 256)
            ? x_in[((size_t)n * 256 + ch) * HW + px0 + p]
            : h[((size_t)n * 512 + (ch - 256)) * HW + px0 + p];
        t[cl][p] = v;
    }
    __syncthreads();

    for (int i = tid; i < 128 * 32; i += 256) {
        int p = i >> 5, c2 = i & 31;
        float v0 = t[c2 * 2][p], v1 = t[c2 * 2 + 1][p];
        uint32_t h0, l0, h1, l1;
        bsplit(v0, h0, l0); bsplit(v1, h1, l1);
        uint32_t hv = h0 | (h1 << 16), lv = l0 | (l1 << 16);
        size_t of = ((size_t)n * HW + px0 + p) * 384 + chb * 32 + c2;
        g_apm_h[of] = hv;
        g_apm_l[of] = lv;
        if (chb >= 4) {
            int g = chb - 4;
            size_t of2 = ((size_t)(n * 8 + g) * HW + px0 + p) * 64 + 32 + c2;
            ((uint32_t*)g_xhp)[of2] = hv;
            ((uint32_t*)(g_xhp + XHPS))[of2] = lv;
        }
    }
}

// ------------------------------------------------------------------
// proj_mma: dense GEMM, N=128 block, 512 threads (16 warps).
// grid (18 tiles, 4 nb, 2 n).  warp = (px16 = w>>1, nh = w&1).
// SMEM/stage: Ah 16K | Al 16K | Bh 16K | Bl 16K = 64K, 2 stages.
// ------------------------------------------------------------------
__global__ __launch_bounds__(512, 1) void proj_mma()
{
    extern __shared__ char smem[];
    uint32_t sb = s2u(smem);
    const int tid = threadIdx.x, w = tid >> 5, lane = tid & 31;
    const int nb = blockIdx.y, n = blockIdx.z;
    const int tile = blockIdx.x;
    const int NCH = 12;
    const int lsub = lane >> 3, lrow = lane & 7;

    auto fill = [&](int s, int k) {
        uint32_t base = sb + s * 65536;
        {
            int r = tid >> 2, q = tid & 3;
            int px = tile * 128 + r;
            const uint32_t* srch = g_apm_h + ((size_t)n * HW + px) * 384 + k * 32;
            const uint32_t* srcl = g_apm_l + ((size_t)n * HW + px) * 384 + k * 32;
            uint32_t sw = (r & 7) << 4;
#pragma unroll
            for (int j = 0; j < 2; j++) {
                int gc = q * 2 + j;
                uint32_t off = r * 128 + ((gc * 16) ^ sw);
                cpa16(base + off, srch + gc * 4, true);
                cpa16(base + 16384 + off, srcl + gc * 4, true);
            }
        }
#pragma unroll
        for (int i = 0; i < 4; i++) {
            int p = tid + i * 512;
            int half = p >> 10, pg = p & 1023;
            int row = pg >> 3, gr = pg & 7;
            int srctile = (nb * 2 + (row >> 6)) * 12 + k;
            int srow = row & 63;
            const uint32_t* src = g_wpb32 + (size_t)srctile * 4096 + half * 2048
                                  + srow * 32 + gr * 4;
            uint32_t off = row * 128 + ((gr * 16) ^ ((row & 7) << 4));
            cpa16(base + 32768 + half * 16384 + off, src, true);
        }
    };

    float acc[8][4];
#pragma unroll
    for (int nt = 0; nt < 8; nt++)
#pragma unroll
        for (int i = 0; i < 4; i++) acc[nt][i] = 0.f;

    fill(0, 0); CP_COMMIT();
    fill(1, 1); CP_COMMIT();

    for (int k = 0; k < NCH; k++) {
        int s = k & 1;
        if (k + 1 < NCH) { CP_WAIT1(); } else { CP_WAIT0(); }
        __syncthreads();
        uint32_t Ab = sb + s * 65536;
        uint32_t Bb = Ab + 32768;
#pragma unroll
        for (int ks = 0; ks < 4; ks++) {
            uint32_t ah[4], al[4];
            {
                int r = (w >> 1) * 16 + (lsub & 1) * 8 + lrow;
                uint32_t gran = ks * 2 + (lsub >> 1);
                uint32_t addr = Ab + r * 128 + ((gran * 16) ^ ((r & 7) << 4));
                LDSM4(ah, addr);
                LDSM4(al, addr + 16384);
            }
#pragma unroll
            for (int p = 0; p < 4; p++) {
                int nn = (w & 1) * 64 + p * 16 + (lsub >> 1) * 8 + lrow;
                uint32_t gran = ks * 2 + (lsub & 1);
                uint32_t addr = Bb + nn * 128 + ((gran * 16) ^ ((nn & 7) << 4));
                uint32_t bh[4], bl[4];
                LDSM4(bh, addr);
                LDSM4(bl, addr + 16384);
                mma16816(acc[2 * p],     ah, bh[0], bh[1]);
                mma16816(acc[2 * p + 1], ah, bh[2], bh[3]);
                mma16816(acc[2 * p],     ah, bl[0], bl[1]);
                mma16816(acc[2 * p + 1], ah, bl[2], bl[3]);
                mma16816(acc[2 * p],     al, bh[0], bh[1]);
                mma16816(acc[2 * p + 1], al, bh[2], bh[3]);
            }
        }
        __syncthreads();
        if (k + 2 < NCH) fill(s, k + 2);
        CP_COMMIT();
    }

    int hd = n * 8 + nb * 2 + (w & 1);
    uint32_t* xhh = (uint32_t*)g_xhp;
    uint32_t* xhl = (uint32_t*)(g_xhp + XHPS);
#pragma unroll
    for (int half = 0; half < 2; half++) {
        int m = tile * 128 + (w >> 1) * 16 + (lane >> 2) + half * 8;
        size_t rb = ((size_t)hd * HW + m) * 64;
#pragma unroll
        for (int nt = 0; nt < 8; nt++) {
            int ocp = nt * 4 + (lane & 3);
            uint32_t h0, l0, h1, l1;
            bsplit(acc[nt][half * 2],     h0, l0);
            bsplit(acc[nt][half * 2 + 1], h1, l1);
            xhh[rb + ocp] = h0 | (h1 << 16);
            xhl[rb + ocp] = l0 | (l1 << 16);
        }
    }
}

// ------------------------------------------------------------------
// qkv_kernel: 512 threads; warp = (px16 = w>>1, nh = w&1 -> 32oc half
// of each of q/k/v).  grid (18, 16).  Stage 80K x 2.
// ------------------------------------------------------------------
__global__ __launch_bounds__(512, 1) void qkv_kernel()
{
    extern __shared__ char smem[];
    const int STAGE = 81920;
    uint32_t sb = s2u(smem);
    const int tid = threadIdx.x, w = tid >> 5, lane = tid & 31;
    const int hd = blockIdx.y, g = hd & 7;
    const int tile = blockIdx.x;
    const int NCH = 18;
    const int lsub = lane >> 3, lrow = lane & 7;

    auto fill = [&](int s, int k) {
        uint32_t base = sb + s * STAGE;
        {
            int r = tid >> 2, q = tid & 3;
            int px_ = tile * 128 + r;
            int py_ = px_ / 48, pxx_ = px_ - py_ * 48;
            int t9 = k >> 1, cb = k & 1, ky = t9 / 3, kx = t9 - ky * 3;
            int iy = py_ + ky - 1, ix = pxx_ + kx - 1;
            bool in = ((unsigned)iy < 48u) && ((unsigned)ix < 48u);
            const __nv_bfloat16* rp =
                g_xhp + (((size_t)hd * HW + iy * 48 + ix) * 128 + cb * 64);
            if (!in) rp = g_xhp;
            const char* sh = (const char*)rp;
            const char* sl = (const char*)(rp + XHPS);
            uint32_t sw = (r & 7) << 4;
#pragma unroll
            for (int j = 0; j < 2; j++) {
                int gc = q * 2 + j;
                uint32_t off = r * 128 + ((gc * 16) ^ sw);
                cpa16(base + off, sh + gc * 16, in);
                cpa16(base + 16384 + off, sl + gc * 16, in);
            }
        }
#pragma unroll
        for (int i = 0; i < 6; i++) {
            int p = tid + i * 512;
            int zz = p >> 10, rem = p & 1023, half = rem >> 9, pg = rem & 511;
            int oc = pg >> 3, gr = pg & 7;
            uint32_t off = oc * 128 + ((gr * 16) ^ ((oc & 7) << 4));
            const uint32_t* wsrc =
                g_wb32 + ((size_t)(zz * 8 + g) * 19 + k) * 4096 + half * 2048;
            cpa16(base + 32768 + zz * 16384 + half * 8192 + off, wsrc + pg * 4, true);
        }
    };

    float acc[3][4][4];
#pragma unroll
    for (int zz = 0; zz < 3; zz++)
#pragma unroll
        for (int nt = 0; nt < 4; nt++)
#pragma unroll
            for (int i = 0; i < 4; i++) acc[zz][nt][i] = 0.f;

    fill(0, 0); CP_COMMIT();
    fill(1, 1); CP_COMMIT();

    for (int k = 0; k < NCH; k++) {
        int s = k & 1;
        if (k + 1 < NCH) { CP_WAIT1(); } else { CP_WAIT0(); }
        __syncthreads();
        uint32_t Ab = sb + s * STAGE;
#pragma unroll
        for (int ks = 0; ks < 4; ks++) {
            uint32_t ah[4], al[4];
            {
                int r = (w >> 1) * 16 + (lsub & 1) * 8 + lrow;
                uint32_t gran = ks * 2 + (lsub >> 1);
                uint32_t addr = Ab + r * 128 + ((gran * 16) ^ ((r & 7) << 4));
                LDSM4(ah, addr);
                LDSM4(al, addr + 16384);
            }
#pragma unroll
            for (int zz = 0; zz < 3; zz++) {
                uint32_t Bb = Ab + 32768 + zz * 16384;
#pragma unroll
                for (int p = 0; p < 2; p++) {
                    int nn = (w & 1) * 32 + p * 16 + (lsub >> 1) * 8 + lrow;
                    uint32_t gran = ks * 2 + (lsub & 1);
                    uint32_t addr = Bb + nn * 128 + ((gran * 16) ^ ((nn & 7) << 4));
                    uint32_t bh[4], bl[4];
                    LDSM4(bh, addr);
                    LDSM4(bl, addr + 8192);
                    mma16816(acc[zz][2 * p],     ah, bh[0], bh[1]);
                    mma16816(acc[zz][2 * p + 1], ah, bh[2], bh[3]);
                    mma16816(acc[zz][2 * p],     ah, bl[0], bl[1]);
                    mma16816(acc[zz][2 * p + 1], ah, bl[2], bl[3]);
                    mma16816(acc[zz][2 * p],     al, bh[0], bh[1]);
                    mma16816(acc[zz][2 * p + 1], al, bh[2], bh[3]);
                }
            }
        }
        __syncthreads();
        if (k + 2 < NCH) fill(s, k + 2);
        CP_COMMIT();
    }

    uint32_t* qh32 = (uint32_t*)g_qh;
    uint32_t* ql32 = (uint32_t*)g_ql;
#pragma unroll
    for (int half = 0; half < 2; half++) {
        int m = tile * 128 + (w >> 1) * 16 + (lane >> 2) + half * 8;
        {
            size_t rb = ((size_t)hd * HW + m) * 32;
#pragma unroll
            for (int nt = 0; nt < 4; nt++) {
                int ocp = (w & 1) * 16 + nt * 4 + (lane & 3);
                uint32_t h0, l0, h1, l1;
                bsplit(acc[0][nt][half * 2],     h0, l0);
                bsplit(acc[0][nt][half * 2 + 1], h1, l1);
                qh32[rb + ocp] = h0 | (h1 << 16);
                ql32[rb + ocp] = l0 | (l1 << 16);
            }
        }
        int oy = m / 48, ox = m - oy * 48;
        if (oy >= 1 && oy <= 46 && ox >= 1 && ox <= 46) {
            int d = (oy - 1) * 46 + (ox - 1);
            size_t rb = ((size_t)hd * DPAD + d) * 32;
#pragma unroll
            for (int zz = 1; zz < 3; zz++) {
                uint32_t* dh = (uint32_t*)((zz == 1) ? g_kh : g_vh);
                uint32_t* dl = (uint32_t*)((zz == 1) ? g_kl : g_vl);
#pragma unroll
                for (int nt = 0; nt < 4; nt++) {
                    int ocp = (w & 1) * 16 + nt * 4 + (lane & 3);
                    uint32_t h0, l0, h1, l1;
                    bsplit(acc[zz][nt][half * 2],     h0, l0);
                    bsplit(acc[zz][nt][half * 2 + 1], h1, l1);
                    dh[rb + ocp] = h0 | (h1 << 16);
                    dl[rb + ocp] = l0 | (l1 << 16);
                }
            }
        }
    }
}

// ------------------------------------------------------------------
// gate_kernel: 512 threads; warp = (px16 = w>>1, zh = w&1 -> 2 gates).
// 19 K chunks.  Stage 96K x 2.  LSTM epilogue via smem exchange.
// ------------------------------------------------------------------
__global__ __launch_bounds__(512, 1) void gate_kernel(
    const float* __restrict__ bbi, const float* __restrict__ bbf,
    const float* __restrict__ bbg, const float* __restrict__ bbo,
    const float* __restrict__ cold, float* __restrict__ out)
{
    extern __shared__ char smem[];
    const int STAGE = 98304;
    uint32_t sb = s2u(smem);
    const int tid = threadIdx.x, w = tid >> 5, lane = tid & 31;
    const int hd = blockIdx.y, g = hd & 7;
    const int tile = blockIdx.x;
    const int NCH = 19;
    const int lsub = lane >> 3, lrow = lane & 7;

    auto fill = [&](int s, int k) {
        uint32_t base = sb + s * STAGE;
        {
            int r = tid >> 2, q = tid & 3;
            int px_ = tile * 128 + r;
            const char *sh, *sl; bool in;
            if (k < 18) {
                int py_ = px_ / 48, pxx_ = px_ - py_ * 48;
                int t9 = k >> 1, cb = k & 1, ky = t9 / 3, kx = t9 - ky * 3;
                int iy = py_ + ky - 1, ix = pxx_ + kx - 1;
                in = ((unsigned)iy < 48u) && ((unsigned)ix < 48u);
                const __nv_bfloat16* rp =
                    g_xhp + (((size_t)hd * HW + iy * 48 + ix) * 128 + cb * 64);
                if (!in) rp = g_xhp;
                sh = (const char*)rp;
                sl = (const char*)(rp + XHPS);
            } else {
                in = true;
                sh = (const char*)(g_ah + ((size_t)hd * HW + px_) * 64);
                sl = (const char*)(g_al + ((size_t)hd * HW + px_) * 64);
            }
            uint32_t sw = (r & 7) << 4;
#pragma unroll
            for (int j = 0; j < 2; j++) {
                int gc = q * 2 + j;
                uint32_t off = r * 128 + ((gc * 16) ^ sw);
                cpa16(base + off, sh + gc * 16, in);
                cpa16(base + 16384 + off, sl + gc * 16, in);
            }
        }
#pragma unroll
        for (int i = 0; i < 8; i++) {
            int p = tid + i * 512;
            int zz = p >> 10, rem = p & 1023, half = rem >> 9, pg = rem & 511;
            int oc = pg >> 3, gr = pg & 7;
            uint32_t off = oc * 128 + ((gr * 16) ^ ((oc & 7) << 4));
            const uint32_t* wsrc =
                g_wb32 + ((size_t)((3 + zz) * 8 + g) * 19 + k) * 4096 + half * 2048;
            cpa16(base + 32768 + zz * 16384 + half * 8192 + off, wsrc + pg * 4, true);
        }
    };

    float acc[2][8][4];
#pragma unroll
    for (int j = 0; j < 2; j++)
#pragma unroll
        for (int nt = 0; nt < 8; nt++)
#pragma unroll
            for (int i = 0; i < 4; i++) acc[j][nt][i] = 0.f;

    fill(0, 0); CP_COMMIT();
    fill(1, 1); CP_COMMIT();

    for (int k = 0; k < NCH; k++) {
        int s = k & 1;
        if (k + 1 < NCH) { CP_WAIT1(); } else { CP_WAIT0(); }
        __syncthreads();
        uint32_t Ab = sb + s * STAGE;
#pragma unroll
        for (int ks = 0; ks < 4; ks++) {
            uint32_t ah[4], al[4];
            {
                int r = (w >> 1) * 16 + (lsub & 1) * 8 + lrow;
                uint32_t gran = ks * 2 + (lsub >> 1);
                uint32_t addr = Ab + r * 128 + ((gran * 16) ^ ((r & 7) << 4));
                LDSM4(ah, addr);
                LDSM4(al, addr + 16384);
            }
#pragma unroll
            for (int j = 0; j < 2; j++) {
                int zz = 2 * (w & 1) + j;
                uint32_t Bb = Ab + 32768 + zz * 16384;
#pragma unroll
                for (int p = 0; p < 4; p++) {
                    int nn = p * 16 + (lsub >> 1) * 8 + lrow;
                    uint32_t gran = ks * 2 + (lsub & 1);
                    uint32_t addr = Bb + nn * 128 + ((gran * 16) ^ ((nn & 7) << 4));
                    uint32_t bh[4], bl[4];
                    LDSM4(bh, addr);
                    LDSM4(bl, addr + 8192);
                    mma16816(acc[j][2 * p],     ah, bh[0], bh[1]);
                    mma16816(acc[j][2 * p + 1], ah, bh[2], bh[3]);
                    mma16816(acc[j][2 * p],     ah, bl[0], bl[1]);
                    mma16816(acc[j][2 * p + 1], ah, bl[2], bl[3]);
                    mma16816(acc[j][2 * p],     al, bh[0], bh[1]);
                    mma16816(acc[j][2 * p + 1], al, bh[2], bh[3]);
                }
            }
        }
        __syncthreads();
        if (k + 2 < NCH) fill(s, k + 2);
        CP_COMMIT();
    }

    // ---- epilogue: exchange gate fragments via smem, LSTM, write ----
    float* smf = (float*)smem;      // [zz][px128][oc64] fp32 = 128 KB
    __syncthreads();
#pragma unroll
    for (int j = 0; j < 2; j++) {
        int zz = 2 * (w & 1) + j;
#pragma unroll
        for (int half = 0; half < 2; half++) {
            int pxl = (w >> 1) * 16 + (lane >> 2) + half * 8;
#pragma unroll
            for (int nt = 0; nt < 8; nt++) {
                int oc0 = nt * 8 + (lane & 3) * 2;
                float2 v = make_float2(acc[j][nt][half * 2], acc[j][nt][half * 2 + 1]);
                *(float2*)(smf + zz * 8192 + pxl * 64 + oc0) = v;
            }
        }
    }
    __syncthreads();

    int n = hd >> 3;
#pragma unroll
    for (int i = 0; i < 16; i++) {
        int elem = i * 512 + tid;
        int pxl = elem >> 6, oc = elem & 63;
        float pi = smf[0 * 8192 + pxl * 64 + oc] + bbi[g * 64 + oc];
        float pf = smf[1 * 8192 + pxl * 64 + oc] + bbf[g * 64 + oc];
        float pg = smf[2 * 8192 + pxl * 64 + oc] + bbg[g * 64 + oc];
        float po = smf[3 * 8192 + pxl * 64 + oc] + bbo[g * 64 + oc];
        float ig = 1.f / (1.f + __expf(-pi));
        float fg = 1.f / (1.f + __expf(-pf));
        float gg = tanhf(pg);
        float og = 1.f / (1.f + __expf(-po));
        size_t ci = ((size_t)n * 512 + g * 64 + oc) * HW + tile * 128 + pxl;
        float cn = fg * cold[ci] + ig * gg;
        out[ci] = og * tanhf(cn);
    }
}

// ------------------------------------------------------------------
// attn_kernel: 512 threads, 256 queries, warp = 16 rows.
// SMEM: Qh 32K | Ql 32K | 2 x (Kh 8K|Kl 8K|Vh 8K|Vl 8K) = 128K.
// grid (9, 16).  s-domain max + ex2 softmax; mask only last chunk.
// ------------------------------------------------------------------
__global__ __launch_bounds__(512, 1) void attn_kernel(const float* __restrict__ tau)
{
    extern __shared__ char smem[];
    uint32_t sb = s2u(smem);
    const int tid = threadIdx.x, w = tid >> 5, lane = tid & 31;
    const int hd = blockIdx.y, g = hd & 7;
    const int qbase = blockIdx.x * 256;
    const int lsub = lane >> 3, lrow = lane & 7;
    const float ts2 = tau[g] * 1.44269504f;
    const int NCHK = (DS + 63) / 64;   // 34

    // Q fill (once)
    {
        int r = tid >> 1;
        int g0 = (tid & 1) * 4;
        const char* qh = (const char*)g_qh + ((size_t)hd * HW + qbase + r) * 128;
        const char* ql = (const char*)g_ql + ((size_t)hd * HW + qbase + r) * 128;
        uint32_t sw = (r & 7) << 4;
#pragma unroll
        for (int gg = 0; gg < 4; gg++) {
            int gc = g0 + gg;
            uint32_t off = r * 128 + ((gc * 16) ^ sw);
            cpa16(sb + off, qh + gc * 16, true);
            cpa16(sb + 32768 + off, ql + gc * 16, true);
        }
    }
    auto fillkv = [&](int s, int c) {
        uint32_t base = sb + 65536 + s * 32768;
        int r = tid >> 3;
        int gr = tid & 7;
        int d = c * 64 + r;
        bool ok = d < DS;
        size_t rb = ((size_t)hd * DPAD + (ok ? d : 0)) * 128;
        uint32_t off = r * 128 + ((gr * 16) ^ ((r & 7) << 4));
        cpa16(base + off,         (const char*)g_kh + rb + gr * 16, ok);
        cpa16(base + 8192 + off,  (const char*)g_kl + rb + gr * 16, ok);
        cpa16(base + 16384 + off, (const char*)g_vh + rb + gr * 16, ok);
        cpa16(base + 24576 + off, (const char*)g_vl + rb + gr * 16, ok);
    };

    fillkv(0, 0); CP_COMMIT();
    fillkv(1, 1); CP_COMMIT();

    float o[8][4];
#pragma unroll
    for (int nt = 0; nt < 8; nt++)
#pragma unroll
        for (int i = 0; i < 4; i++) o[nt][i] = 0.f;
    float mrow[2] = {-1e30f, -1e30f};
    float lsum[2] = {0.f, 0.f};

    for (int c = 0; c < NCHK; c++) {
        int s = c & 1;
        if (c + 1 < NCHK) { CP_WAIT1(); } else { CP_WAIT0(); }
        __syncthreads();
        uint32_t Kb = sb + 65536 + s * 32768;
        uint32_t Vb = Kb + 16384;

        float sf[8][4];
#pragma unroll
        for (int nt = 0; nt < 8; nt++)
#pragma unroll
            for (int i = 0; i < 4; i++) sf[nt][i] = 0.f;
#pragma unroll
        for (int ks = 0; ks < 4; ks++) {
            uint32_t ah[4], al[4];
            {
                int r = w * 16 + (lsub & 1) * 8 + lrow;
                uint32_t gran = ks * 2 + (lsub >> 1);
                uint32_t addr = sb + r * 128 + ((gran * 16) ^ ((r & 7) << 4));
                LDSM4(ah, addr);
                LDSM4(al, addr + 32768);
            }
#pragma unroll
            for (int p = 0; p < 4; p++) {
                int nn = p * 16 + (lsub >> 1) * 8 + lrow;
                uint32_t gran = ks * 2 + (lsub & 1);
                uint32_t addr = Kb + nn * 128 + ((gran * 16) ^ ((nn & 7) << 4));
                uint32_t bh[4], bl[4];
                LDSM4(bh, addr);
                LDSM4(bl, addr + 8192);
                mma16816(sf[2 * p],     ah, bh[0], bh[1]);
                mma16816(sf[2 * p + 1], ah, bh[2], bh[3]);
                mma16816(sf[2 * p],     ah, bl[0], bl[1]);
                mma16816(sf[2 * p + 1], ah, bl[2], bl[3]);
                mma16816(sf[2 * p],     al, bh[0], bh[1]);
                mma16816(sf[2 * p + 1], al, bh[2], bh[3]);
            }
        }

        // mask tail keys (only last chunk)
        if (c == NCHK - 1) {
            int dbase = c * 64 + (lane & 3) * 2;
#pragma unroll
            for (int nt = 0; nt < 8; nt++)
#pragma unroll
                for (int i = 0; i < 4; i++) {
                    int d = dbase + nt * 8 + (i & 1);
                    if (d >= DS) sf[nt][i] = -1e30f;
                }
        }

        // online softmax (s-domain max, ex2)
        float alpha[2];
#pragma unroll
        for (int h = 0; h < 2; h++) {
            float mx = mrow[h];
#pragma unroll
            for (int nt = 0; nt < 8; nt++) {
                mx = fmaxf(mx, sf[nt][h * 2]);
                mx = fmaxf(mx, sf[nt][h * 2 + 1]);
            }
            mx = fmaxf(mx, __shfl_xor_sync(0xffffffffu, mx, 1));
            mx = fmaxf(mx, __shfl_xor_sync(0xffffffffu, mx, 2));
            float nm = mx * ts2;
            float al_ = ex2(fmaf(mrow[h], ts2, -nm));
            mrow[h] = mx;
            alpha[h] = al_;
            float ls = lsum[h] * al_;
#pragma unroll
            for (int nt = 0; nt < 8; nt++) {
#pragma unroll
                for (int e = 0; e < 2; e++) {
                    float p = ex2(fmaf(sf[nt][h * 2 + e], ts2, -nm));
                    sf[nt][h * 2 + e] = p;
                    ls += p;
                }
            }
            lsum[h] = ls;
        }
#pragma unroll
        for (int nt = 0; nt < 8; nt++) {
            o[nt][0] *= alpha[0];
            o[nt][1] *= alpha[0];
            o[nt][2] *= alpha[1];
            o[nt][3] *= alpha[1];
        }

        // O += P V
#pragma unroll
        for (int kt = 0; kt < 4; kt++) {
            uint32_t pah[4], pal[4];
#pragma unroll
            for (int i = 0; i < 4; i++) {
                int nt = 2 * kt + (i >> 1);
                float p0 = sf[nt][(i & 1) * 2];
                float p1 = sf[nt][(i & 1) * 2 + 1];
                uint32_t ph = packbf(p0, p1);
                float r0 = p0 - __uint_as_float(ph << 16);
                float r1 = p1 - __uint_as_float(ph & 0xffff0000u);
                pah[i] = ph;
                pal[i] = packbf(r0, r1);
            }
#pragma unroll
            for (int np = 0; np < 4; np++) {
                int rr = kt * 16 + (lane & 15);
                uint32_t gran = np * 2 + (lane >> 4);
                uint32_t addr = Vb + rr * 128 + ((gran * 16) ^ ((rr & 7) << 4));
                uint32_t vh[4], vl[4];
                LDSM4T(vh, addr);
                LDSM4T(vl, addr + 8192);
                mma16816(o[2 * np],     pah, vh[0], vh[1]);
                mma16816(o[2 * np + 1], pah, vh[2], vh[3]);
                mma16816(o[2 * np],     pal, vh[0], vh[1]);
                mma16816(o[2 * np + 1], pal, vh[2], vh[3]);
                mma16816(o[2 * np],     pah, vl[0], vl[1]);
                mma16816(o[2 * np + 1], pah, vl[2], vl[3]);
            }
        }
        __syncthreads();
        if (c + 2 < NCHK) fillkv(s, c + 2);
        CP_COMMIT();
    }

    uint32_t* ah32 = (uint32_t*)g_ah;
    uint32_t* al32 = (uint32_t*)g_al;
#pragma unroll
    for (int h = 0; h < 2; h++) {
        float l = lsum[h];
        l += __shfl_xor_sync(0xffffffffu, l, 1);
        l += __shfl_xor_sync(0xffffffffu, l, 2);
        float inv = 1.f / l;
        int m = qbase + w * 16 + (lane >> 2) + h * 8;
        size_t rb = ((size_t)hd * HW + m) * 32;
#pragma unroll
        for (int nt = 0; nt < 8; nt++) {
            int ocp = nt * 4 + (lane & 3);
            float v0 = o[nt][h * 2] * inv;
            float v1 = o[nt][h * 2 + 1] * inv;
            uint32_t h0, l0, h1, l1;
            bsplit(v0, h0, l0); bsplit(v1, h1, l1);
            ah32[rb + ocp] = h0 | (h1 << 16);
            al32[rb + ocp] = l0 | (l1 << 16);
        }
    }
}

// ------------------------------------------------------------------
extern "C" void kernel_launch(void* const* d_in, const int* in_sizes, int n_in,
                              void* d_out, int out_size)
{
    const float* x_in = (const float*)d_in[0];
    const float* h    = (const float*)d_in[1];
    const float* c    = (const float*)d_in[2];
    const float* tau  = (const float*)d_in[3];
    const float* Wx   = (const float*)d_in[4];
    const float* Wig  = (const float*)d_in[5];
    const float* Wq   = (const float*)d_in[6];
    const float* Wk   = (const float*)d_in[7];
    const float* Wv   = (const float*)d_in[8];
    const float* Wia  = (const float*)d_in[9];
    const float* Wix  = (const float*)d_in[10];
    const float* bi   = (const float*)d_in[11];
    const float* Wfa  = (const float*)d_in[12];
    const float* Wfx  = (const float*)d_in[13];
    const float* bf   = (const float*)d_in[14];
    const float* Wga  = (const float*)d_in[15];
    const float* Wgx  = (const float*)d_in[16];
    const float* bg   = (const float*)d_in[17];
    const float* Woa  = (const float*)d_in[18];
    const float* Wox  = (const float*)d_in[19];
    const float* bo   = (const float*)d_in[20];
    float* out = (float*)d_out;

    const int PSMEM = 2 * 65536;            // 128 KB proj
    const int QSMEM = 2 * 81920;            // 160 KB qkv
    const int GSMEM = 2 * 98304;            // 192 KB gates
    const int ASMEM = 65536 + 2 * 32768;    // 128 KB attn
    cudaFuncSetAttribute(proj_mma,
                         cudaFuncAttributeMaxDynamicSharedMemorySize, PSMEM);
    cudaFuncSetAttribute(qkv_kernel,
                         cudaFuncAttributeMaxDynamicSharedMemorySize, QSMEM);
    cudaFuncSetAttribute(gate_kernel,
                         cudaFuncAttributeMaxDynamicSharedMemorySize, GSMEM);
    cudaFuncSetAttribute(attn_kernel,
                         cudaFuncAttributeMaxDynamicSharedMemorySize, ASMEM);

    prep_w<<<8512, 256>>>(Wq, Wk, Wv, Wix, Wfx, Wgx, Wox, Wia, Wfa, Wga, Woa);
    prep_pw<<<768, 256>>>(Wx, Wig);
    prep_x<<<dim3(18, 12, 2), 256>>>(x_in, h);
    proj_mma<<<dim3(18, 4, 2), 512, PSMEM>>>();
    qkv_kernel<<<dim3(18, 16), 512, QSMEM>>>();
    attn_kernel<<<dim3(9, 16), 512, ASMEM>>>(tau);
    gate_kernel<<<dim3(18, 16), 512, GSMEM>>>(bi, bf, bg, bo, c, out);
}

// round 11
// speedup vs baseline: 6.1347x; 1.3462x over previous
#include <cuda_runtime.h>
#include <cuda_fp16.h>
#include <math.h>
#include <stdint.h>

#define NB   2
#define CINC 256
#define CT   512
#define HH   48
#define HW   2304
#define DS   2116
#define DPAD 2176
#define TOT  (NB*CT*HW)

// fp16 2-term split: v ~= hi + lo (22-bit effective)
__device__ __forceinline__ void hsplit(float v, uint32_t& h16, uint32_t& l16) {
    __half hh = __float2half_rn(v);
    __half hl = __float2half_rn(v - __half2float(hh));
    h16 = (uint32_t)__half_as_ushort(hh);
    l16 = (uint32_t)__half_as_ushort(hl);
}
__device__ __forceinline__ uint32_t packh(float lo, float hi) {
    uint32_t r;
    asm("cvt.rn.f16x2.f32 %0, %1, %2;" : "=r"(r) : "f"(hi), "f"(lo));
    return r;
}
__device__ __forceinline__ float ex2(float x) {
    float y; asm("ex2.approx.f32 %0, %1;" : "=f"(y) : "f"(x)); return y;
}

// ---------------- scratch ----------------
#define XHPS (16 * HW * 128)
__device__ __align__(256) __half g_xhp[2 * XHPS];              // [split][hd][px][128]
__device__ __align__(256) uint32_t g_wb32[7 * 8 * 19 * 2048];  // conv W fp16 imgs
__device__ __align__(256) uint32_t g_wpb32[8 * 12 * 2048];     // proj W fp16 imgs
__device__ __align__(256) uint32_t g_apm_h[NB * HW * 384];     // proj A hi [n][px][768]
__device__ __align__(256) uint32_t g_apm_l[NB * HW * 384];
__device__ __align__(256) __half g_qh[16 * HW * 64];
__device__ __align__(256) __half g_ql[16 * HW * 64];
__device__ __align__(256) __half g_k [16 * DPAD * 64];         // single fp16
__device__ __align__(256) __half g_v [16 * DPAD * 64];
__device__ __align__(256) __half g_ah[16 * HW * 64];
__device__ __align__(256) __half g_al[16 * HW * 64];

// ---------------- cp.async ----------------
__device__ __forceinline__ uint32_t s2u(const void* p) {
    return (uint32_t)__cvta_generic_to_shared(p);
}
__device__ __forceinline__ void cpa16(uint32_t dst, const void* src, bool pred) {
    int sz = pred ? 16 : 0;
    asm volatile("cp.async.cg.shared.global [%0], [%1], 16, %2;\n"
                 :: "r"(dst), "l"(src), "r"(sz) : "memory");
}
#define CP_COMMIT() asm volatile("cp.async.commit_group;\n" ::: "memory")
#define CP_WAIT0()  asm volatile("cp.async.wait_group 0;\n" ::: "memory")
#define CP_WAIT1()  asm volatile("cp.async.wait_group 1;\n" ::: "memory")

// ---------------- mma.sync helpers (fp16 in, fp32 accum) ----------------
#define LDSM4(r, a) \
    asm volatile("ldmatrix.sync.aligned.m8n8.x4.shared.b16 {%0,%1,%2,%3}, [%4];" \
                 : "=r"((r)[0]), "=r"((r)[1]), "=r"((r)[2]), "=r"((r)[3]) : "r"(a))
#define LDSM4T(r, a) \
    asm volatile("ldmatrix.sync.aligned.m8n8.x4.trans.shared.b16 {%0,%1,%2,%3}, [%4];" \
                 : "=r"((r)[0]), "=r"((r)[1]), "=r"((r)[2]), "=r"((r)[3]) : "r"(a))

__device__ __forceinline__ void mma16816(float* d, const uint32_t* a,
                                         uint32_t b0, uint32_t b1) {
    asm volatile(
        "mma.sync.aligned.m16n8k16.row.col.f32.f16.f16.f32 "
        "{%0,%1,%2,%3}, {%4,%5,%6,%7}, {%8,%9}, {%0,%1,%2,%3};"
        : "+f"(d[0]), "+f"(d[1]), "+f"(d[2]), "+f"(d[3])
        : "r"(a[0]), "r"(a[1]), "r"(a[2]), "r"(a[3]), "r"(b0), "r"(b1));
}

// ------------------------------------------------------------------
// prep_w: conv weights -> single fp16 images (64oc x 64ch)
// ------------------------------------------------------------------
__global__ void prep_w(const float* __restrict__ Wq, const float* __restrict__ Wk,
                       const float* __restrict__ Wv,
                       const float* __restrict__ Wix, const float* __restrict__ Wfx,
                       const float* __restrict__ Wgx, const float* __restrict__ Wox,
                       const float* __restrict__ Wia, const float* __restrict__ Wfa,
                       const float* __restrict__ Wga, const float* __restrict__ Woa)
{
    int idx = blockIdx.x * 256 + threadIdx.x;
    if (idx >= 7 * 8 * 19 * 64 * 32) return;
    int c2    = idx & 31;
    int oc    = (idx >> 5) & 63;
    int rem   = idx >> 11;
    int chunk = rem % 19;
    int g     = (rem / 19) & 7;
    int type  = rem / 152;
    if (type < 3 && chunk == 18) return;

    float w0, w1;
    if (chunk < 18) {
        const float* W3 = (type == 0) ? Wq : (type == 1) ? Wk : (type == 2) ? Wv :
                          (type == 3) ? Wix : (type == 4) ? Wfx : (type == 5) ? Wgx : Wox;
        int t9 = chunk >> 1, cb = chunk & 1;
        size_t b = ((size_t)(g * 64 + oc) * 128 + cb * 64 + c2 * 2) * 9 + t9;
        w0 = W3[b]; w1 = W3[b + 9];
    } else {
        const float* Wa = (type == 3) ? Wia : (type == 4) ? Wfa : (type == 5) ? Wga : Woa;
        size_t b = (size_t)(g * 64 + oc) * 64 + c2 * 2;
        w0 = Wa[b]; w1 = Wa[b + 1];
    }
    g_wb32[(size_t)rem * 2048 + oc * 32 + c2] = packh(w0, w1);
}

// ------------------------------------------------------------------
// prep_pw: proj weights -> single fp16 images
// ------------------------------------------------------------------
__global__ void prep_pw(const float* __restrict__ Wx, const float* __restrict__ Wig)
{
    int idx = blockIdx.x * 256 + threadIdx.x;
    if (idx >= 8 * 12 * 64 * 32) return;
    int c2    = idx & 31;
    int oc    = (idx >> 5) & 63;
    int rem   = idx >> 11;
    int chunk = rem % 12;
    int g     = rem / 12;

    float w0, w1;
    if (chunk < 4) {
        size_t b = (size_t)(g * 64 + oc) * 256 + chunk * 64 + c2 * 2;
        w0 = Wx[b]; w1 = Wx[b + 1];
    } else {
        size_t b = (size_t)(g * 64 + oc) * 512 + (chunk - 4) * 64 + c2 * 2;
        w0 = Wig[b]; w1 = Wig[b + 1];
    }
    g_wpb32[(size_t)rem * 2048 + oc * 32 + c2] = packh(w0, w1);
}

// ------------------------------------------------------------------
// prep_x: transpose x_in+h -> pixel-major fp16 hi/lo + xh h-half
// ------------------------------------------------------------------
__global__ __launch_bounds__(256) void prep_x(
    const float* __restrict__ x_in, const float* __restrict__ h)
{
    __shared__ float t[64][129];
    int px0 = blockIdx.x * 128;
    int chb = blockIdx.y;
    int n   = blockIdx.z;
    int tid = threadIdx.x;

    for (int i = tid; i < 64 * 128; i += 256) {
        int cl = i >> 7, p = i & 127;
        int ch = chb * 64 + cl;
        float v = (ch < 256)
            ? x_in[((size_t)n * 256 + ch) * HW + px0 + p]
            : h[((size_t)n * 512 + (ch - 256)) * HW + px0 + p];
        t[cl][p] = v;
    }
    __syncthreads();

    for (int i = tid; i < 128 * 32; i += 256) {
        int p = i >> 5, c2 = i & 31;
        float v0 = t[c2 * 2][p], v1 = t[c2 * 2 + 1][p];
        uint32_t h0, l0, h1, l1;
        hsplit(v0, h0, l0); hsplit(v1, h1, l1);
        uint32_t hv = h0 | (h1 << 16), lv = l0 | (l1 << 16);
        size_t of = ((size_t)n * HW + px0 + p) * 384 + chb * 32 + c2;
        g_apm_h[of] = hv;
        g_apm_l[of] = lv;
        if (chb >= 4) {
            int g = chb - 4;
            size_t of2 = ((size_t)(n * 8 + g) * HW + px0 + p) * 64 + 32 + c2;
            ((uint32_t*)g_xhp)[of2] = hv;
            ((uint32_t*)(g_xhp + XHPS))[of2] = lv;
        }
    }
}

// ------------------------------------------------------------------
// proj_mma: dense GEMM, N=128 block, 512 threads, 3-stage pipeline.
// stage: Ah 16K | Al 16K | B 16K = 48K; x3 = 144K.
// ------------------------------------------------------------------
__global__ __launch_bounds__(512, 1) void proj_mma()
{
    extern __shared__ char smem[];
    const int STAGE = 49152;
    uint32_t sb = s2u(smem);
    const int tid = threadIdx.x, w = tid >> 5, lane = tid & 31;
    const int nb = blockIdx.y, n = blockIdx.z;
    const int tile = blockIdx.x;
    const int NCH = 12;
    const int lsub = lane >> 3, lrow = lane & 7;

    auto fill = [&](int s, int k) {
        uint32_t base = sb + s * STAGE;
        {
            int r = tid >> 2, q = tid & 3;
            int px = tile * 128 + r;
            const uint32_t* srch = g_apm_h + ((size_t)n * HW + px) * 384 + k * 32;
            const uint32_t* srcl = g_apm_l + ((size_t)n * HW + px) * 384 + k * 32;
            uint32_t sw = (r & 7) << 4;
#pragma unroll
            for (int j = 0; j < 2; j++) {
                int gc = q * 2 + j;
                uint32_t off = r * 128 + ((gc * 16) ^ sw);
                cpa16(base + off, srch + gc * 4, true);
                cpa16(base + 16384 + off, srcl + gc * 4, true);
            }
        }
#pragma unroll
        for (int i = 0; i < 2; i++) {
            int p = tid + i * 512;        // 0..1023
            int row = p >> 3, gr = p & 7;
            int srctile = (nb * 2 + (row >> 6)) * 12 + k;
            int srow = row & 63;
            const uint32_t* src = g_wpb32 + (size_t)srctile * 2048 + srow * 32 + gr * 4;
            uint32_t off = row * 128 + ((gr * 16) ^ ((row & 7) << 4));
            cpa16(base + 32768 + off, src, true);
        }
    };

    float acc[8][4];
#pragma unroll
    for (int nt = 0; nt < 8; nt++)
#pragma unroll
        for (int i = 0; i < 4; i++) acc[nt][i] = 0.f;

    fill(0, 0); CP_COMMIT();
    fill(1, 1); CP_COMMIT();

    for (int k = 0; k < NCH; k++) {
        int s = k % 3;
        if (k + 1 < NCH) { CP_WAIT1(); } else { CP_WAIT0(); }
        __syncthreads();
        if (k + 2 < NCH) { fill((k + 2) % 3, k + 2); CP_COMMIT(); }
        uint32_t Ab = sb + s * STAGE;
        uint32_t Bb = Ab + 32768;
#pragma unroll
        for (int ks = 0; ks < 4; ks++) {
            uint32_t ah[4], al[4];
            {
                int r = (w >> 1) * 16 + (lsub & 1) * 8 + lrow;
                uint32_t gran = ks * 2 + (lsub >> 1);
                uint32_t addr = Ab + r * 128 + ((gran * 16) ^ ((r & 7) << 4));
                LDSM4(ah, addr);
                LDSM4(al, addr + 16384);
            }
#pragma unroll
            for (int p = 0; p < 4; p++) {
                int nn = (w & 1) * 64 + p * 16 + (lsub >> 1) * 8 + lrow;
                uint32_t gran = ks * 2 + (lsub & 1);
                uint32_t addr = Bb + nn * 128 + ((gran * 16) ^ ((nn & 7) << 4));
                uint32_t bq[4];
                LDSM4(bq, addr);
                mma16816(acc[2 * p],     ah, bq[0], bq[1]);
                mma16816(acc[2 * p + 1], ah, bq[2], bq[3]);
                mma16816(acc[2 * p],     al, bq[0], bq[1]);
                mma16816(acc[2 * p + 1], al, bq[2], bq[3]);
            }
        }
    }

    int hd = n * 8 + nb * 2 + (w & 1);
    uint32_t* xhh = (uint32_t*)g_xhp;
    uint32_t* xhl = (uint32_t*)(g_xhp + XHPS);
#pragma unroll
    for (int half = 0; half < 2; half++) {
        int m = tile * 128 + (w >> 1) * 16 + (lane >> 2) + half * 8;
        size_t rb = ((size_t)hd * HW + m) * 64;
#pragma unroll
        for (int nt = 0; nt < 8; nt++) {
            int ocp = nt * 4 + (lane & 3);
            uint32_t h0, l0, h1, l1;
            hsplit(acc[nt][half * 2],     h0, l0);
            hsplit(acc[nt][half * 2 + 1], h1, l1);
            xhh[rb + ocp] = h0 | (h1 << 16);
            xhl[rb + ocp] = l0 | (l1 << 16);
        }
    }
}

// ------------------------------------------------------------------
// qkv_kernel: 512 threads, 3-stage.  stage: A 32K + 3x8K B = 56K.
// warp = (px16 = w>>1, 32-oc half = w&1) of each of q/k/v.
// ------------------------------------------------------------------
__global__ __launch_bounds__(512, 1) void qkv_kernel()
{
    extern __shared__ char smem[];
    const int STAGE = 57344;
    uint32_t sb = s2u(smem);
    const int tid = threadIdx.x, w = tid >> 5, lane = tid & 31;
    const int hd = blockIdx.y, g = hd & 7;
    const int tile = blockIdx.x;
    const int NCH = 18;
    const int lsub = lane >> 3, lrow = lane & 7;

    auto fill = [&](int s, int k) {
        uint32_t base = sb + s * STAGE;
        {
            int r = tid >> 2, q = tid & 3;
            int px_ = tile * 128 + r;
            int py_ = px_ / 48, pxx_ = px_ - py_ * 48;
            int t9 = k >> 1, cb = k & 1, ky = t9 / 3, kx = t9 - ky * 3;
            int iy = py_ + ky - 1, ix = pxx_ + kx - 1;
            bool in = ((unsigned)iy < 48u) && ((unsigned)ix < 48u);
            const __half* rp =
                g_xhp + (((size_t)hd * HW + iy * 48 + ix) * 128 + cb * 64);
            if (!in) rp = g_xhp;
            const char* sh = (const char*)rp;
            const char* sl = (const char*)(rp + XHPS);
            uint32_t sw = (r & 7) << 4;
#pragma unroll
            for (int j = 0; j < 2; j++) {
                int gc = q * 2 + j;
                uint32_t off = r * 128 + ((gc * 16) ^ sw);
                cpa16(base + off, sh + gc * 16, in);
                cpa16(base + 16384 + off, sl + gc * 16, in);
            }
        }
#pragma unroll
        for (int i = 0; i < 3; i++) {
            int p = tid + i * 512;        // 0..1535
            int zz = p >> 9, pg = p & 511;
            int oc = pg >> 3, gr = pg & 7;
            uint32_t off = oc * 128 + ((gr * 16) ^ ((oc & 7) << 4));
            const uint32_t* wsrc =
                g_wb32 + ((size_t)(zz * 8 + g) * 19 + k) * 2048;
            cpa16(base + 32768 + zz * 8192 + off, wsrc + pg * 4, true);
        }
    };

    float acc[3][4][4];
#pragma unroll
    for (int zz = 0; zz < 3; zz++)
#pragma unroll
        for (int nt = 0; nt < 4; nt++)
#pragma unroll
            for (int i = 0; i < 4; i++) acc[zz][nt][i] = 0.f;

    fill(0, 0); CP_COMMIT();
    fill(1, 1); CP_COMMIT();

    for (int k = 0; k < NCH; k++) {
        int s = k % 3;
        if (k + 1 < NCH) { CP_WAIT1(); } else { CP_WAIT0(); }
        __syncthreads();
        if (k + 2 < NCH) { fill((k + 2) % 3, k + 2); CP_COMMIT(); }
        uint32_t Ab = sb + s * STAGE;
#pragma unroll
        for (int ks = 0; ks < 4; ks++) {
            uint32_t ah[4], al[4];
            {
                int r = (w >> 1) * 16 + (lsub & 1) * 8 + lrow;
                uint32_t gran = ks * 2 + (lsub >> 1);
                uint32_t addr = Ab + r * 128 + ((gran * 16) ^ ((r & 7) << 4));
                LDSM4(ah, addr);
                LDSM4(al, addr + 16384);
            }
#pragma unroll
            for (int zz = 0; zz < 3; zz++) {
                uint32_t Bb = Ab + 32768 + zz * 8192;
#pragma unroll
                for (int p = 0; p < 2; p++) {
                    int nn = (w & 1) * 32 + p * 16 + (lsub >> 1) * 8 + lrow;
                    uint32_t gran = ks * 2 + (lsub & 1);
                    uint32_t addr = Bb + nn * 128 + ((gran * 16) ^ ((nn & 7) << 4));
                    uint32_t bq[4];
                    LDSM4(bq, addr);
                    mma16816(acc[zz][2 * p],     ah, bq[0], bq[1]);
                    mma16816(acc[zz][2 * p + 1], ah, bq[2], bq[3]);
                    mma16816(acc[zz][2 * p],     al, bq[0], bq[1]);
                    mma16816(acc[zz][2 * p + 1], al, bq[2], bq[3]);
                }
            }
        }
    }

    uint32_t* qh32 = (uint32_t*)g_qh;
    uint32_t* ql32 = (uint32_t*)g_ql;
#pragma unroll
    for (int half = 0; half < 2; half++) {
        int m = tile * 128 + (w >> 1) * 16 + (lane >> 2) + half * 8;
        {
            size_t rb = ((size_t)hd * HW + m) * 32;
#pragma unroll
            for (int nt = 0; nt < 4; nt++) {
                int ocp = (w & 1) * 16 + nt * 4 + (lane & 3);
                uint32_t h0, l0, h1, l1;
                hsplit(acc[0][nt][half * 2],     h0, l0);
                hsplit(acc[0][nt][half * 2 + 1], h1, l1);
                qh32[rb + ocp] = h0 | (h1 << 16);
                ql32[rb + ocp] = l0 | (l1 << 16);
            }
        }
        int oy = m / 48, ox = m - oy * 48;
        if (oy >= 1 && oy <= 46 && ox >= 1 && ox <= 46) {
            int d = (oy - 1) * 46 + (ox - 1);
            size_t rb = ((size_t)hd * DPAD + d) * 32;
#pragma unroll
            for (int zz = 1; zz < 3; zz++) {
                uint32_t* dst = (uint32_t*)((zz == 1) ? g_k : g_v);
#pragma unroll
                for (int nt = 0; nt < 4; nt++) {
                    int ocp = (w & 1) * 16 + nt * 4 + (lane & 3);
                    dst[rb + ocp] = packh(acc[zz][nt][half * 2],
                                          acc[zz][nt][half * 2 + 1]);
                }
            }
        }
    }
}

// ------------------------------------------------------------------
// gate_kernel: 512 threads, 3-stage.  stage: A 32K + 4x8K B = 64K.
// warp = (px16 = w>>1, 2 gates = w&1).  LSTM fused via smem exchange.
// ------------------------------------------------------------------
__global__ __launch_bounds__(512, 1) void gate_kernel(
    const float* __restrict__ bbi, const float* __restrict__ bbf,
    const float* __restrict__ bbg, const float* __restrict__ bbo,
    const float* __restrict__ cold, float* __restrict__ out)
{
    extern __shared__ char smem[];
    const int STAGE = 65536;
    uint32_t sb = s2u(smem);
    const int tid = threadIdx.x, w = tid >> 5, lane = tid & 31;
    const int hd = blockIdx.y, g = hd & 7;
    const int tile = blockIdx.x;
    const int NCH = 19;
    const int lsub = lane >> 3, lrow = lane & 7;

    auto fill = [&](int s, int k) {
        uint32_t base = sb + s * STAGE;
        {
            int r = tid >> 2, q = tid & 3;
            int px_ = tile * 128 + r;
            const char *sh, *sl; bool in;
            if (k < 18) {
                int py_ = px_ / 48, pxx_ = px_ - py_ * 48;
                int t9 = k >> 1, cb = k & 1, ky = t9 / 3, kx = t9 - ky * 3;
                int iy = py_ + ky - 1, ix = pxx_ + kx - 1;
                in = ((unsigned)iy < 48u) && ((unsigned)ix < 48u);
                const __half* rp =
                    g_xhp + (((size_t)hd * HW + iy * 48 + ix) * 128 + cb * 64);
                if (!in) rp = g_xhp;
                sh = (const char*)rp;
                sl = (const char*)(rp + XHPS);
            } else {
                in = true;
                sh = (const char*)(g_ah + ((size_t)hd * HW + px_) * 64);
                sl = (const char*)(g_al + ((size_t)hd * HW + px_) * 64);
            }
            uint32_t sw = (r & 7) << 4;
#pragma unroll
            for (int j = 0; j < 2; j++) {
                int gc = q * 2 + j;
                uint32_t off = r * 128 + ((gc * 16) ^ sw);
                cpa16(base + off, sh + gc * 16, in);
                cpa16(base + 16384 + off, sl + gc * 16, in);
            }
        }
#pragma unroll
        for (int i = 0; i < 4; i++) {
            int p = tid + i * 512;        // 0..2047
            int zz = p >> 9, pg = p & 511;
            int oc = pg >> 3, gr = pg & 7;
            uint32_t off = oc * 128 + ((gr * 16) ^ ((oc & 7) << 4));
            const uint32_t* wsrc =
                g_wb32 + ((size_t)((3 + zz) * 8 + g) * 19 + k) * 2048;
            cpa16(base + 32768 + zz * 8192 + off, wsrc + pg * 4, true);
        }
    };

    float acc[2][8][4];
#pragma unroll
    for (int j = 0; j < 2; j++)
#pragma unroll
        for (int nt = 0; nt < 8; nt++)
#pragma unroll
            for (int i = 0; i < 4; i++) acc[j][nt][i] = 0.f;

    fill(0, 0); CP_COMMIT();
    fill(1, 1); CP_COMMIT();

    for (int k = 0; k < NCH; k++) {
        int s = k % 3;
        if (k + 1 < NCH) { CP_WAIT1(); } else { CP_WAIT0(); }
        __syncthreads();
        if (k + 2 < NCH) { fill((k + 2) % 3, k + 2); CP_COMMIT(); }
        uint32_t Ab = sb + s * STAGE;
#pragma unroll
        for (int ks = 0; ks < 4; ks++) {
            uint32_t ah[4], al[4];
            {
                int r = (w >> 1) * 16 + (lsub & 1) * 8 + lrow;
                uint32_t gran = ks * 2 + (lsub >> 1);
                uint32_t addr = Ab + r * 128 + ((gran * 16) ^ ((r & 7) << 4));
                LDSM4(ah, addr);
                LDSM4(al, addr + 16384);
            }
#pragma unroll
            for (int j = 0; j < 2; j++) {
                int zz = 2 * (w & 1) + j;
                uint32_t Bb = Ab + 32768 + zz * 8192;
#pragma unroll
                for (int p = 0; p < 4; p++) {
                    int nn = p * 16 + (lsub >> 1) * 8 + lrow;
                    uint32_t gran = ks * 2 + (lsub & 1);
                    uint32_t addr = Bb + nn * 128 + ((gran * 16) ^ ((nn & 7) << 4));
                    uint32_t bq[4];
                    LDSM4(bq, addr);
                    mma16816(acc[j][2 * p],     ah, bq[0], bq[1]);
                    mma16816(acc[j][2 * p + 1], ah, bq[2], bq[3]);
                    mma16816(acc[j][2 * p],     al, bq[0], bq[1]);
                    mma16816(acc[j][2 * p + 1], al, bq[2], bq[3]);
                }
            }
        }
    }

    // ---- epilogue: exchange gate fragments via smem, LSTM, write ----
    float* smf = (float*)smem;      // [zz][px128][oc64] fp32 = 128 KB
    __syncthreads();
#pragma unroll
    for (int j = 0; j < 2; j++) {
        int zz = 2 * (w & 1) + j;
#pragma unroll
        for (int half = 0; half < 2; half++) {
            int pxl = (w >> 1) * 16 + (lane >> 2) + half * 8;
#pragma unroll
            for (int nt = 0; nt < 8; nt++) {
                int oc0 = nt * 8 + (lane & 3) * 2;
                float2 v = make_float2(acc[j][nt][half * 2], acc[j][nt][half * 2 + 1]);
                *(float2*)(smf + zz * 8192 + pxl * 64 + oc0) = v;
            }
        }
    }
    __syncthreads();

    int n = hd >> 3;
#pragma unroll
    for (int i = 0; i < 16; i++) {
        int elem = i * 512 + tid;
        int pxl = elem >> 6, oc = elem & 63;
        float pi = smf[0 * 8192 + pxl * 64 + oc] + bbi[g * 64 + oc];
        float pf = smf[1 * 8192 + pxl * 64 + oc] + bbf[g * 64 + oc];
        float pg = smf[2 * 8192 + pxl * 64 + oc] + bbg[g * 64 + oc];
        float po = smf[3 * 8192 + pxl * 64 + oc] + bbo[g * 64 + oc];
        float ig = 1.f / (1.f + __expf(-pi));
        float fg = 1.f / (1.f + __expf(-pf));
        float gg = tanhf(pg);
        float og = 1.f / (1.f + __expf(-po));
        size_t ci = ((size_t)n * 512 + g * 64 + oc) * HW + tile * 128 + pxl;
        float cn = fg * cold[ci] + ig * gg;
        out[ci] = og * tanhf(cn);
    }
}

// ------------------------------------------------------------------
// attn_kernel: 512 threads, 256 queries, 3-stage KV.
// SMEM: Qh 32K | Ql 32K | 3 x (K 8K | V 8K) = 112K.  grid (9, 16).
// ------------------------------------------------------------------
__global__ __launch_bounds__(512, 1) void attn_kernel(const float* __restrict__ tau)
{
    extern __shared__ char smem[];
    uint32_t sb = s2u(smem);
    const int tid = threadIdx.x, w = tid >> 5, lane = tid & 31;
    const int hd = blockIdx.y, g = hd & 7;
    const int qbase = blockIdx.x * 256;
    const int lsub = lane >> 3, lrow = lane & 7;
    const float ts2 = tau[g] * 1.44269504f;
    const int NCHK = (DS + 63) / 64;   // 34

    // Q fill (once)
    {
        int r = tid >> 1;
        int g0 = (tid & 1) * 4;
        const char* qh = (const char*)g_qh + ((size_t)hd * HW + qbase + r) * 128;
        const char* ql = (const char*)g_ql + ((size_t)hd * HW + qbase + r) * 128;
        uint32_t sw = (r & 7) << 4;
#pragma unroll
        for (int gg = 0; gg < 4; gg++) {
            int gc = g0 + gg;
            uint32_t off = r * 128 + ((gc * 16) ^ sw);
            cpa16(sb + off, qh + gc * 16, true);
            cpa16(sb + 32768 + off, ql + gc * 16, true);
        }
    }
    auto fillkv = [&](int s, int c) {
        uint32_t base = sb + 65536 + s * 16384;
        int r = tid >> 3;
        int gr = tid & 7;
        int d = c * 64 + r;
        bool ok = d < DS;
        size_t rb = ((size_t)hd * DPAD + (ok ? d : 0)) * 128;  // bytes
        uint32_t off = r * 128 + ((gr * 16) ^ ((r & 7) << 4));
        cpa16(base + off,        (const char*)g_k + rb + gr * 16, ok);
        cpa16(base + 8192 + off, (const char*)g_v + rb + gr * 16, ok);
    };

    fillkv(0, 0); CP_COMMIT();
    fillkv(1, 1); CP_COMMIT();

    float o[8][4];
#pragma unroll
    for (int nt = 0; nt < 8; nt++)
#pragma unroll
        for (int i = 0; i < 4; i++) o[nt][i] = 0.f;
    float mrow[2] = {-1e30f, -1e30f};
    float lsum[2] = {0.f, 0.f};

    for (int c = 0; c < NCHK; c++) {
        int s = c % 3;
        if (c + 1 < NCHK) { CP_WAIT1(); } else { CP_WAIT0(); }
        __syncthreads();
        if (c + 2 < NCHK) { fillkv((c + 2) % 3, c + 2); CP_COMMIT(); }
        uint32_t Kb = sb + 65536 + s * 16384;
        uint32_t Vb = Kb + 8192;

        float sf[8][4];
#pragma unroll
        for (int nt = 0; nt < 8; nt++)
#pragma unroll
            for (int i = 0; i < 4; i++) sf[nt][i] = 0.f;
#pragma unroll
        for (int ks = 0; ks < 4; ks++) {
            uint32_t ah[4], al[4];
            {
                int r = w * 16 + (lsub & 1) * 8 + lrow;
                uint32_t gran = ks * 2 + (lsub >> 1);
                uint32_t addr = sb + r * 128 + ((gran * 16) ^ ((r & 7) << 4));
                LDSM4(ah, addr);
                LDSM4(al, addr + 32768);
            }
#pragma unroll
            for (int p = 0; p < 4; p++) {
                int nn = p * 16 + (lsub >> 1) * 8 + lrow;
                uint32_t gran = ks * 2 + (lsub & 1);
                uint32_t addr = Kb + nn * 128 + ((gran * 16) ^ ((nn & 7) << 4));
                uint32_t bq[4];
                LDSM4(bq, addr);
                mma16816(sf[2 * p],     ah, bq[0], bq[1]);
                mma16816(sf[2 * p + 1], ah, bq[2], bq[3]);
                mma16816(sf[2 * p],     al, bq[0], bq[1]);
                mma16816(sf[2 * p + 1], al, bq[2], bq[3]);
            }
        }

        // mask tail keys (only last chunk)
        if (c == NCHK - 1) {
            int dbase = c * 64 + (lane & 3) * 2;
#pragma unroll
            for (int nt = 0; nt < 8; nt++)
#pragma unroll
                for (int i = 0; i < 4; i++) {
                    int d = dbase + nt * 8 + (i & 1);
                    if (d >= DS) sf[nt][i] = -1e30f;
                }
        }

        // online softmax (s-domain max, ex2)
        float alpha[2];
#pragma unroll
        for (int h = 0; h < 2; h++) {
            float mx = mrow[h];
#pragma unroll
            for (int nt = 0; nt < 8; nt++) {
                mx = fmaxf(mx, sf[nt][h * 2]);
                mx = fmaxf(mx, sf[nt][h * 2 + 1]);
            }
            mx = fmaxf(mx, __shfl_xor_sync(0xffffffffu, mx, 1));
            mx = fmaxf(mx, __shfl_xor_sync(0xffffffffu, mx, 2));
            float nm = mx * ts2;
            float al_ = ex2(fmaf(mrow[h], ts2, -nm));
            mrow[h] = mx;
            alpha[h] = al_;
            float ls = lsum[h] * al_;
#pragma unroll
            for (int nt = 0; nt < 8; nt++) {
#pragma unroll
                for (int e = 0; e < 2; e++) {
                    float p = ex2(fmaf(sf[nt][h * 2 + e], ts2, -nm));
                    sf[nt][h * 2 + e] = p;
                    ls += p;
                }
            }
            lsum[h] = ls;
        }
#pragma unroll
        for (int nt = 0; nt < 8; nt++) {
            o[nt][0] *= alpha[0];
            o[nt][1] *= alpha[0];
            o[nt][2] *= alpha[1];
            o[nt][3] *= alpha[1];
        }

        // O += P V (P split, V single)
#pragma unroll
        for (int kt = 0; kt < 4; kt++) {
            uint32_t pah[4], pal[4];
#pragma unroll
            for (int i = 0; i < 4; i++) {
                int nt = 2 * kt + (i >> 1);
                float p0 = sf[nt][(i & 1) * 2];
                float p1 = sf[nt][(i & 1) * 2 + 1];
                __half p0h = __float2half_rn(p0), p1h = __float2half_rn(p1);
                pah[i] = (uint32_t)__half_as_ushort(p0h)
                       | ((uint32_t)__half_as_ushort(p1h) << 16);
                pal[i] = packh(p0 - __half2float(p0h), p1 - __half2float(p1h));
            }
#pragma unroll
            for (int np = 0; np < 4; np++) {
                int rr = kt * 16 + (lane & 15);
                uint32_t gran = np * 2 + (lane >> 4);
                uint32_t addr = Vb + rr * 128 + ((gran * 16) ^ ((rr & 7) << 4));
                uint32_t vq[4];
                LDSM4T(vq, addr);
                mma16816(o[2 * np],     pah, vq[0], vq[1]);
                mma16816(o[2 * np + 1], pah, vq[2], vq[3]);
                mma16816(o[2 * np],     pal, vq[0], vq[1]);
                mma16816(o[2 * np + 1], pal, vq[2], vq[3]);
            }
        }
    }

    uint32_t* ah32 = (uint32_t*)g_ah;
    uint32_t* al32 = (uint32_t*)g_al;
#pragma unroll
    for (int h = 0; h < 2; h++) {
        float l = lsum[h];
        l += __shfl_xor_sync(0xffffffffu, l, 1);
        l += __shfl_xor_sync(0xffffffffu, l, 2);
        float inv = 1.f / l;
        int m = qbase + w * 16 + (lane >> 2) + h * 8;
        size_t rb = ((size_t)hd * HW + m) * 32;
#pragma unroll
        for (int nt = 0; nt < 8; nt++) {
            int ocp = nt * 4 + (lane & 3);
            float v0 = o[nt][h * 2] * inv;
            float v1 = o[nt][h * 2 + 1] * inv;
            uint32_t h0, l0, h1, l1;
            hsplit(v0, h0, l0); hsplit(v1, h1, l1);
            ah32[rb + ocp] = h0 | (h1 << 16);
            al32[rb + ocp] = l0 | (l1 << 16);
        }
    }
}

// ------------------------------------------------------------------
extern "C" void kernel_launch(void* const* d_in, const int* in_sizes, int n_in,
                              void* d_out, int out_size)
{
    const float* x_in = (const float*)d_in[0];
    const float* h    = (const float*)d_in[1];
    const float* c    = (const float*)d_in[2];
    const float* tau  = (const float*)d_in[3];
    const float* Wx   = (const float*)d_in[4];
    const float* Wig  = (const float*)d_in[5];
    const float* Wq   = (const float*)d_in[6];
    const float* Wk   = (const float*)d_in[7];
    const float* Wv   = (const float*)d_in[8];
    const float* Wia  = (const float*)d_in[9];
    const float* Wix  = (const float*)d_in[10];
    const float* bi   = (const float*)d_in[11];
    const float* Wfa  = (const float*)d_in[12];
    const float* Wfx  = (const float*)d_in[13];
    const float* bf   = (const float*)d_in[14];
    const float* Wga  = (const float*)d_in[15];
    const float* Wgx  = (const float*)d_in[16];
    const float* bg   = (const float*)d_in[17];
    const float* Woa  = (const float*)d_in[18];
    const float* Wox  = (const float*)d_in[19];
    const float* bo   = (const float*)d_in[20];
    float* out = (float*)d_out;

    const int PSMEM = 3 * 49152;            // 144 KB proj
    const int QSMEM = 3 * 57344;            // 168 KB qkv
    const int GSMEM = 3 * 65536;            // 192 KB gates
    const int ASMEM = 65536 + 3 * 16384;    // 112 KB attn
    cudaFuncSetAttribute(proj_mma,
                         cudaFuncAttributeMaxDynamicSharedMemorySize, PSMEM);
    cudaFuncSetAttribute(qkv_kernel,
                         cudaFuncAttributeMaxDynamicSharedMemorySize, QSMEM);
    cudaFuncSetAttribute(gate_kernel,
                         cudaFuncAttributeMaxDynamicSharedMemorySize, GSMEM);
    cudaFuncSetAttribute(attn_kernel,
                         cudaFuncAttributeMaxDynamicSharedMemorySize, ASMEM);

    prep_w<<<8512, 256>>>(Wq, Wk, Wv, Wix, Wfx, Wgx, Wox, Wia, Wfa, Wga, Woa);
    prep_pw<<<768, 256>>>(Wx, Wig);
    prep_x<<<dim3(18, 12, 2), 256>>>(x_in, h);
    proj_mma<<<dim3(18, 4, 2), 512, PSMEM>>>();
    qkv_kernel<<<dim3(18, 16), 512, QSMEM>>>();
    attn_kernel<<<dim3(9, 16), 512, ASMEM>>>(tau);
    gate_kernel<<<dim3(18, 16), 512, GSMEM>>>(bi, bf, bg, bo, c, out);
}

// round 12
// speedup vs baseline: 8.9005x; 1.4508x over previous
#include <cuda_runtime.h>
#include <cuda_fp16.h>
#include <math.h>
#include <stdint.h>

#define NB   2
#define CINC 256
#define CT   512
#define HH   48
#define HW   2304
#define DS   2116
#define DPAD 2176
#define TOT  (NB*CT*HW)

__device__ __forceinline__ uint32_t packh(float lo, float hi) {
    uint32_t r;
    asm("cvt.rn.f16x2.f32 %0, %1, %2;" : "=r"(r) : "f"(hi), "f"(lo));
    return r;
}
__device__ __forceinline__ float ex2(float x) {
    float y; asm("ex2.approx.f32 %0, %1;" : "=f"(y) : "f"(x)); return y;
}

// ---------------- scratch (all single fp16) ----------------
#define XHPS (16 * HW * 128)
__device__ __align__(256) __half g_xhp[XHPS];                  // [hd][px][128]
__device__ __align__(256) uint32_t g_wb32[7 * 8 * 19 * 2048];  // conv W imgs
__device__ __align__(256) uint32_t g_wpb32[8 * 12 * 2048];     // proj W imgs
__device__ __align__(256) uint32_t g_apm[NB * HW * 384];       // proj A [n][px][768]
__device__ __align__(256) __half g_q[16 * HW * 64];
__device__ __align__(256) __half g_k[16 * DPAD * 64];
__device__ __align__(256) __half g_v[16 * DPAD * 64];
__device__ __align__(256) __half g_a[16 * HW * 64];

// ---------------- cp.async ----------------
__device__ __forceinline__ uint32_t s2u(const void* p) {
    return (uint32_t)__cvta_generic_to_shared(p);
}
__device__ __forceinline__ void cpa16(uint32_t dst, const void* src, bool pred) {
    int sz = pred ? 16 : 0;
    asm volatile("cp.async.cg.shared.global [%0], [%1], 16, %2;\n"
                 :: "r"(dst), "l"(src), "r"(sz) : "memory");
}
#define CP_COMMIT() asm volatile("cp.async.commit_group;\n" ::: "memory")
#define CP_WAIT0()  asm volatile("cp.async.wait_group 0;\n" ::: "memory")
#define CP_WAIT1()  asm volatile("cp.async.wait_group 1;\n" ::: "memory")

// ---------------- mma.sync helpers (fp16 in, fp32 accum) ----------------
#define LDSM4(r, a) \
    asm volatile("ldmatrix.sync.aligned.m8n8.x4.shared.b16 {%0,%1,%2,%3}, [%4];" \
                 : "=r"((r)[0]), "=r"((r)[1]), "=r"((r)[2]), "=r"((r)[3]) : "r"(a))
#define LDSM4T(r, a) \
    asm volatile("ldmatrix.sync.aligned.m8n8.x4.trans.shared.b16 {%0,%1,%2,%3}, [%4];" \
                 : "=r"((r)[0]), "=r"((r)[1]), "=r"((r)[2]), "=r"((r)[3]) : "r"(a))

__device__ __forceinline__ void mma16816(float* d, const uint32_t* a,
                                         uint32_t b0, uint32_t b1) {
    asm volatile(
        "mma.sync.aligned.m16n8k16.row.col.f32.f16.f16.f32 "
        "{%0,%1,%2,%3}, {%4,%5,%6,%7}, {%8,%9}, {%0,%1,%2,%3};"
        : "+f"(d[0]), "+f"(d[1]), "+f"(d[2]), "+f"(d[3])
        : "r"(a[0]), "r"(a[1]), "r"(a[2]), "r"(a[3]), "r"(b0), "r"(b1));
}

// ------------------------------------------------------------------
// prep_w: conv weights -> fp16 images (64oc x 64ch)
// ------------------------------------------------------------------
__global__ void prep_w(const float* __restrict__ Wq, const float* __restrict__ Wk,
                       const float* __restrict__ Wv,
                       const float* __restrict__ Wix, const float* __restrict__ Wfx,
                       const float* __restrict__ Wgx, const float* __restrict__ Wox,
                       const float* __restrict__ Wia, const float* __restrict__ Wfa,
                       const float* __restrict__ Wga, const float* __restrict__ Woa)
{
    int idx = blockIdx.x * 256 + threadIdx.x;
    if (idx >= 7 * 8 * 19 * 64 * 32) return;
    int c2    = idx & 31;
    int oc    = (idx >> 5) & 63;
    int rem   = idx >> 11;
    int chunk = rem % 19;
    int g     = (rem / 19) & 7;
    int type  = rem / 152;
    if (type < 3 && chunk == 18) return;

    float w0, w1;
    if (chunk < 18) {
        const float* W3 = (type == 0) ? Wq : (type == 1) ? Wk : (type == 2) ? Wv :
                          (type == 3) ? Wix : (type == 4) ? Wfx : (type == 5) ? Wgx : Wox;
        int t9 = chunk >> 1, cb = chunk & 1;
        size_t b = ((size_t)(g * 64 + oc) * 128 + cb * 64 + c2 * 2) * 9 + t9;
        w0 = W3[b]; w1 = W3[b + 9];
    } else {
        const float* Wa = (type == 3) ? Wia : (type == 4) ? Wfa : (type == 5) ? Wga : Woa;
        size_t b = (size_t)(g * 64 + oc) * 64 + c2 * 2;
        w0 = Wa[b]; w1 = Wa[b + 1];
    }
    g_wb32[(size_t)rem * 2048 + oc * 32 + c2] = packh(w0, w1);
}

// ------------------------------------------------------------------
// prep_pw: proj weights -> fp16 images
// ------------------------------------------------------------------
__global__ void prep_pw(const float* __restrict__ Wx, const float* __restrict__ Wig)
{
    int idx = blockIdx.x * 256 + threadIdx.x;
    if (idx >= 8 * 12 * 64 * 32) return;
    int c2    = idx & 31;
    int oc    = (idx >> 5) & 63;
    int rem   = idx >> 11;
    int chunk = rem % 12;
    int g     = rem / 12;

    float w0, w1;
    if (chunk < 4) {
        size_t b = (size_t)(g * 64 + oc) * 256 + chunk * 64 + c2 * 2;
        w0 = Wx[b]; w1 = Wx[b + 1];
    } else {
        size_t b = (size_t)(g * 64 + oc) * 512 + (chunk - 4) * 64 + c2 * 2;
        w0 = Wig[b]; w1 = Wig[b + 1];
    }
    g_wpb32[(size_t)rem * 2048 + oc * 32 + c2] = packh(w0, w1);
}

// ------------------------------------------------------------------
// prep_x: transpose x_in+h -> pixel-major fp16 + xh h-half
// ------------------------------------------------------------------
__global__ __launch_bounds__(256) void prep_x(
    const float* __restrict__ x_in, const float* __restrict__ h)
{
    __shared__ float t[64][129];
    int px0 = blockIdx.x * 128;
    int chb = blockIdx.y;
    int n   = blockIdx.z;
    int tid = threadIdx.x;

    for (int i = tid; i < 64 * 128; i += 256) {
        int cl = i >> 7, p = i & 127;
        int ch = chb * 64 + cl;
        float v = (ch < 256)
            ? x_in[((size_t)n * 256 + ch) * HW + px0 + p]
            : h[((size_t)n * 512 + (ch - 256)) * HW + px0 + p];
        t[cl][p] = v;
    }
    __syncthreads();

    for (int i = tid; i < 128 * 32; i += 256) {
        int p = i >> 5, c2 = i & 31;
        uint32_t hv = packh(t[c2 * 2][p], t[c2 * 2 + 1][p]);
        g_apm[((size_t)n * HW + px0 + p) * 384 + chb * 32 + c2] = hv;
        if (chb >= 4) {
            int g = chb - 4;
            ((uint32_t*)g_xhp)[((size_t)(n * 8 + g) * HW + px0 + p) * 64 + 32 + c2] = hv;
        }
    }
}

// ------------------------------------------------------------------
// proj_mma: dense GEMM, N=128, 512 threads, 3-stage (32K/stage).
// ------------------------------------------------------------------
__global__ __launch_bounds__(512, 1) void proj_mma()
{
    extern __shared__ char smem[];
    const int STAGE = 32768;
    uint32_t sb = s2u(smem);
    const int tid = threadIdx.x, w = tid >> 5, lane = tid & 31;
    const int nb = blockIdx.y, n = blockIdx.z;
    const int tile = blockIdx.x;
    const int NCH = 12;
    const int lsub = lane >> 3, lrow = lane & 7;

    auto fill = [&](int s, int k) {
        uint32_t base = sb + s * STAGE;
        {
            int r = tid >> 2, q = tid & 3;
            int px = tile * 128 + r;
            const uint32_t* src = g_apm + ((size_t)n * HW + px) * 384 + k * 32;
            uint32_t sw = (r & 7) << 4;
#pragma unroll
            for (int j = 0; j < 2; j++) {
                int gc = q * 2 + j;
                cpa16(base + r * 128 + ((gc * 16) ^ sw), src + gc * 4, true);
            }
        }
#pragma unroll
        for (int i = 0; i < 2; i++) {
            int p = tid + i * 512;
            int row = p >> 3, gr = p & 7;
            int srctile = (nb * 2 + (row >> 6)) * 12 + k;
            int srow = row & 63;
            const uint32_t* src = g_wpb32 + (size_t)srctile * 2048 + srow * 32 + gr * 4;
            cpa16(base + 16384 + row * 128 + ((gr * 16) ^ ((row & 7) << 4)), src, true);
        }
    };

    float acc[8][4];
#pragma unroll
    for (int nt = 0; nt < 8; nt++)
#pragma unroll
        for (int i = 0; i < 4; i++) acc[nt][i] = 0.f;

    fill(0, 0); CP_COMMIT();
    fill(1, 1); CP_COMMIT();

    for (int k = 0; k < NCH; k++) {
        int s = k % 3;
        if (k + 1 < NCH) { CP_WAIT1(); } else { CP_WAIT0(); }
        __syncthreads();
        if (k + 2 < NCH) { fill((k + 2) % 3, k + 2); CP_COMMIT(); }
        uint32_t Ab = sb + s * STAGE;
        uint32_t Bb = Ab + 16384;
#pragma unroll
        for (int ks = 0; ks < 4; ks++) {
            uint32_t aq[4];
            {
                int r = (w >> 1) * 16 + (lsub & 1) * 8 + lrow;
                uint32_t gran = ks * 2 + (lsub >> 1);
                LDSM4(aq, Ab + r * 128 + ((gran * 16) ^ ((r & 7) << 4)));
            }
#pragma unroll
            for (int p = 0; p < 4; p++) {
                int nn = (w & 1) * 64 + p * 16 + (lsub >> 1) * 8 + lrow;
                uint32_t gran = ks * 2 + (lsub & 1);
                uint32_t bq[4];
                LDSM4(bq, Bb + nn * 128 + ((gran * 16) ^ ((nn & 7) << 4)));
                mma16816(acc[2 * p],     aq, bq[0], bq[1]);
                mma16816(acc[2 * p + 1], aq, bq[2], bq[3]);
            }
        }
    }

    int hd = n * 8 + nb * 2 + (w & 1);
    uint32_t* xh32 = (uint32_t*)g_xhp;
#pragma unroll
    for (int half = 0; half < 2; half++) {
        int m = tile * 128 + (w >> 1) * 16 + (lane >> 2) + half * 8;
        size_t rb = ((size_t)hd * HW + m) * 64;
#pragma unroll
        for (int nt = 0; nt < 8; nt++) {
            int ocp = nt * 4 + (lane & 3);
            xh32[rb + ocp] = packh(acc[nt][half * 2], acc[nt][half * 2 + 1]);
        }
    }
}

// ------------------------------------------------------------------
// qkv_kernel: 512 threads, 3-stage (40K/stage: A 16K + 3x8K B).
// warp = (px16 = w>>1, 32-oc half = w&1) of each of q/k/v.
// ------------------------------------------------------------------
__global__ __launch_bounds__(512, 1) void qkv_kernel()
{
    extern __shared__ char smem[];
    const int STAGE = 40960;
    uint32_t sb = s2u(smem);
    const int tid = threadIdx.x, w = tid >> 5, lane = tid & 31;
    const int hd = blockIdx.y, g = hd & 7;
    const int tile = blockIdx.x;
    const int NCH = 18;
    const int lsub = lane >> 3, lrow = lane & 7;

    auto fill = [&](int s, int k) {
        uint32_t base = sb + s * STAGE;
        {
            int r = tid >> 2, q = tid & 3;
            int px_ = tile * 128 + r;
            int py_ = px_ / 48, pxx_ = px_ - py_ * 48;
            int t9 = k >> 1, cb = k & 1, ky = t9 / 3, kx = t9 - ky * 3;
            int iy = py_ + ky - 1, ix = pxx_ + kx - 1;
            bool in = ((unsigned)iy < 48u) && ((unsigned)ix < 48u);
            const __half* rp =
                g_xhp + (((size_t)hd * HW + iy * 48 + ix) * 128 + cb * 64);
            if (!in) rp = g_xhp;
            uint32_t sw = (r & 7) << 4;
#pragma unroll
            for (int j = 0; j < 2; j++) {
                int gc = q * 2 + j;
                cpa16(base + r * 128 + ((gc * 16) ^ sw),
                      (const char*)rp + gc * 16, in);
            }
        }
#pragma unroll
        for (int i = 0; i < 3; i++) {
            int p = tid + i * 512;
            int zz = p >> 9, pg = p & 511;
            int oc = pg >> 3, gr = pg & 7;
            const uint32_t* wsrc = g_wb32 + ((size_t)(zz * 8 + g) * 19 + k) * 2048;
            cpa16(base + 16384 + zz * 8192 + oc * 128 + ((gr * 16) ^ ((oc & 7) << 4)),
                  wsrc + pg * 4, true);
        }
    };

    float acc[3][4][4];
#pragma unroll
    for (int zz = 0; zz < 3; zz++)
#pragma unroll
        for (int nt = 0; nt < 4; nt++)
#pragma unroll
            for (int i = 0; i < 4; i++) acc[zz][nt][i] = 0.f;

    fill(0, 0); CP_COMMIT();
    fill(1, 1); CP_COMMIT();

    for (int k = 0; k < NCH; k++) {
        int s = k % 3;
        if (k + 1 < NCH) { CP_WAIT1(); } else { CP_WAIT0(); }
        __syncthreads();
        if (k + 2 < NCH) { fill((k + 2) % 3, k + 2); CP_COMMIT(); }
        uint32_t Ab = sb + s * STAGE;
#pragma unroll
        for (int ks = 0; ks < 4; ks++) {
            uint32_t aq[4];
            {
                int r = (w >> 1) * 16 + (lsub & 1) * 8 + lrow;
                uint32_t gran = ks * 2 + (lsub >> 1);
                LDSM4(aq, Ab + r * 128 + ((gran * 16) ^ ((r & 7) << 4)));
            }
#pragma unroll
            for (int zz = 0; zz < 3; zz++) {
                uint32_t Bb = Ab + 16384 + zz * 8192;
#pragma unroll
                for (int p = 0; p < 2; p++) {
                    int nn = (w & 1) * 32 + p * 16 + (lsub >> 1) * 8 + lrow;
                    uint32_t gran = ks * 2 + (lsub & 1);
                    uint32_t bq[4];
                    LDSM4(bq, Bb + nn * 128 + ((gran * 16) ^ ((nn & 7) << 4)));
                    mma16816(acc[zz][2 * p],     aq, bq[0], bq[1]);
                    mma16816(acc[zz][2 * p + 1], aq, bq[2], bq[3]);
                }
            }
        }
    }

    uint32_t* q32 = (uint32_t*)g_q;
#pragma unroll
    for (int half = 0; half < 2; half++) {
        int m = tile * 128 + (w >> 1) * 16 + (lane >> 2) + half * 8;
        {
            size_t rb = ((size_t)hd * HW + m) * 32;
#pragma unroll
            for (int nt = 0; nt < 4; nt++) {
                int ocp = (w & 1) * 16 + nt * 4 + (lane & 3);
                q32[rb + ocp] = packh(acc[0][nt][half * 2], acc[0][nt][half * 2 + 1]);
            }
        }
        int oy = m / 48, ox = m - oy * 48;
        if (oy >= 1 && oy <= 46 && ox >= 1 && ox <= 46) {
            int d = (oy - 1) * 46 + (ox - 1);
            size_t rb = ((size_t)hd * DPAD + d) * 32;
#pragma unroll
            for (int zz = 1; zz < 3; zz++) {
                uint32_t* dst = (uint32_t*)((zz == 1) ? g_k : g_v);
#pragma unroll
                for (int nt = 0; nt < 4; nt++) {
                    int ocp = (w & 1) * 16 + nt * 4 + (lane & 3);
                    dst[rb + ocp] = packh(acc[zz][nt][half * 2],
                                          acc[zz][nt][half * 2 + 1]);
                }
            }
        }
    }
}

// ------------------------------------------------------------------
// gate_kernel: 512 threads, 3-stage (48K/stage: A 16K + 4x8K B).
// warp = (px16 = w>>1, 2 gates = w&1).  LSTM fused via smem exchange.
// ------------------------------------------------------------------
__global__ __launch_bounds__(512, 1) void gate_kernel(
    const float* __restrict__ bbi, const float* __restrict__ bbf,
    const float* __restrict__ bbg, const float* __restrict__ bbo,
    const float* __restrict__ cold, float* __restrict__ out)
{
    extern __shared__ char smem[];
    const int STAGE = 49152;
    uint32_t sb = s2u(smem);
    const int tid = threadIdx.x, w = tid >> 5, lane = tid & 31;
    const int hd = blockIdx.y, g = hd & 7;
    const int tile = blockIdx.x;
    const int NCH = 19;
    const int lsub = lane >> 3, lrow = lane & 7;

    auto fill = [&](int s, int k) {
        uint32_t base = sb + s * STAGE;
        {
            int r = tid >> 2, q = tid & 3;
            int px_ = tile * 128 + r;
            const char* sh; bool in;
            if (k < 18) {
                int py_ = px_ / 48, pxx_ = px_ - py_ * 48;
                int t9 = k >> 1, cb = k & 1, ky = t9 / 3, kx = t9 - ky * 3;
                int iy = py_ + ky - 1, ix = pxx_ + kx - 1;
                in = ((unsigned)iy < 48u) && ((unsigned)ix < 48u);
                const __half* rp =
                    g_xhp + (((size_t)hd * HW + iy * 48 + ix) * 128 + cb * 64);
                if (!in) rp = g_xhp;
                sh = (const char*)rp;
            } else {
                in = true;
                sh = (const char*)(g_a + ((size_t)hd * HW + px_) * 64);
            }
            uint32_t sw = (r & 7) << 4;
#pragma unroll
            for (int j = 0; j < 2; j++) {
                int gc = q * 2 + j;
                cpa16(base + r * 128 + ((gc * 16) ^ sw), sh + gc * 16, in);
            }
        }
#pragma unroll
        for (int i = 0; i < 4; i++) {
            int p = tid + i * 512;
            int zz = p >> 9, pg = p & 511;
            int oc = pg >> 3, gr = pg & 7;
            const uint32_t* wsrc =
                g_wb32 + ((size_t)((3 + zz) * 8 + g) * 19 + k) * 2048;
            cpa16(base + 16384 + zz * 8192 + oc * 128 + ((gr * 16) ^ ((oc & 7) << 4)),
                  wsrc + pg * 4, true);
        }
    };

    float acc[2][8][4];
#pragma unroll
    for (int j = 0; j < 2; j++)
#pragma unroll
        for (int nt = 0; nt < 8; nt++)
#pragma unroll
            for (int i = 0; i < 4; i++) acc[j][nt][i] = 0.f;

    fill(0, 0); CP_COMMIT();
    fill(1, 1); CP_COMMIT();

    for (int k = 0; k < NCH; k++) {
        int s = k % 3;
        if (k + 1 < NCH) { CP_WAIT1(); } else { CP_WAIT0(); }
        __syncthreads();
        if (k + 2 < NCH) { fill((k + 2) % 3, k + 2); CP_COMMIT(); }
        uint32_t Ab = sb + s * STAGE;
#pragma unroll
        for (int ks = 0; ks < 4; ks++) {
            uint32_t aq[4];
            {
                int r = (w >> 1) * 16 + (lsub & 1) * 8 + lrow;
                uint32_t gran = ks * 2 + (lsub >> 1);
                LDSM4(aq, Ab + r * 128 + ((gran * 16) ^ ((r & 7) << 4)));
            }
#pragma unroll
            for (int j = 0; j < 2; j++) {
                int zz = 2 * (w & 1) + j;
                uint32_t Bb = Ab + 16384 + zz * 8192;
#pragma unroll
                for (int p = 0; p < 4; p++) {
                    int nn = p * 16 + (lsub >> 1) * 8 + lrow;
                    uint32_t gran = ks * 2 + (lsub & 1);
                    uint32_t bq[4];
                    LDSM4(bq, Bb + nn * 128 + ((gran * 16) ^ ((nn & 7) << 4)));
                    mma16816(acc[j][2 * p],     aq, bq[0], bq[1]);
                    mma16816(acc[j][2 * p + 1], aq, bq[2], bq[3]);
                }
            }
        }
    }

    // ---- epilogue: exchange gate fragments via smem, LSTM, write ----
    float* smf = (float*)smem;      // [zz][px128][oc64] fp32 = 128 KB
    __syncthreads();
#pragma unroll
    for (int j = 0; j < 2; j++) {
        int zz = 2 * (w & 1) + j;
#pragma unroll
        for (int half = 0; half < 2; half++) {
            int pxl = (w >> 1) * 16 + (lane >> 2) + half * 8;
#pragma unroll
            for (int nt = 0; nt < 8; nt++) {
                int oc0 = nt * 8 + (lane & 3) * 2;
                float2 v = make_float2(acc[j][nt][half * 2], acc[j][nt][half * 2 + 1]);
                *(float2*)(smf + zz * 8192 + pxl * 64 + oc0) = v;
            }
        }
    }
    __syncthreads();

    int n = hd >> 3;
#pragma unroll
    for (int i = 0; i < 16; i++) {
        int elem = i * 512 + tid;
        int pxl = elem >> 6, oc = elem & 63;
        float pi = smf[0 * 8192 + pxl * 64 + oc] + bbi[g * 64 + oc];
        float pf = smf[1 * 8192 + pxl * 64 + oc] + bbf[g * 64 + oc];
        float pg = smf[2 * 8192 + pxl * 64 + oc] + bbg[g * 64 + oc];
        float po = smf[3 * 8192 + pxl * 64 + oc] + bbo[g * 64 + oc];
        float ig = 1.f / (1.f + __expf(-pi));
        float fg = 1.f / (1.f + __expf(-pf));
        float gg = tanhf(pg);
        float og = 1.f / (1.f + __expf(-po));
        size_t ci = ((size_t)n * 512 + g * 64 + oc) * HW + tile * 128 + pxl;
        float cn = fg * cold[ci] + ig * gg;
        out[ci] = og * tanhf(cn);
    }
}

// ------------------------------------------------------------------
// attn_kernel: 512 threads, 256 queries, 3-stage KV.
// SMEM: Q 32K | 3 x (K 8K | V 8K) = 80K.  grid (9, 16).
// ------------------------------------------------------------------
__global__ __launch_bounds__(512, 1) void attn_kernel(const float* __restrict__ tau)
{
    extern __shared__ char smem[];
    uint32_t sb = s2u(smem);
    const int tid = threadIdx.x, w = tid >> 5, lane = tid & 31;
    const int hd = blockIdx.y, g = hd & 7;
    const int qbase = blockIdx.x * 256;
    const int lsub = lane >> 3, lrow = lane & 7;
    const float ts2 = tau[g] * 1.44269504f;
    const int NCHK = (DS + 63) / 64;   // 34

    // Q fill (once): 256 rows x 128 bytes
    {
        int r = tid >> 1;
        int g0 = (tid & 1) * 4;
        const char* qs = (const char*)g_q + ((size_t)hd * HW + qbase + r) * 128;
        uint32_t sw = (r & 7) << 4;
#pragma unroll
        for (int gg = 0; gg < 4; gg++) {
            int gc = g0 + gg;
            cpa16(sb + r * 128 + ((gc * 16) ^ sw), qs + gc * 16, true);
        }
    }
    auto fillkv = [&](int s, int c) {
        uint32_t base = sb + 32768 + s * 16384;
        int r = tid >> 3;
        int gr = tid & 7;
        int d = c * 64 + r;
        bool ok = d < DS;
        size_t rb = ((size_t)hd * DPAD + (ok ? d : 0)) * 128;  // bytes
        uint32_t off = r * 128 + ((gr * 16) ^ ((r & 7) << 4));
        cpa16(base + off,        (const char*)g_k + rb + gr * 16, ok);
        cpa16(base + 8192 + off, (const char*)g_v + rb + gr * 16, ok);
    };

    fillkv(0, 0); CP_COMMIT();
    fillkv(1, 1); CP_COMMIT();

    float o[8][4];
#pragma unroll
    for (int nt = 0; nt < 8; nt++)
#pragma unroll
        for (int i = 0; i < 4; i++) o[nt][i] = 0.f;
    float mrow[2] = {-1e30f, -1e30f};
    float lsum[2] = {0.f, 0.f};

    for (int c = 0; c < NCHK; c++) {
        int s = c % 3;
        if (c + 1 < NCHK) { CP_WAIT1(); } else { CP_WAIT0(); }
        __syncthreads();
        if (c + 2 < NCHK) { fillkv((c + 2) % 3, c + 2); CP_COMMIT(); }
        uint32_t Kb = sb + 32768 + s * 16384;
        uint32_t Vb = Kb + 8192;

        float sf[8][4];
#pragma unroll
        for (int nt = 0; nt < 8; nt++)
#pragma unroll
            for (int i = 0; i < 4; i++) sf[nt][i] = 0.f;
#pragma unroll
        for (int ks = 0; ks < 4; ks++) {
            uint32_t aq[4];
            {
                int r = w * 16 + (lsub & 1) * 8 + lrow;
                uint32_t gran = ks * 2 + (lsub >> 1);
                LDSM4(aq, sb + r * 128 + ((gran * 16) ^ ((r & 7) << 4)));
            }
#pragma unroll
            for (int p = 0; p < 4; p++) {
                int nn = p * 16 + (lsub >> 1) * 8 + lrow;
                uint32_t gran = ks * 2 + (lsub & 1);
                uint32_t bq[4];
                LDSM4(bq, Kb + nn * 128 + ((gran * 16) ^ ((nn & 7) << 4)));
                mma16816(sf[2 * p],     aq, bq[0], bq[1]);
                mma16816(sf[2 * p + 1], aq, bq[2], bq[3]);
            }
        }

        // mask tail keys (only last chunk)
        if (c == NCHK - 1) {
            int dbase = c * 64 + (lane & 3) * 2;
#pragma unroll
            for (int nt = 0; nt < 8; nt++)
#pragma unroll
                for (int i = 0; i < 4; i++) {
                    int d = dbase + nt * 8 + (i & 1);
                    if (d >= DS) sf[nt][i] = -1e30f;
                }
        }

        // online softmax (s-domain max, ex2)
        float alpha[2];
#pragma unroll
        for (int h = 0; h < 2; h++) {
            float mx = mrow[h];
#pragma unroll
            for (int nt = 0; nt < 8; nt++) {
                mx = fmaxf(mx, sf[nt][h * 2]);
                mx = fmaxf(mx, sf[nt][h * 2 + 1]);
            }
            mx = fmaxf(mx, __shfl_xor_sync(0xffffffffu, mx, 1));
            mx = fmaxf(mx, __shfl_xor_sync(0xffffffffu, mx, 2));
            float nm = mx * ts2;
            float al_ = ex2(fmaf(mrow[h], ts2, -nm));
            mrow[h] = mx;
            alpha[h] = al_;
            float ls = lsum[h] * al_;
#pragma unroll
            for (int nt = 0; nt < 8; nt++) {
#pragma unroll
                for (int e = 0; e < 2; e++) {
                    float p = ex2(fmaf(sf[nt][h * 2 + e], ts2, -nm));
                    sf[nt][h * 2 + e] = p;
                    ls += p;
                }
            }
            lsum[h] = ls;
        }
#pragma unroll
        for (int nt = 0; nt < 8; nt++) {
            o[nt][0] *= alpha[0];
            o[nt][1] *= alpha[0];
            o[nt][2] *= alpha[1];
            o[nt][3] *= alpha[1];
        }

        // O += P V (single fp16 P and V)
#pragma unroll
        for (int kt = 0; kt < 4; kt++) {
            uint32_t pa[4];
#pragma unroll
            for (int i = 0; i < 4; i++) {
                int nt = 2 * kt + (i >> 1);
                pa[i] = packh(sf[nt][(i & 1) * 2], sf[nt][(i & 1) * 2 + 1]);
            }
#pragma unroll
            for (int np = 0; np < 4; np++) {
                int rr = kt * 16 + (lane & 15);
                uint32_t gran = np * 2 + (lane >> 4);
                uint32_t vq[4];
                LDSM4T(vq, Vb + rr * 128 + ((gran * 16) ^ ((rr & 7) << 4)));
                mma16816(o[2 * np],     pa, vq[0], vq[1]);
                mma16816(o[2 * np + 1], pa, vq[2], vq[3]);
            }
        }
    }

    uint32_t* a32 = (uint32_t*)g_a;
#pragma unroll
    for (int h = 0; h < 2; h++) {
        float l = lsum[h];
        l += __shfl_xor_sync(0xffffffffu, l, 1);
        l += __shfl_xor_sync(0xffffffffu, l, 2);
        float inv = 1.f / l;
        int m = qbase + w * 16 + (lane >> 2) + h * 8;
        size_t rb = ((size_t)hd * HW + m) * 32;
#pragma unroll
        for (int nt = 0; nt < 8; nt++) {
            int ocp = nt * 4 + (lane & 3);
            a32[rb + ocp] = packh(o[nt][h * 2] * inv, o[nt][h * 2 + 1] * inv);
        }
    }
}

// ------------------------------------------------------------------
extern "C" void kernel_launch(void* const* d_in, const int* in_sizes, int n_in,
                              void* d_out, int out_size)
{
    const float* x_in = (const float*)d_in[0];
    const float* h    = (const float*)d_in[1];
    const float* c    = (const float*)d_in[2];
    const float* tau  = (const float*)d_in[3];
    const float* Wx   = (const float*)d_in[4];
    const float* Wig  = (const float*)d_in[5];
    const float* Wq   = (const float*)d_in[6];
    const float* Wk   = (const float*)d_in[7];
    const float* Wv   = (const float*)d_in[8];
    const float* Wia  = (const float*)d_in[9];
    const float* Wix  = (const float*)d_in[10];
    const float* bi   = (const float*)d_in[11];
    const float* Wfa  = (const float*)d_in[12];
    const float* Wfx  = (const float*)d_in[13];
    const float* bf   = (const float*)d_in[14];
    const float* Wga  = (const float*)d_in[15];
    const float* Wgx  = (const float*)d_in[16];
    const float* bg   = (const float*)d_in[17];
    const float* Woa  = (const float*)d_in[18];
    const float* Wox  = (const float*)d_in[19];
    const float* bo   = (const float*)d_in[20];
    float* out = (float*)d_out;

    const int PSMEM = 3 * 32768;            //  96 KB proj
    const int QSMEM = 3 * 40960;            // 120 KB qkv
    const int GSMEM = 3 * 49152;            // 144 KB gates
    const int ASMEM = 32768 + 3 * 16384;    //  80 KB attn
    cudaFuncSetAttribute(proj_mma,
                         cudaFuncAttributeMaxDynamicSharedMemorySize, PSMEM);
    cudaFuncSetAttribute(qkv_kernel,
                         cudaFuncAttributeMaxDynamicSharedMemorySize, QSMEM);
    cudaFuncSetAttribute(gate_kernel,
                         cudaFuncAttributeMaxDynamicSharedMemorySize, GSMEM);
    cudaFuncSetAttribute(attn_kernel,
                         cudaFuncAttributeMaxDynamicSharedMemorySize, ASMEM);

    prep_w<<<8512, 256>>>(Wq, Wk, Wv, Wix, Wfx, Wgx, Wox, Wia, Wfa, Wga, Woa);
    prep_pw<<<768, 256>>>(Wx, Wig);
    prep_x<<<dim3(18, 12, 2), 256>>>(x_in, h);
    proj_mma<<<dim3(18, 4, 2), 512, PSMEM>>>();
    qkv_kernel<<<dim3(18, 16), 512, QSMEM>>>();
    attn_kernel<<<dim3(9, 16), 512, ASMEM>>>(tau);
    gate_kernel<<<dim3(18, 16), 512, GSMEM>>>(bi, bf, bg, bo, c, out);
}

// round 13
// speedup vs baseline: 9.2580x; 1.0402x over previous
#include <cuda_runtime.h>
#include <cuda_fp16.h>
#include <math.h>
#include <stdint.h>

#define NB   2
#define CINC 256
#define CT   512
#define HH   48
#define HW   2304
#define DS   2116
#define DPAD 2176
#define TOT  (NB*CT*HW)

__device__ __forceinline__ uint32_t packh(float lo, float hi) {
    uint32_t r;
    asm("cvt.rn.f16x2.f32 %0, %1, %2;" : "=r"(r) : "f"(hi), "f"(lo));
    return r;
}
__device__ __forceinline__ float ex2(float x) {
    float y; asm("ex2.approx.f32 %0, %1;" : "=f"(y) : "f"(x)); return y;
}

// ---------------- scratch (all single fp16) ----------------
#define XHPS (16 * HW * 128)
__device__ __align__(256) __half g_xhp[XHPS];                  // [hd][px][128]
__device__ __align__(256) uint32_t g_wb32[7 * 8 * 19 * 2048];  // conv W imgs
__device__ __align__(256) uint32_t g_wpb32[8 * 12 * 2048];     // proj W imgs
__device__ __align__(256) uint32_t g_apm[NB * HW * 384];       // proj A [n][px][768]
__device__ __align__(256) __half g_q[16 * HW * 64];
__device__ __align__(256) __half g_k[16 * DPAD * 64];
__device__ __align__(256) __half g_v[16 * DPAD * 64];
__device__ __align__(256) __half g_a[16 * HW * 64];

// ---------------- cp.async ----------------
__device__ __forceinline__ uint32_t s2u(const void* p) {
    return (uint32_t)__cvta_generic_to_shared(p);
}
__device__ __forceinline__ void cpa16(uint32_t dst, const void* src, bool pred) {
    int sz = pred ? 16 : 0;
    asm volatile("cp.async.cg.shared.global [%0], [%1], 16, %2;\n"
                 :: "r"(dst), "l"(src), "r"(sz) : "memory");
}
#define CP_COMMIT() asm volatile("cp.async.commit_group;\n" ::: "memory")
#define CP_WAIT0()  asm volatile("cp.async.wait_group 0;\n" ::: "memory")
#define CP_WAIT1()  asm volatile("cp.async.wait_group 1;\n" ::: "memory")

// ---------------- mma.sync helpers (fp16 in, fp32 accum) ----------------
#define LDSM4(r, a) \
    asm volatile("ldmatrix.sync.aligned.m8n8.x4.shared.b16 {%0,%1,%2,%3}, [%4];" \
                 : "=r"((r)[0]), "=r"((r)[1]), "=r"((r)[2]), "=r"((r)[3]) : "r"(a))
#define LDSM4T(r, a) \
    asm volatile("ldmatrix.sync.aligned.m8n8.x4.trans.shared.b16 {%0,%1,%2,%3}, [%4];" \
                 : "=r"((r)[0]), "=r"((r)[1]), "=r"((r)[2]), "=r"((r)[3]) : "r"(a))

__device__ __forceinline__ void mma16816(float* d, const uint32_t* a,
                                         uint32_t b0, uint32_t b1) {
    asm volatile(
        "mma.sync.aligned.m16n8k16.row.col.f32.f16.f16.f32 "
        "{%0,%1,%2,%3}, {%4,%5,%6,%7}, {%8,%9}, {%0,%1,%2,%3};"
        : "+f"(d[0]), "+f"(d[1]), "+f"(d[2]), "+f"(d[3])
        : "r"(a[0]), "r"(a[1]), "r"(a[2]), "r"(a[3]), "r"(b0), "r"(b1));
}

// ------------------------------------------------------------------
// prep_w: conv weights -> fp16 images (64oc x 64ch)
// ------------------------------------------------------------------
__global__ void prep_w(const float* __restrict__ Wq, const float* __restrict__ Wk,
                       const float* __restrict__ Wv,
                       const float* __restrict__ Wix, const float* __restrict__ Wfx,
                       const float* __restrict__ Wgx, const float* __restrict__ Wox,
                       const float* __restrict__ Wia, const float* __restrict__ Wfa,
                       const float* __restrict__ Wga, const float* __restrict__ Woa)
{
    int idx = blockIdx.x * 256 + threadIdx.x;
    if (idx >= 7 * 8 * 19 * 64 * 32) return;
    int c2    = idx & 31;
    int oc    = (idx >> 5) & 63;
    int rem   = idx >> 11;
    int chunk = rem % 19;
    int g     = (rem / 19) & 7;
    int type  = rem / 152;
    if (type < 3 && chunk == 18) return;

    float w0, w1;
    if (chunk < 18) {
        const float* W3 = (type == 0) ? Wq : (type == 1) ? Wk : (type == 2) ? Wv :
                          (type == 3) ? Wix : (type == 4) ? Wfx : (type == 5) ? Wgx : Wox;
        int t9 = chunk >> 1, cb = chunk & 1;
        size_t b = ((size_t)(g * 64 + oc) * 128 + cb * 64 + c2 * 2) * 9 + t9;
        w0 = W3[b]; w1 = W3[b + 9];
    } else {
        const float* Wa = (type == 3) ? Wia : (type == 4) ? Wfa : (type == 5) ? Wga : Woa;
        size_t b = (size_t)(g * 64 + oc) * 64 + c2 * 2;
        w0 = Wa[b]; w1 = Wa[b + 1];
    }
    g_wb32[(size_t)rem * 2048 + oc * 32 + c2] = packh(w0, w1);
}

// ------------------------------------------------------------------
// prep_pw: proj weights -> fp16 images
// ------------------------------------------------------------------
__global__ void prep_pw(const float* __restrict__ Wx, const float* __restrict__ Wig)
{
    int idx = blockIdx.x * 256 + threadIdx.x;
    if (idx >= 8 * 12 * 64 * 32) return;
    int c2    = idx & 31;
    int oc    = (idx >> 5) & 63;
    int rem   = idx >> 11;
    int chunk = rem % 12;
    int g     = rem / 12;

    float w0, w1;
    if (chunk < 4) {
        size_t b = (size_t)(g * 64 + oc) * 256 + chunk * 64 + c2 * 2;
        w0 = Wx[b]; w1 = Wx[b + 1];
    } else {
        size_t b = (size_t)(g * 64 + oc) * 512 + (chunk - 4) * 64 + c2 * 2;
        w0 = Wig[b]; w1 = Wig[b + 1];
    }
    g_wpb32[(size_t)rem * 2048 + oc * 32 + c2] = packh(w0, w1);
}

// ------------------------------------------------------------------
// prep_x: transpose x_in+h -> pixel-major fp16 + xh h-half
// ------------------------------------------------------------------
__global__ __launch_bounds__(256) void prep_x(
    const float* __restrict__ x_in, const float* __restrict__ h)
{
    __shared__ float t[64][129];
    int px0 = blockIdx.x * 128;
    int chb = blockIdx.y;
    int n   = blockIdx.z;
    int tid = threadIdx.x;

    for (int i = tid; i < 64 * 128; i += 256) {
        int cl = i >> 7, p = i & 127;
        int ch = chb * 64 + cl;
        float v = (ch < 256)
            ? x_in[((size_t)n * 256 + ch) * HW + px0 + p]
            : h[((size_t)n * 512 + (ch - 256)) * HW + px0 + p];
        t[cl][p] = v;
    }
    __syncthreads();

    for (int i = tid; i < 128 * 32; i += 256) {
        int p = i >> 5, c2 = i & 31;
        uint32_t hv = packh(t[c2 * 2][p], t[c2 * 2 + 1][p]);
        g_apm[((size_t)n * HW + px0 + p) * 384 + chb * 32 + c2] = hv;
        if (chb >= 4) {
            int g = chb - 4;
            ((uint32_t*)g_xhp)[((size_t)(n * 8 + g) * HW + px0 + p) * 64 + 32 + c2] = hv;
        }
    }
}

// ------------------------------------------------------------------
// proj_mma: dense GEMM, N=128, 512 threads, 3-stage (32K/stage).
// ------------------------------------------------------------------
__global__ __launch_bounds__(512, 1) void proj_mma()
{
    extern __shared__ char smem[];
    const int STAGE = 32768;
    uint32_t sb = s2u(smem);
    const int tid = threadIdx.x, w = tid >> 5, lane = tid & 31;
    const int nb = blockIdx.y, n = blockIdx.z;
    const int tile = blockIdx.x;
    const int NCH = 12;
    const int lsub = lane >> 3, lrow = lane & 7;

    auto fill = [&](int s, int k) {
        uint32_t base = sb + s * STAGE;
        {
            int r = tid >> 2, q = tid & 3;
            int px = tile * 128 + r;
            const uint32_t* src = g_apm + ((size_t)n * HW + px) * 384 + k * 32;
            uint32_t sw = (r & 7) << 4;
#pragma unroll
            for (int j = 0; j < 2; j++) {
                int gc = q * 2 + j;
                cpa16(base + r * 128 + ((gc * 16) ^ sw), src + gc * 4, true);
            }
        }
#pragma unroll
        for (int i = 0; i < 2; i++) {
            int p = tid + i * 512;
            int row = p >> 3, gr = p & 7;
            int srctile = (nb * 2 + (row >> 6)) * 12 + k;
            int srow = row & 63;
            const uint32_t* src = g_wpb32 + (size_t)srctile * 2048 + srow * 32 + gr * 4;
            cpa16(base + 16384 + row * 128 + ((gr * 16) ^ ((row & 7) << 4)), src, true);
        }
    };

    float acc[8][4];
#pragma unroll
    for (int nt = 0; nt < 8; nt++)
#pragma unroll
        for (int i = 0; i < 4; i++) acc[nt][i] = 0.f;

    fill(0, 0); CP_COMMIT();
    fill(1, 1); CP_COMMIT();

    for (int k = 0; k < NCH; k++) {
        int s = k % 3;
        if (k + 1 < NCH) { CP_WAIT1(); } else { CP_WAIT0(); }
        __syncthreads();
        if (k + 2 < NCH) { fill((k + 2) % 3, k + 2); CP_COMMIT(); }
        uint32_t Ab = sb + s * STAGE;
        uint32_t Bb = Ab + 16384;
#pragma unroll
        for (int ks = 0; ks < 4; ks++) {
            uint32_t aq[4];
            {
                int r = (w >> 1) * 16 + (lsub & 1) * 8 + lrow;
                uint32_t gran = ks * 2 + (lsub >> 1);
                LDSM4(aq, Ab + r * 128 + ((gran * 16) ^ ((r & 7) << 4)));
            }
#pragma unroll
            for (int p = 0; p < 4; p++) {
                int nn = (w & 1) * 64 + p * 16 + (lsub >> 1) * 8 + lrow;
                uint32_t gran = ks * 2 + (lsub & 1);
                uint32_t bq[4];
                LDSM4(bq, Bb + nn * 128 + ((gran * 16) ^ ((nn & 7) << 4)));
                mma16816(acc[2 * p],     aq, bq[0], bq[1]);
                mma16816(acc[2 * p + 1], aq, bq[2], bq[3]);
            }
        }
    }

    int hd = n * 8 + nb * 2 + (w & 1);
    uint32_t* xh32 = (uint32_t*)g_xhp;
#pragma unroll
    for (int half = 0; half < 2; half++) {
        int m = tile * 128 + (w >> 1) * 16 + (lane >> 2) + half * 8;
        size_t rb = ((size_t)hd * HW + m) * 64;
#pragma unroll
        for (int nt = 0; nt < 8; nt++) {
            int ocp = nt * 4 + (lane & 3);
            xh32[rb + ocp] = packh(acc[nt][half * 2], acc[nt][half * 2 + 1]);
        }
    }
}

// ------------------------------------------------------------------
// qkv_kernel: 512 threads, 3-stage (40K/stage: A 16K + 3x8K B).
// warp = (px16 = w>>1, 32-oc half = w&1) of each of q/k/v.
// ------------------------------------------------------------------
__global__ __launch_bounds__(512, 1) void qkv_kernel()
{
    extern __shared__ char smem[];
    const int STAGE = 40960;
    uint32_t sb = s2u(smem);
    const int tid = threadIdx.x, w = tid >> 5, lane = tid & 31;
    const int hd = blockIdx.y, g = hd & 7;
    const int tile = blockIdx.x;
    const int NCH = 18;
    const int lsub = lane >> 3, lrow = lane & 7;

    auto fill = [&](int s, int k) {
        uint32_t base = sb + s * STAGE;
        {
            int r = tid >> 2, q = tid & 3;
            int px_ = tile * 128 + r;
            int py_ = px_ / 48, pxx_ = px_ - py_ * 48;
            int t9 = k >> 1, cb = k & 1, ky = t9 / 3, kx = t9 - ky * 3;
            int iy = py_ + ky - 1, ix = pxx_ + kx - 1;
            bool in = ((unsigned)iy < 48u) && ((unsigned)ix < 48u);
            const __half* rp =
                g_xhp + (((size_t)hd * HW + iy * 48 + ix) * 128 + cb * 64);
            if (!in) rp = g_xhp;
            uint32_t sw = (r & 7) << 4;
#pragma unroll
            for (int j = 0; j < 2; j++) {
                int gc = q * 2 + j;
                cpa16(base + r * 128 + ((gc * 16) ^ sw),
                      (const char*)rp + gc * 16, in);
            }
        }
#pragma unroll
        for (int i = 0; i < 3; i++) {
            int p = tid + i * 512;
            int zz = p >> 9, pg = p & 511;
            int oc = pg >> 3, gr = pg & 7;
            const uint32_t* wsrc = g_wb32 + ((size_t)(zz * 8 + g) * 19 + k) * 2048;
            cpa16(base + 16384 + zz * 8192 + oc * 128 + ((gr * 16) ^ ((oc & 7) << 4)),
                  wsrc + pg * 4, true);
        }
    };

    float acc[3][4][4];
#pragma unroll
    for (int zz = 0; zz < 3; zz++)
#pragma unroll
        for (int nt = 0; nt < 4; nt++)
#pragma unroll
            for (int i = 0; i < 4; i++) acc[zz][nt][i] = 0.f;

    fill(0, 0); CP_COMMIT();
    fill(1, 1); CP_COMMIT();

    for (int k = 0; k < NCH; k++) {
        int s = k % 3;
        if (k + 1 < NCH) { CP_WAIT1(); } else { CP_WAIT0(); }
        __syncthreads();
        if (k + 2 < NCH) { fill((k + 2) % 3, k + 2); CP_COMMIT(); }
        uint32_t Ab = sb + s * STAGE;
#pragma unroll
        for (int ks = 0; ks < 4; ks++) {
            uint32_t aq[4];
            {
                int r = (w >> 1) * 16 + (lsub & 1) * 8 + lrow;
                uint32_t gran = ks * 2 + (lsub >> 1);
                LDSM4(aq, Ab + r * 128 + ((gran * 16) ^ ((r & 7) << 4)));
            }
#pragma unroll
            for (int zz = 0; zz < 3; zz++) {
                uint32_t Bb = Ab + 16384 + zz * 8192;
#pragma unroll
                for (int p = 0; p < 2; p++) {
                    int nn = (w & 1) * 32 + p * 16 + (lsub >> 1) * 8 + lrow;
                    uint32_t gran = ks * 2 + (lsub & 1);
                    uint32_t bq[4];
                    LDSM4(bq, Bb + nn * 128 + ((gran * 16) ^ ((nn & 7) << 4)));
                    mma16816(acc[zz][2 * p],     aq, bq[0], bq[1]);
                    mma16816(acc[zz][2 * p + 1], aq, bq[2], bq[3]);
                }
            }
        }
    }

    uint32_t* q32 = (uint32_t*)g_q;
#pragma unroll
    for (int half = 0; half < 2; half++) {
        int m = tile * 128 + (w >> 1) * 16 + (lane >> 2) + half * 8;
        {
            size_t rb = ((size_t)hd * HW + m) * 32;
#pragma unroll
            for (int nt = 0; nt < 4; nt++) {
                int ocp = (w & 1) * 16 + nt * 4 + (lane & 3);
                q32[rb + ocp] = packh(acc[0][nt][half * 2], acc[0][nt][half * 2 + 1]);
            }
        }
        int oy = m / 48, ox = m - oy * 48;
        if (oy >= 1 && oy <= 46 && ox >= 1 && ox <= 46) {
            int d = (oy - 1) * 46 + (ox - 1);
            size_t rb = ((size_t)hd * DPAD + d) * 32;
#pragma unroll
            for (int zz = 1; zz < 3; zz++) {
                uint32_t* dst = (uint32_t*)((zz == 1) ? g_k : g_v);
#pragma unroll
                for (int nt = 0; nt < 4; nt++) {
                    int ocp = (w & 1) * 16 + nt * 4 + (lane & 3);
                    dst[rb + ocp] = packh(acc[zz][nt][half * 2],
                                          acc[zz][nt][half * 2 + 1]);
                }
            }
        }
    }
}

// ------------------------------------------------------------------
// gate_kernel: 512 threads, 3-stage.  warp = (32px = w&3, 1 gate = w>>2).
// Per ks: 2 LDSM_A + 4 LDSM_B + 16 mma (B reused across 2 M-tiles).
// LSTM fused via smem exchange.
// ------------------------------------------------------------------
__global__ __launch_bounds__(512, 1) void gate_kernel(
    const float* __restrict__ bbi, const float* __restrict__ bbf,
    const float* __restrict__ bbg, const float* __restrict__ bbo,
    const float* __restrict__ cold, float* __restrict__ out)
{
    extern __shared__ char smem[];
    const int STAGE = 49152;
    uint32_t sb = s2u(smem);
    const int tid = threadIdx.x, w = tid >> 5, lane = tid & 31;
    const int hd = blockIdx.y, g = hd & 7;
    const int tile = blockIdx.x;
    const int NCH = 19;
    const int lsub = lane >> 3, lrow = lane & 7;
    const int pxg = w & 3, z = w >> 2;

    auto fill = [&](int s, int k) {
        uint32_t base = sb + s * STAGE;
        {
            int r = tid >> 2, q = tid & 3;
            int px_ = tile * 128 + r;
            const char* sh; bool in;
            if (k < 18) {
                int py_ = px_ / 48, pxx_ = px_ - py_ * 48;
                int t9 = k >> 1, cb = k & 1, ky = t9 / 3, kx = t9 - ky * 3;
                int iy = py_ + ky - 1, ix = pxx_ + kx - 1;
                in = ((unsigned)iy < 48u) && ((unsigned)ix < 48u);
                const __half* rp =
                    g_xhp + (((size_t)hd * HW + iy * 48 + ix) * 128 + cb * 64);
                if (!in) rp = g_xhp;
                sh = (const char*)rp;
            } else {
                in = true;
                sh = (const char*)(g_a + ((size_t)hd * HW + px_) * 64);
            }
            uint32_t sw = (r & 7) << 4;
#pragma unroll
            for (int j = 0; j < 2; j++) {
                int gc = q * 2 + j;
                cpa16(base + r * 128 + ((gc * 16) ^ sw), sh + gc * 16, in);
            }
        }
#pragma unroll
        for (int i = 0; i < 4; i++) {
            int p = tid + i * 512;
            int zz = p >> 9, pg = p & 511;
            int oc = pg >> 3, gr = pg & 7;
            const uint32_t* wsrc =
                g_wb32 + ((size_t)((3 + zz) * 8 + g) * 19 + k) * 2048;
            cpa16(base + 16384 + zz * 8192 + oc * 128 + ((gr * 16) ^ ((oc & 7) << 4)),
                  wsrc + pg * 4, true);
        }
    };

    float acc[2][8][4];
#pragma unroll
    for (int mt = 0; mt < 2; mt++)
#pragma unroll
        for (int nt = 0; nt < 8; nt++)
#pragma unroll
            for (int i = 0; i < 4; i++) acc[mt][nt][i] = 0.f;

    fill(0, 0); CP_COMMIT();
    fill(1, 1); CP_COMMIT();

    for (int k = 0; k < NCH; k++) {
        int s = k % 3;
        if (k + 1 < NCH) { CP_WAIT1(); } else { CP_WAIT0(); }
        __syncthreads();
        if (k + 2 < NCH) { fill((k + 2) % 3, k + 2); CP_COMMIT(); }
        uint32_t Ab = sb + s * STAGE;
        uint32_t Bb = Ab + 16384 + z * 8192;
#pragma unroll
        for (int ks = 0; ks < 4; ks++) {
            uint32_t aq[2][4];
#pragma unroll
            for (int mt = 0; mt < 2; mt++) {
                int r = pxg * 32 + mt * 16 + (lsub & 1) * 8 + lrow;
                uint32_t gran = ks * 2 + (lsub >> 1);
                LDSM4(aq[mt], Ab + r * 128 + ((gran * 16) ^ ((r & 7) << 4)));
            }
#pragma unroll
            for (int p = 0; p < 4; p++) {
                int nn = p * 16 + (lsub >> 1) * 8 + lrow;
                uint32_t gran = ks * 2 + (lsub & 1);
                uint32_t bq[4];
                LDSM4(bq, Bb + nn * 128 + ((gran * 16) ^ ((nn & 7) << 4)));
#pragma unroll
                for (int mt = 0; mt < 2; mt++) {
                    mma16816(acc[mt][2 * p],     aq[mt], bq[0], bq[1]);
                    mma16816(acc[mt][2 * p + 1], aq[mt], bq[2], bq[3]);
                }
            }
        }
    }

    // ---- epilogue: exchange gate fragments via smem, LSTM, write ----
    float* smf = (float*)smem;      // [z][px128][oc64] fp32 = 128 KB
    __syncthreads();
#pragma unroll
    for (int mt = 0; mt < 2; mt++) {
#pragma unroll
        for (int half = 0; half < 2; half++) {
            int pxl = pxg * 32 + mt * 16 + (lane >> 2) + half * 8;
#pragma unroll
            for (int nt = 0; nt < 8; nt++) {
                int oc0 = nt * 8 + (lane & 3) * 2;
                float2 v = make_float2(acc[mt][nt][half * 2],
                                       acc[mt][nt][half * 2 + 1]);
                *(float2*)(smf + z * 8192 + pxl * 64 + oc0) = v;
            }
        }
    }
    __syncthreads();

    int n = hd >> 3;
#pragma unroll
    for (int i = 0; i < 16; i++) {
        int elem = i * 512 + tid;
        int pxl = elem >> 6, oc = elem & 63;
        float pi = smf[0 * 8192 + pxl * 64 + oc] + bbi[g * 64 + oc];
        float pf = smf[1 * 8192 + pxl * 64 + oc] + bbf[g * 64 + oc];
        float pg = smf[2 * 8192 + pxl * 64 + oc] + bbg[g * 64 + oc];
        float po = smf[3 * 8192 + pxl * 64 + oc] + bbo[g * 64 + oc];
        float ig = 1.f / (1.f + __expf(-pi));
        float fg = 1.f / (1.f + __expf(-pf));
        float gg = tanhf(pg);
        float og = 1.f / (1.f + __expf(-po));
        size_t ci = ((size_t)n * 512 + g * 64 + oc) * HW + tile * 128 + pxl;
        float cn = fg * cold[ci] + ig * gg;
        out[ci] = og * tanhf(cn);
    }
}

// ------------------------------------------------------------------
// attn_kernel: 256 threads, 8 warps, warp = 32 queries x 64 keys.
// CTA = 256 queries, 3-stage KV.  SMEM: Q 32K | 3 x 16K = 80K.
// ------------------------------------------------------------------
__global__ __launch_bounds__(256, 1) void attn_kernel(const float* __restrict__ tau)
{
    extern __shared__ char smem[];
    uint32_t sb = s2u(smem);
    const int tid = threadIdx.x, w = tid >> 5, lane = tid & 31;
    const int hd = blockIdx.y, g = hd & 7;
    const int qbase = blockIdx.x * 256;
    const int lsub = lane >> 3, lrow = lane & 7;
    const float ts2 = tau[g] * 1.44269504f;
    const int NCHK = (DS + 63) / 64;   // 34

    // Q fill (once): 256 rows x 128 bytes, 1 thread per row
    {
        int r = tid;
        const char* qs = (const char*)g_q + ((size_t)hd * HW + qbase + r) * 128;
        uint32_t sw = (r & 7) << 4;
#pragma unroll
        for (int gc = 0; gc < 8; gc++)
            cpa16(sb + r * 128 + ((gc * 16) ^ sw), qs + gc * 16, true);
    }
    auto fillkv = [&](int s, int c) {
        uint32_t base = sb + 32768 + s * 16384;
        int r = tid >> 2;
        int q4 = tid & 3;
        int d = c * 64 + r;
        bool ok = d < DS;
        size_t rb = ((size_t)hd * DPAD + (ok ? d : 0)) * 128;  // bytes
        uint32_t sw = (r & 7) << 4;
#pragma unroll
        for (int gg = 0; gg < 2; gg++) {
            int gran = q4 * 2 + gg;
            uint32_t off = r * 128 + ((gran * 16) ^ sw);
            cpa16(base + off,        (const char*)g_k + rb + gran * 16, ok);
            cpa16(base + 8192 + off, (const char*)g_v + rb + gran * 16, ok);
        }
    };

    fillkv(0, 0); CP_COMMIT();
    fillkv(1, 1); CP_COMMIT();

    float o[2][8][4];
#pragma unroll
    for (int mt = 0; mt < 2; mt++)
#pragma unroll
        for (int nt = 0; nt < 8; nt++)
#pragma unroll
            for (int i = 0; i < 4; i++) o[mt][nt][i] = 0.f;
    float mrow[2][2] = {{-1e30f, -1e30f}, {-1e30f, -1e30f}};
    float lsum[2][2] = {{0.f, 0.f}, {0.f, 0.f}};

    for (int c = 0; c < NCHK; c++) {
        int s = c % 3;
        if (c + 1 < NCHK) { CP_WAIT1(); } else { CP_WAIT0(); }
        __syncthreads();
        if (c + 2 < NCHK) { fillkv((c + 2) % 3, c + 2); CP_COMMIT(); }
        uint32_t Kb = sb + 32768 + s * 16384;
        uint32_t Vb = Kb + 8192;

        float sf[2][8][4];
#pragma unroll
        for (int mt = 0; mt < 2; mt++)
#pragma unroll
            for (int nt = 0; nt < 8; nt++)
#pragma unroll
                for (int i = 0; i < 4; i++) sf[mt][nt][i] = 0.f;
#pragma unroll
        for (int ks = 0; ks < 4; ks++) {
            uint32_t aq[2][4];
#pragma unroll
            for (int mt = 0; mt < 2; mt++) {
                int r = w * 32 + mt * 16 + (lsub & 1) * 8 + lrow;
                uint32_t gran = ks * 2 + (lsub >> 1);
                LDSM4(aq[mt], sb + r * 128 + ((gran * 16) ^ ((r & 7) << 4)));
            }
#pragma unroll
            for (int p = 0; p < 4; p++) {
                int nn = p * 16 + (lsub >> 1) * 8 + lrow;
                uint32_t gran = ks * 2 + (lsub & 1);
                uint32_t bq[4];
                LDSM4(bq, Kb + nn * 128 + ((gran * 16) ^ ((nn & 7) << 4)));
#pragma unroll
                for (int mt = 0; mt < 2; mt++) {
                    mma16816(sf[mt][2 * p],     aq[mt], bq[0], bq[1]);
                    mma16816(sf[mt][2 * p + 1], aq[mt], bq[2], bq[3]);
                }
            }
        }

        // mask tail keys (only last chunk)
        if (c == NCHK - 1) {
            int dbase = c * 64 + (lane & 3) * 2;
#pragma unroll
            for (int mt = 0; mt < 2; mt++)
#pragma unroll
                for (int nt = 0; nt < 8; nt++)
#pragma unroll
                    for (int i = 0; i < 4; i++) {
                        int d = dbase + nt * 8 + (i & 1);
                        if (d >= DS) sf[mt][nt][i] = -1e30f;
                    }
        }

        // online softmax (s-domain max, ex2)
        float alpha[2][2];
#pragma unroll
        for (int mt = 0; mt < 2; mt++) {
#pragma unroll
            for (int h = 0; h < 2; h++) {
                float mx = mrow[mt][h];
#pragma unroll
                for (int nt = 0; nt < 8; nt++) {
                    mx = fmaxf(mx, sf[mt][nt][h * 2]);
                    mx = fmaxf(mx, sf[mt][nt][h * 2 + 1]);
                }
                mx = fmaxf(mx, __shfl_xor_sync(0xffffffffu, mx, 1));
                mx = fmaxf(mx, __shfl_xor_sync(0xffffffffu, mx, 2));
                float nm = mx * ts2;
                float al_ = ex2(fmaf(mrow[mt][h], ts2, -nm));
                mrow[mt][h] = mx;
                alpha[mt][h] = al_;
                float ls = lsum[mt][h] * al_;
#pragma unroll
                for (int nt = 0; nt < 8; nt++) {
#pragma unroll
                    for (int e = 0; e < 2; e++) {
                        float p = ex2(fmaf(sf[mt][nt][h * 2 + e], ts2, -nm));
                        sf[mt][nt][h * 2 + e] = p;
                        ls += p;
                    }
                }
                lsum[mt][h] = ls;
            }
        }
#pragma unroll
        for (int mt = 0; mt < 2; mt++)
#pragma unroll
            for (int nt = 0; nt < 8; nt++) {
                o[mt][nt][0] *= alpha[mt][0];
                o[mt][nt][1] *= alpha[mt][0];
                o[mt][nt][2] *= alpha[mt][1];
                o[mt][nt][3] *= alpha[mt][1];
            }

        // O += P V
#pragma unroll
        for (int kt = 0; kt < 4; kt++) {
            uint32_t pa[2][4];
#pragma unroll
            for (int mt = 0; mt < 2; mt++)
#pragma unroll
                for (int i = 0; i < 4; i++) {
                    int nt = 2 * kt + (i >> 1);
                    pa[mt][i] = packh(sf[mt][nt][(i & 1) * 2],
                                      sf[mt][nt][(i & 1) * 2 + 1]);
                }
#pragma unroll
            for (int np = 0; np < 4; np++) {
                int rr = kt * 16 + (lane & 15);
                uint32_t gran = np * 2 + (lane >> 4);
                uint32_t vq[4];
                LDSM4T(vq, Vb + rr * 128 + ((gran * 16) ^ ((rr & 7) << 4)));
#pragma unroll
                for (int mt = 0; mt < 2; mt++) {
                    mma16816(o[mt][2 * np],     pa[mt], vq[0], vq[1]);
                    mma16816(o[mt][2 * np + 1], pa[mt], vq[2], vq[3]);
                }
            }
        }
    }

    uint32_t* a32 = (uint32_t*)g_a;
#pragma unroll
    for (int mt = 0; mt < 2; mt++) {
#pragma unroll
        for (int h = 0; h < 2; h++) {
            float l = lsum[mt][h];
            l += __shfl_xor_sync(0xffffffffu, l, 1);
            l += __shfl_xor_sync(0xffffffffu, l, 2);
            float inv = 1.f / l;
            int m = qbase + w * 32 + mt * 16 + (lane >> 2) + h * 8;
            size_t rb = ((size_t)hd * HW + m) * 32;
#pragma unroll
            for (int nt = 0; nt < 8; nt++) {
                int ocp = nt * 4 + (lane & 3);
                a32[rb + ocp] = packh(o[mt][nt][h * 2] * inv,
                                      o[mt][nt][h * 2 + 1] * inv);
            }
        }
    }
}

// ------------------------------------------------------------------
extern "C" void kernel_launch(void* const* d_in, const int* in_sizes, int n_in,
                              void* d_out, int out_size)
{
    const float* x_in = (const float*)d_in[0];
    const float* h    = (const float*)d_in[1];
    const float* c    = (const float*)d_in[2];
    const float* tau  = (const float*)d_in[3];
    const float* Wx   = (const float*)d_in[4];
    const float* Wig  = (const float*)d_in[5];
    const float* Wq   = (const float*)d_in[6];
    const float* Wk   = (const float*)d_in[7];
    const float* Wv   = (const float*)d_in[8];
    const float* Wia  = (const float*)d_in[9];
    const float* Wix  = (const float*)d_in[10];
    const float* bi   = (const float*)d_in[11];
    const float* Wfa  = (const float*)d_in[12];
    const float* Wfx  = (const float*)d_in[13];
    const float* bf   = (const float*)d_in[14];
    const float* Wga  = (const float*)d_in[15];
    const float* Wgx  = (const float*)d_in[16];
    const float* bg   = (const float*)d_in[17];
    const float* Woa  = (const float*)d_in[18];
    const float* Wox  = (const float*)d_in[19];
    const float* bo   = (const float*)d_in[20];
    float* out = (float*)d_out;

    const int PSMEM = 3 * 32768;            //  96 KB proj
    const int QSMEM = 3 * 40960;            // 120 KB qkv
    const int GSMEM = 3 * 49152;            // 144 KB gates (>=128K for exchange)
    const int ASMEM = 32768 + 3 * 16384;    //  80 KB attn
    cudaFuncSetAttribute(proj_mma,
                         cudaFuncAttributeMaxDynamicSharedMemorySize, PSMEM);
    cudaFuncSetAttribute(qkv_kernel,
                         cudaFuncAttributeMaxDynamicSharedMemorySize, QSMEM);
    cudaFuncSetAttribute(gate_kernel,
                         cudaFuncAttributeMaxDynamicSharedMemorySize, GSMEM);
    cudaFuncSetAttribute(attn_kernel,
                         cudaFuncAttributeMaxDynamicSharedMemorySize, ASMEM);

    prep_w<<<8512, 256>>>(Wq, Wk, Wv, Wix, Wfx, Wgx, Wox, Wia, Wfa, Wga, Woa);
    prep_pw<<<768, 256>>>(Wx, Wig);
    prep_x<<<dim3(18, 12, 2), 256>>>(x_in, h);
    proj_mma<<<dim3(18, 4, 2), 512, PSMEM>>>();
    qkv_kernel<<<dim3(18, 16), 512, QSMEM>>>();
    attn_kernel<<<dim3(9, 16), 256, ASMEM>>>(tau);
    gate_kernel<<<dim3(18, 16), 512, GSMEM>>>(bi, bf, bg, bo, c, out);
}

// round 14
// speedup vs baseline: 9.5083x; 1.0270x over previous
#include <cuda_runtime.h>
#include <cuda_fp16.h>
#include <math.h>
#include <stdint.h>

#define NB   2
#define CINC 256
#define CT   512
#define HH   48
#define HW   2304
#define DS   2116
#define DPAD 2176
#define TOT  (NB*CT*HW)

__device__ __forceinline__ uint32_t packh(float lo, float hi) {
    uint32_t r;
    asm("cvt.rn.f16x2.f32 %0, %1, %2;" : "=r"(r) : "f"(hi), "f"(lo));
    return r;
}
__device__ __forceinline__ float ex2(float x) {
    float y; asm("ex2.approx.f32 %0, %1;" : "=f"(y) : "f"(x)); return y;
}

// ---------------- scratch (all single fp16) ----------------
#define XHPS (16 * HW * 128)
__device__ __align__(256) __half g_xhp[XHPS];                  // [hd][px][128]
__device__ __align__(256) uint32_t g_wb32[7 * 8 * 19 * 2048];  // conv W imgs
__device__ __align__(256) uint32_t g_wpb32[8 * 12 * 2048];     // proj W imgs
__device__ __align__(256) uint32_t g_apm[NB * HW * 384];       // proj A [n][px][768]
__device__ __align__(256) __half g_q[16 * HW * 64];
__device__ __align__(256) __half g_k[16 * DPAD * 64];
__device__ __align__(256) __half g_v[16 * DPAD * 64];
__device__ __align__(256) __half g_a[16 * HW * 64];

// ---------------- cp.async ----------------
__device__ __forceinline__ uint32_t s2u(const void* p) {
    return (uint32_t)__cvta_generic_to_shared(p);
}
__device__ __forceinline__ void cpa16(uint32_t dst, const void* src, bool pred) {
    int sz = pred ? 16 : 0;
    asm volatile("cp.async.cg.shared.global [%0], [%1], 16, %2;\n"
                 :: "r"(dst), "l"(src), "r"(sz) : "memory");
}
#define CP_COMMIT() asm volatile("cp.async.commit_group;\n" ::: "memory")
#define CP_WAIT0()  asm volatile("cp.async.wait_group 0;\n" ::: "memory")
#define CP_WAIT1()  asm volatile("cp.async.wait_group 1;\n" ::: "memory")

// ---------------- mma.sync helpers (fp16 in, fp32 accum) ----------------
#define LDSM4(r, a) \
    asm volatile("ldmatrix.sync.aligned.m8n8.x4.shared.b16 {%0,%1,%2,%3}, [%4];" \
                 : "=r"((r)[0]), "=r"((r)[1]), "=r"((r)[2]), "=r"((r)[3]) : "r"(a))
#define LDSM4T(r, a) \
    asm volatile("ldmatrix.sync.aligned.m8n8.x4.trans.shared.b16 {%0,%1,%2,%3}, [%4];" \
                 : "=r"((r)[0]), "=r"((r)[1]), "=r"((r)[2]), "=r"((r)[3]) : "r"(a))

__device__ __forceinline__ void mma16816(float* d, const uint32_t* a,
                                         uint32_t b0, uint32_t b1) {
    asm volatile(
        "mma.sync.aligned.m16n8k16.row.col.f32.f16.f16.f32 "
        "{%0,%1,%2,%3}, {%4,%5,%6,%7}, {%8,%9}, {%0,%1,%2,%3};"
        : "+f"(d[0]), "+f"(d[1]), "+f"(d[2]), "+f"(d[3])
        : "r"(a[0]), "r"(a[1]), "r"(a[2]), "r"(a[3]), "r"(b0), "r"(b1));
}

// ------------------------------------------------------------------
// prep_all: conv + proj weights -> fp16 images (merged launch)
// blocks [0, 8512): conv weights;  [8512, 9280): proj weights
// ------------------------------------------------------------------
__global__ void prep_all(const float* __restrict__ Wq, const float* __restrict__ Wk,
                         const float* __restrict__ Wv,
                         const float* __restrict__ Wix, const float* __restrict__ Wfx,
                         const float* __restrict__ Wgx, const float* __restrict__ Wox,
                         const float* __restrict__ Wia, const float* __restrict__ Wfa,
                         const float* __restrict__ Wga, const float* __restrict__ Woa,
                         const float* __restrict__ Wx, const float* __restrict__ Wig)
{
    if (blockIdx.x < 8512) {
        int idx = blockIdx.x * 256 + threadIdx.x;
        if (idx >= 7 * 8 * 19 * 64 * 32) return;
        int c2    = idx & 31;
        int oc    = (idx >> 5) & 63;
        int rem   = idx >> 11;
        int chunk = rem % 19;
        int g     = (rem / 19) & 7;
        int type  = rem / 152;
        if (type < 3 && chunk == 18) return;

        float w0, w1;
        if (chunk < 18) {
            const float* W3 = (type == 0) ? Wq : (type == 1) ? Wk : (type == 2) ? Wv :
                              (type == 3) ? Wix : (type == 4) ? Wfx :
                              (type == 5) ? Wgx : Wox;
            int t9 = chunk >> 1, cb = chunk & 1;
            size_t b = ((size_t)(g * 64 + oc) * 128 + cb * 64 + c2 * 2) * 9 + t9;
            w0 = W3[b]; w1 = W3[b + 9];
        } else {
            const float* Wa = (type == 3) ? Wia : (type == 4) ? Wfa :
                              (type == 5) ? Wga : Woa;
            size_t b = (size_t)(g * 64 + oc) * 64 + c2 * 2;
            w0 = Wa[b]; w1 = Wa[b + 1];
        }
        g_wb32[(size_t)rem * 2048 + oc * 32 + c2] = packh(w0, w1);
    } else {
        int idx = (blockIdx.x - 8512) * 256 + threadIdx.x;
        if (idx >= 8 * 12 * 64 * 32) return;
        int c2    = idx & 31;
        int oc    = (idx >> 5) & 63;
        int rem   = idx >> 11;
        int chunk = rem % 12;
        int g     = rem / 12;

        float w0, w1;
        if (chunk < 4) {
            size_t b = (size_t)(g * 64 + oc) * 256 + chunk * 64 + c2 * 2;
            w0 = Wx[b]; w1 = Wx[b + 1];
        } else {
            size_t b = (size_t)(g * 64 + oc) * 512 + (chunk - 4) * 64 + c2 * 2;
            w0 = Wig[b]; w1 = Wig[b + 1];
        }
        g_wpb32[(size_t)rem * 2048 + oc * 32 + c2] = packh(w0, w1);
    }
}

// ------------------------------------------------------------------
// prep_x: transpose x_in+h -> pixel-major fp16 + xh h-half
// ------------------------------------------------------------------
__global__ __launch_bounds__(256) void prep_x(
    const float* __restrict__ x_in, const float* __restrict__ h)
{
    __shared__ float t[64][129];
    int px0 = blockIdx.x * 128;
    int chb = blockIdx.y;
    int n   = blockIdx.z;
    int tid = threadIdx.x;

    for (int i = tid; i < 64 * 128; i += 256) {
        int cl = i >> 7, p = i & 127;
        int ch = chb * 64 + cl;
        float v = (ch < 256)
            ? x_in[((size_t)n * 256 + ch) * HW + px0 + p]
            : h[((size_t)n * 512 + (ch - 256)) * HW + px0 + p];
        t[cl][p] = v;
    }
    __syncthreads();

    for (int i = tid; i < 128 * 32; i += 256) {
        int p = i >> 5, c2 = i & 31;
        uint32_t hv = packh(t[c2 * 2][p], t[c2 * 2 + 1][p]);
        g_apm[((size_t)n * HW + px0 + p) * 384 + chb * 32 + c2] = hv;
        if (chb >= 4) {
            int g = chb - 4;
            ((uint32_t*)g_xhp)[((size_t)(n * 8 + g) * HW + px0 + p) * 64 + 32 + c2] = hv;
        }
    }
}

// ------------------------------------------------------------------
// proj_mma: dense GEMM, N=128, 512 threads, 3-stage (32K/stage).
// ------------------------------------------------------------------
__global__ __launch_bounds__(512, 1) void proj_mma()
{
    extern __shared__ char smem[];
    const int STAGE = 32768;
    uint32_t sb = s2u(smem);
    const int tid = threadIdx.x, w = tid >> 5, lane = tid & 31;
    const int nb = blockIdx.y, n = blockIdx.z;
    const int tile = blockIdx.x;
    const int NCH = 12;
    const int lsub = lane >> 3, lrow = lane & 7;

    auto fill = [&](int s, int k) {
        uint32_t base = sb + s * STAGE;
        {
            int r = tid >> 2, q = tid & 3;
            int px = tile * 128 + r;
            const uint32_t* src = g_apm + ((size_t)n * HW + px) * 384 + k * 32;
            uint32_t sw = (r & 7) << 4;
#pragma unroll
            for (int j = 0; j < 2; j++) {
                int gc = q * 2 + j;
                cpa16(base + r * 128 + ((gc * 16) ^ sw), src + gc * 4, true);
            }
        }
#pragma unroll
        for (int i = 0; i < 2; i++) {
            int p = tid + i * 512;
            int row = p >> 3, gr = p & 7;
            int srctile = (nb * 2 + (row >> 6)) * 12 + k;
            int srow = row & 63;
            const uint32_t* src = g_wpb32 + (size_t)srctile * 2048 + srow * 32 + gr * 4;
            cpa16(base + 16384 + row * 128 + ((gr * 16) ^ ((row & 7) << 4)), src, true);
        }
    };

    float acc[8][4];
#pragma unroll
    for (int nt = 0; nt < 8; nt++)
#pragma unroll
        for (int i = 0; i < 4; i++) acc[nt][i] = 0.f;

    fill(0, 0); CP_COMMIT();
    fill(1, 1); CP_COMMIT();

    for (int k = 0; k < NCH; k++) {
        int s = k % 3;
        if (k + 1 < NCH) { CP_WAIT1(); } else { CP_WAIT0(); }
        __syncthreads();
        if (k + 2 < NCH) { fill((k + 2) % 3, k + 2); CP_COMMIT(); }
        uint32_t Ab = sb + s * STAGE;
        uint32_t Bb = Ab + 16384;
#pragma unroll
        for (int ks = 0; ks < 4; ks++) {
            uint32_t aq[4];
            {
                int r = (w >> 1) * 16 + (lsub & 1) * 8 + lrow;
                uint32_t gran = ks * 2 + (lsub >> 1);
                LDSM4(aq, Ab + r * 128 + ((gran * 16) ^ ((r & 7) << 4)));
            }
#pragma unroll
            for (int p = 0; p < 4; p++) {
                int nn = (w & 1) * 64 + p * 16 + (lsub >> 1) * 8 + lrow;
                uint32_t gran = ks * 2 + (lsub & 1);
                uint32_t bq[4];
                LDSM4(bq, Bb + nn * 128 + ((gran * 16) ^ ((nn & 7) << 4)));
                mma16816(acc[2 * p],     aq, bq[0], bq[1]);
                mma16816(acc[2 * p + 1], aq, bq[2], bq[3]);
            }
        }
    }

    int hd = n * 8 + nb * 2 + (w & 1);
    uint32_t* xh32 = (uint32_t*)g_xhp;
#pragma unroll
    for (int half = 0; half < 2; half++) {
        int m = tile * 128 + (w >> 1) * 16 + (lane >> 2) + half * 8;
        size_t rb = ((size_t)hd * HW + m) * 64;
#pragma unroll
        for (int nt = 0; nt < 8; nt++) {
            int ocp = nt * 4 + (lane & 3);
            xh32[rb + ocp] = packh(acc[nt][half * 2], acc[nt][half * 2 + 1]);
        }
    }
}

// ------------------------------------------------------------------
// qkv_kernel: 384 threads, 12 warps; warp = (32px = w&3, zz = w>>2).
// Per ks: 2 LDSM_A + 4 LDSM_B + 16 mma.  3-stage (40K/stage).
// ------------------------------------------------------------------
__global__ __launch_bounds__(384, 1) void qkv_kernel()
{
    extern __shared__ char smem[];
    const int STAGE = 40960;
    uint32_t sb = s2u(smem);
    const int tid = threadIdx.x, w = tid >> 5, lane = tid & 31;
    const int hd = blockIdx.y, g = hd & 7;
    const int tile = blockIdx.x;
    const int NCH = 18;
    const int lsub = lane >> 3, lrow = lane & 7;
    const int pxg = w & 3, z = w >> 2;

    auto fill = [&](int s, int k) {
        uint32_t base = sb + s * STAGE;
        int t9 = k >> 1, cb = k & 1, ky = t9 / 3, kx = t9 - ky * 3;
        for (int p = tid; p < 1024; p += 384) {
            int r = p >> 3, gc = p & 7;
            int px_ = tile * 128 + r;
            int py_ = px_ / 48, pxx_ = px_ - py_ * 48;
            int iy = py_ + ky - 1, ix = pxx_ + kx - 1;
            bool in = ((unsigned)iy < 48u) && ((unsigned)ix < 48u);
            const __half* rp =
                g_xhp + (((size_t)hd * HW + iy * 48 + ix) * 128 + cb * 64);
            if (!in) rp = g_xhp;
            cpa16(base + r * 128 + ((gc * 16) ^ ((r & 7) << 4)),
                  (const char*)rp + gc * 16, in);
        }
#pragma unroll
        for (int i = 0; i < 4; i++) {
            int p = tid + i * 384;   // 0..1535
            int zz = p >> 9, pg = p & 511;
            int oc = pg >> 3, gr = pg & 7;
            const uint32_t* wsrc = g_wb32 + ((size_t)(zz * 8 + g) * 19 + k) * 2048;
            cpa16(base + 16384 + zz * 8192 + oc * 128 + ((gr * 16) ^ ((oc & 7) << 4)),
                  wsrc + pg * 4, true);
        }
    };

    float acc[2][8][4];
#pragma unroll
    for (int mt = 0; mt < 2; mt++)
#pragma unroll
        for (int nt = 0; nt < 8; nt++)
#pragma unroll
            for (int i = 0; i < 4; i++) acc[mt][nt][i] = 0.f;

    fill(0, 0); CP_COMMIT();
    fill(1, 1); CP_COMMIT();

    for (int k = 0; k < NCH; k++) {
        int s = k % 3;
        if (k + 1 < NCH) { CP_WAIT1(); } else { CP_WAIT0(); }
        __syncthreads();
        if (k + 2 < NCH) { fill((k + 2) % 3, k + 2); CP_COMMIT(); }
        uint32_t Ab = sb + s * STAGE;
        uint32_t Bb = Ab + 16384 + z * 8192;
#pragma unroll
        for (int ks = 0; ks < 4; ks++) {
            uint32_t aq[2][4];
#pragma unroll
            for (int mt = 0; mt < 2; mt++) {
                int r = pxg * 32 + mt * 16 + (lsub & 1) * 8 + lrow;
                uint32_t gran = ks * 2 + (lsub >> 1);
                LDSM4(aq[mt], Ab + r * 128 + ((gran * 16) ^ ((r & 7) << 4)));
            }
#pragma unroll
            for (int p = 0; p < 4; p++) {
                int nn = p * 16 + (lsub >> 1) * 8 + lrow;
                uint32_t gran = ks * 2 + (lsub & 1);
                uint32_t bq[4];
                LDSM4(bq, Bb + nn * 128 + ((gran * 16) ^ ((nn & 7) << 4)));
#pragma unroll
                for (int mt = 0; mt < 2; mt++) {
                    mma16816(acc[mt][2 * p],     aq[mt], bq[0], bq[1]);
                    mma16816(acc[mt][2 * p + 1], aq[mt], bq[2], bq[3]);
                }
            }
        }
    }

    uint32_t* q32 = (uint32_t*)g_q;
#pragma unroll
    for (int mt = 0; mt < 2; mt++) {
#pragma unroll
        for (int half = 0; half < 2; half++) {
            int m = tile * 128 + pxg * 32 + mt * 16 + (lane >> 2) + half * 8;
            if (z == 0) {
                size_t rb = ((size_t)hd * HW + m) * 32;
#pragma unroll
                for (int nt = 0; nt < 8; nt++) {
                    int ocp = nt * 4 + (lane & 3);
                    q32[rb + ocp] = packh(acc[mt][nt][half * 2],
                                          acc[mt][nt][half * 2 + 1]);
                }
            } else {
                int oy = m / 48, ox = m - oy * 48;
                if (oy >= 1 && oy <= 46 && ox >= 1 && ox <= 46) {
                    int d = (oy - 1) * 46 + (ox - 1);
                    size_t rb = ((size_t)hd * DPAD + d) * 32;
                    uint32_t* dst = (uint32_t*)((z == 1) ? g_k : g_v);
#pragma unroll
                    for (int nt = 0; nt < 8; nt++) {
                        int ocp = nt * 4 + (lane & 3);
                        dst[rb + ocp] = packh(acc[mt][nt][half * 2],
                                              acc[mt][nt][half * 2 + 1]);
                    }
                }
            }
        }
    }
}

// ------------------------------------------------------------------
// gate_kernel: 512 threads, 3-stage.  warp = (32px = w&3, 1 gate = w>>2).
// LSTM fused via smem exchange.
// ------------------------------------------------------------------
__global__ __launch_bounds__(512, 1) void gate_kernel(
    const float* __restrict__ bbi, const float* __restrict__ bbf,
    const float* __restrict__ bbg, const float* __restrict__ bbo,
    const float* __restrict__ cold, float* __restrict__ out)
{
    extern __shared__ char smem[];
    const int STAGE = 49152;
    uint32_t sb = s2u(smem);
    const int tid = threadIdx.x, w = tid >> 5, lane = tid & 31;
    const int hd = blockIdx.y, g = hd & 7;
    const int tile = blockIdx.x;
    const int NCH = 19;
    const int lsub = lane >> 3, lrow = lane & 7;
    const int pxg = w & 3, z = w >> 2;

    auto fill = [&](int s, int k) {
        uint32_t base = sb + s * STAGE;
        {
            int r = tid >> 2, q = tid & 3;
            int px_ = tile * 128 + r;
            const char* sh; bool in;
            if (k < 18) {
                int py_ = px_ / 48, pxx_ = px_ - py_ * 48;
                int t9 = k >> 1, cb = k & 1, ky = t9 / 3, kx = t9 - ky * 3;
                int iy = py_ + ky - 1, ix = pxx_ + kx - 1;
                in = ((unsigned)iy < 48u) && ((unsigned)ix < 48u);
                const __half* rp =
                    g_xhp + (((size_t)hd * HW + iy * 48 + ix) * 128 + cb * 64);
                if (!in) rp = g_xhp;
                sh = (const char*)rp;
            } else {
                in = true;
                sh = (const char*)(g_a + ((size_t)hd * HW + px_) * 64);
            }
            uint32_t sw = (r & 7) << 4;
#pragma unroll
            for (int j = 0; j < 2; j++) {
                int gc = q * 2 + j;
                cpa16(base + r * 128 + ((gc * 16) ^ sw), sh + gc * 16, in);
            }
        }
#pragma unroll
        for (int i = 0; i < 4; i++) {
            int p = tid + i * 512;
            int zz = p >> 9, pg = p & 511;
            int oc = pg >> 3, gr = pg & 7;
            const uint32_t* wsrc =
                g_wb32 + ((size_t)((3 + zz) * 8 + g) * 19 + k) * 2048;
            cpa16(base + 16384 + zz * 8192 + oc * 128 + ((gr * 16) ^ ((oc & 7) << 4)),
                  wsrc + pg * 4, true);
        }
    };

    float acc[2][8][4];
#pragma unroll
    for (int mt = 0; mt < 2; mt++)
#pragma unroll
        for (int nt = 0; nt < 8; nt++)
#pragma unroll
            for (int i = 0; i < 4; i++) acc[mt][nt][i] = 0.f;

    fill(0, 0); CP_COMMIT();
    fill(1, 1); CP_COMMIT();

    for (int k = 0; k < NCH; k++) {
        int s = k % 3;
        if (k + 1 < NCH) { CP_WAIT1(); } else { CP_WAIT0(); }
        __syncthreads();
        if (k + 2 < NCH) { fill((k + 2) % 3, k + 2); CP_COMMIT(); }
        uint32_t Ab = sb + s * STAGE;
        uint32_t Bb = Ab + 16384 + z * 8192;
#pragma unroll
        for (int ks = 0; ks < 4; ks++) {
            uint32_t aq[2][4];
#pragma unroll
            for (int mt = 0; mt < 2; mt++) {
                int r = pxg * 32 + mt * 16 + (lsub & 1) * 8 + lrow;
                uint32_t gran = ks * 2 + (lsub >> 1);
                LDSM4(aq[mt], Ab + r * 128 + ((gran * 16) ^ ((r & 7) << 4)));
            }
#pragma unroll
            for (int p = 0; p < 4; p++) {
                int nn = p * 16 + (lsub >> 1) * 8 + lrow;
                uint32_t gran = ks * 2 + (lsub & 1);
                uint32_t bq[4];
                LDSM4(bq, Bb + nn * 128 + ((gran * 16) ^ ((nn & 7) << 4)));
#pragma unroll
                for (int mt = 0; mt < 2; mt++) {
                    mma16816(acc[mt][2 * p],     aq[mt], bq[0], bq[1]);
                    mma16816(acc[mt][2 * p + 1], aq[mt], bq[2], bq[3]);
                }
            }
        }
    }

    // ---- epilogue: exchange gate fragments via smem, LSTM, write ----
    float* smf = (float*)smem;      // [z][px128][oc64] fp32 = 128 KB
    __syncthreads();
#pragma unroll
    for (int mt = 0; mt < 2; mt++) {
#pragma unroll
        for (int half = 0; half < 2; half++) {
            int pxl = pxg * 32 + mt * 16 + (lane >> 2) + half * 8;
#pragma unroll
            for (int nt = 0; nt < 8; nt++) {
                int oc0 = nt * 8 + (lane & 3) * 2;
                float2 v = make_float2(acc[mt][nt][half * 2],
                                       acc[mt][nt][half * 2 + 1]);
                *(float2*)(smf + z * 8192 + pxl * 64 + oc0) = v;
            }
        }
    }
    __syncthreads();

    int n = hd >> 3;
#pragma unroll
    for (int i = 0; i < 16; i++) {
        int elem = i * 512 + tid;
        int pxl = elem >> 6, oc = elem & 63;
        float pi = smf[0 * 8192 + pxl * 64 + oc] + bbi[g * 64 + oc];
        float pf = smf[1 * 8192 + pxl * 64 + oc] + bbf[g * 64 + oc];
        float pg = smf[2 * 8192 + pxl * 64 + oc] + bbg[g * 64 + oc];
        float po = smf[3 * 8192 + pxl * 64 + oc] + bbo[g * 64 + oc];
        float ig = 1.f / (1.f + __expf(-pi));
        float fg = 1.f / (1.f + __expf(-pf));
        float gg = tanhf(pg);
        float og = 1.f / (1.f + __expf(-po));
        size_t ci = ((size_t)n * 512 + g * 64 + oc) * HW + tile * 128 + pxl;
        float cn = fg * cold[ci] + ig * gg;
        out[ci] = og * tanhf(cn);
    }
}

// ------------------------------------------------------------------
// attn_kernel: 256 threads, 8 warps, warp = 32 queries x 64 keys.
// CTA = 256 queries, 3-stage KV.  SMEM: Q 32K | 3 x 16K = 80K.
// ------------------------------------------------------------------
__global__ __launch_bounds__(256, 1) void attn_kernel(const float* __restrict__ tau)
{
    extern __shared__ char smem[];
    uint32_t sb = s2u(smem);
    const int tid = threadIdx.x, w = tid >> 5, lane = tid & 31;
    const int hd = blockIdx.y, g = hd & 7;
    const int qbase = blockIdx.x * 256;
    const int lsub = lane >> 3, lrow = lane & 7;
    const float ts2 = tau[g] * 1.44269504f;
    const int NCHK = (DS + 63) / 64;   // 34

    // Q fill (once): 256 rows x 128 bytes, 1 thread per row
    {
        int r = tid;
        const char* qs = (const char*)g_q + ((size_t)hd * HW + qbase + r) * 128;
        uint32_t sw = (r & 7) << 4;
#pragma unroll
        for (int gc = 0; gc < 8; gc++)
            cpa16(sb + r * 128 + ((gc * 16) ^ sw), qs + gc * 16, true);
    }
    auto fillkv = [&](int s, int c) {
        uint32_t base = sb + 32768 + s * 16384;
        int r = tid >> 2;
        int q4 = tid & 3;
        int d = c * 64 + r;
        bool ok = d < DS;
        size_t rb = ((size_t)hd * DPAD + (ok ? d : 0)) * 128;  // bytes
        uint32_t sw = (r & 7) << 4;
#pragma unroll
        for (int gg = 0; gg < 2; gg++) {
            int gran = q4 * 2 + gg;
            uint32_t off = r * 128 + ((gran * 16) ^ sw);
            cpa16(base + off,        (const char*)g_k + rb + gran * 16, ok);
            cpa16(base + 8192 + off, (const char*)g_v + rb + gran * 16, ok);
        }
    };

    fillkv(0, 0); CP_COMMIT();
    fillkv(1, 1); CP_COMMIT();

    float o[2][8][4];
#pragma unroll
    for (int mt = 0; mt < 2; mt++)
#pragma unroll
        for (int nt = 0; nt < 8; nt++)
#pragma unroll
            for (int i = 0; i < 4; i++) o[mt][nt][i] = 0.f;
    float mrow[2][2] = {{-1e30f, -1e30f}, {-1e30f, -1e30f}};
    float lsum[2][2] = {{0.f, 0.f}, {0.f, 0.f}};

    for (int c = 0; c < NCHK; c++) {
        int s = c % 3;
        if (c + 1 < NCHK) { CP_WAIT1(); } else { CP_WAIT0(); }
        __syncthreads();
        if (c + 2 < NCHK) { fillkv((c + 2) % 3, c + 2); CP_COMMIT(); }
        uint32_t Kb = sb + 32768 + s * 16384;
        uint32_t Vb = Kb + 8192;

        float sf[2][8][4];
#pragma unroll
        for (int mt = 0; mt < 2; mt++)
#pragma unroll
            for (int nt = 0; nt < 8; nt++)
#pragma unroll
                for (int i = 0; i < 4; i++) sf[mt][nt][i] = 0.f;
#pragma unroll
        for (int ks = 0; ks < 4; ks++) {
            uint32_t aq[2][4];
#pragma unroll
            for (int mt = 0; mt < 2; mt++) {
                int r = w * 32 + mt * 16 + (lsub & 1) * 8 + lrow;
                uint32_t gran = ks * 2 + (lsub >> 1);
                LDSM4(aq[mt], sb + r * 128 + ((gran * 16) ^ ((r & 7) << 4)));
            }
#pragma unroll
            for (int p = 0; p < 4; p++) {
                int nn = p * 16 + (lsub >> 1) * 8 + lrow;
                uint32_t gran = ks * 2 + (lsub & 1);
                uint32_t bq[4];
                LDSM4(bq, Kb + nn * 128 + ((gran * 16) ^ ((nn & 7) << 4)));
#pragma unroll
                for (int mt = 0; mt < 2; mt++) {
                    mma16816(sf[mt][2 * p],     aq[mt], bq[0], bq[1]);
                    mma16816(sf[mt][2 * p + 1], aq[mt], bq[2], bq[3]);
                }
            }
        }

        // mask tail keys (only last chunk)
        if (c == NCHK - 1) {
            int dbase = c * 64 + (lane & 3) * 2;
#pragma unroll
            for (int mt = 0; mt < 2; mt++)
#pragma unroll
                for (int nt = 0; nt < 8; nt++)
#pragma unroll
                    for (int i = 0; i < 4; i++) {
                        int d = dbase + nt * 8 + (i & 1);
                        if (d >= DS) sf[mt][nt][i] = -1e30f;
                    }
        }

        // online softmax (s-domain max, ex2)
        float alpha[2][2];
#pragma unroll
        for (int mt = 0; mt < 2; mt++) {
#pragma unroll
            for (int h = 0; h < 2; h++) {
                float mx = mrow[mt][h];
#pragma unroll
                for (int nt = 0; nt < 8; nt++) {
                    mx = fmaxf(mx, sf[mt][nt][h * 2]);
                    mx = fmaxf(mx, sf[mt][nt][h * 2 + 1]);
                }
                mx = fmaxf(mx, __shfl_xor_sync(0xffffffffu, mx, 1));
                mx = fmaxf(mx, __shfl_xor_sync(0xffffffffu, mx, 2));
                float nm = mx * ts2;
                float al_ = ex2(fmaf(mrow[mt][h], ts2, -nm));
                mrow[mt][h] = mx;
                alpha[mt][h] = al_;
                float ls = lsum[mt][h] * al_;
#pragma unroll
                for (int nt = 0; nt < 8; nt++) {
#pragma unroll
                    for (int e = 0; e < 2; e++) {
                        float p = ex2(fmaf(sf[mt][nt][h * 2 + e], ts2, -nm));
                        sf[mt][nt][h * 2 + e] = p;
                        ls += p;
                    }
                }
                lsum[mt][h] = ls;
            }
        }
#pragma unroll
        for (int mt = 0; mt < 2; mt++)
#pragma unroll
            for (int nt = 0; nt < 8; nt++) {
                o[mt][nt][0] *= alpha[mt][0];
                o[mt][nt][1] *= alpha[mt][0];
                o[mt][nt][2] *= alpha[mt][1];
                o[mt][nt][3] *= alpha[mt][1];
            }

        // O += P V
#pragma unroll
        for (int kt = 0; kt < 4; kt++) {
            uint32_t pa[2][4];
#pragma unroll
            for (int mt = 0; mt < 2; mt++)
#pragma unroll
                for (int i = 0; i < 4; i++) {
                    int nt = 2 * kt + (i >> 1);
                    pa[mt][i] = packh(sf[mt][nt][(i & 1) * 2],
                                      sf[mt][nt][(i & 1) * 2 + 1]);
                }
#pragma unroll
            for (int np = 0; np < 4; np++) {
                int rr = kt * 16 + (lane & 15);
                uint32_t gran = np * 2 + (lane >> 4);
                uint32_t vq[4];
                LDSM4T(vq, Vb + rr * 128 + ((gran * 16) ^ ((rr & 7) << 4)));
#pragma unroll
                for (int mt = 0; mt < 2; mt++) {
                    mma16816(o[mt][2 * np],     pa[mt], vq[0], vq[1]);
                    mma16816(o[mt][2 * np + 1], pa[mt], vq[2], vq[3]);
                }
            }
        }
    }

    uint32_t* a32 = (uint32_t*)g_a;
#pragma unroll
    for (int mt = 0; mt < 2; mt++) {
#pragma unroll
        for (int h = 0; h < 2; h++) {
            float l = lsum[mt][h];
            l += __shfl_xor_sync(0xffffffffu, l, 1);
            l += __shfl_xor_sync(0xffffffffu, l, 2);
            float inv = 1.f / l;
            int m = qbase + w * 32 + mt * 16 + (lane >> 2) + h * 8;
            size_t rb = ((size_t)hd * HW + m) * 32;
#pragma unroll
            for (int nt = 0; nt < 8; nt++) {
                int ocp = nt * 4 + (lane & 3);
                a32[rb + ocp] = packh(o[mt][nt][h * 2] * inv,
                                      o[mt][nt][h * 2 + 1] * inv);
            }
        }
    }
}

// ------------------------------------------------------------------
extern "C" void kernel_launch(void* const* d_in, const int* in_sizes, int n_in,
                              void* d_out, int out_size)
{
    const float* x_in = (const float*)d_in[0];
    const float* h    = (const float*)d_in[1];
    const float* c    = (const float*)d_in[2];
    const float* tau  = (const float*)d_in[3];
    const float* Wx   = (const float*)d_in[4];
    const float* Wig  = (const float*)d_in[5];
    const float* Wq   = (const float*)d_in[6];
    const float* Wk   = (const float*)d_in[7];
    const float* Wv   = (const float*)d_in[8];
    const float* Wia  = (const float*)d_in[9];
    const float* Wix  = (const float*)d_in[10];
    const float* bi   = (const float*)d_in[11];
    const float* Wfa  = (const float*)d_in[12];
    const float* Wfx  = (const float*)d_in[13];
    const float* bf   = (const float*)d_in[14];
    const float* Wga  = (const float*)d_in[15];
    const float* Wgx  = (const float*)d_in[16];
    const float* bg   = (const float*)d_in[17];
    const float* Woa  = (const float*)d_in[18];
    const float* Wox  = (const float*)d_in[19];
    const float* bo   = (const float*)d_in[20];
    float* out = (float*)d_out;

    const int PSMEM = 3 * 32768;            //  96 KB proj
    const int QSMEM = 3 * 40960;            // 120 KB qkv
    const int GSMEM = 3 * 49152;            // 144 KB gates
    const int ASMEM = 32768 + 3 * 16384;    //  80 KB attn
    cudaFuncSetAttribute(proj_mma,
                         cudaFuncAttributeMaxDynamicSharedMemorySize, PSMEM);
    cudaFuncSetAttribute(qkv_kernel,
                         cudaFuncAttributeMaxDynamicSharedMemorySize, QSMEM);
    cudaFuncSetAttribute(gate_kernel,
                         cudaFuncAttributeMaxDynamicSharedMemorySize, GSMEM);
    cudaFuncSetAttribute(attn_kernel,
                         cudaFuncAttributeMaxDynamicSharedMemorySize, ASMEM);

    prep_all<<<9280, 256>>>(Wq, Wk, Wv, Wix, Wfx, Wgx, Wox,
                            Wia, Wfa, Wga, Woa, Wx, Wig);
    prep_x<<<dim3(18, 12, 2), 256>>>(x_in, h);
    proj_mma<<<dim3(18, 4, 2), 512, PSMEM>>>();
    qkv_kernel<<<dim3(18, 16), 384, QSMEM>>>();
    attn_kernel<<<dim3(9, 16), 256, ASMEM>>>(tau);
    gate_kernel<<<dim3(18, 16), 512, GSMEM>>>(bi, bf, bg, bo, c, out);
}

// round 15
// speedup vs baseline: 9.5540x; 1.0048x over previous
#include <cuda_runtime.h>
#include <cuda_fp16.h>
#include <math.h>
#include <stdint.h>

#define NB   2
#define CINC 256
#define CT   512
#define HH   48
#define HW   2304
#define DS   2116
#define DPAD 2176
#define TOT  (NB*CT*HW)

__device__ __forceinline__ uint32_t packh(float lo, float hi) {
    uint32_t r;
    asm("cvt.rn.f16x2.f32 %0, %1, %2;" : "=r"(r) : "f"(hi), "f"(lo));
    return r;
}
__device__ __forceinline__ float ex2(float x) {
    float y; asm("ex2.approx.f32 %0, %1;" : "=f"(y) : "f"(x)); return y;
}

// ---------------- scratch (all single fp16) ----------------
#define XHPS (16 * HW * 128)
__device__ __align__(256) __half g_xhp[XHPS];                  // [hd][px][128]
__device__ __align__(256) uint32_t g_wb32[7 * 8 * 19 * 2048];  // conv W imgs
__device__ __align__(256) uint32_t g_wpb32[8 * 12 * 2048];     // proj W imgs
__device__ __align__(256) uint32_t g_apm[NB * HW * 384];       // proj A [n][px][768]
__device__ __align__(256) __half g_q[16 * HW * 64];
__device__ __align__(256) __half g_k[16 * DPAD * 64];
__device__ __align__(256) __half g_v[16 * DPAD * 64];
__device__ __align__(256) __half g_a[16 * HW * 64];

// ---------------- cp.async ----------------
__device__ __forceinline__ uint32_t s2u(const void* p) {
    return (uint32_t)__cvta_generic_to_shared(p);
}
__device__ __forceinline__ void cpa16(uint32_t dst, const void* src, bool pred) {
    int sz = pred ? 16 : 0;
    asm volatile("cp.async.cg.shared.global [%0], [%1], 16, %2;\n"
                 :: "r"(dst), "l"(src), "r"(sz) : "memory");
}
#define CP_COMMIT() asm volatile("cp.async.commit_group;\n" ::: "memory")
#define CP_WAIT0()  asm volatile("cp.async.wait_group 0;\n" ::: "memory")
#define CP_WAIT1()  asm volatile("cp.async.wait_group 1;\n" ::: "memory")

// ---------------- mma.sync helpers (fp16 in, fp32 accum) ----------------
#define LDSM4(r, a) \
    asm volatile("ldmatrix.sync.aligned.m8n8.x4.shared.b16 {%0,%1,%2,%3}, [%4];" \
                 : "=r"((r)[0]), "=r"((r)[1]), "=r"((r)[2]), "=r"((r)[3]) : "r"(a))
#define LDSM4T(r, a) \
    asm volatile("ldmatrix.sync.aligned.m8n8.x4.trans.shared.b16 {%0,%1,%2,%3}, [%4];" \
                 : "=r"((r)[0]), "=r"((r)[1]), "=r"((r)[2]), "=r"((r)[3]) : "r"(a))

__device__ __forceinline__ void mma16816(float* d, const uint32_t* a,
                                         uint32_t b0, uint32_t b1) {
    asm volatile(
        "mma.sync.aligned.m16n8k16.row.col.f32.f16.f16.f32 "
        "{%0,%1,%2,%3}, {%4,%5,%6,%7}, {%8,%9}, {%0,%1,%2,%3};"
        : "+f"(d[0]), "+f"(d[1]), "+f"(d[2]), "+f"(d[3])
        : "r"(a[0]), "r"(a[1]), "r"(a[2]), "r"(a[3]), "r"(b0), "r"(b1));
}

// ------------------------------------------------------------------
// prep_all: conv + proj weights -> fp16 images (merged launch)
// ------------------------------------------------------------------
__global__ void prep_all(const float* __restrict__ Wq, const float* __restrict__ Wk,
                         const float* __restrict__ Wv,
                         const float* __restrict__ Wix, const float* __restrict__ Wfx,
                         const float* __restrict__ Wgx, const float* __restrict__ Wox,
                         const float* __restrict__ Wia, const float* __restrict__ Wfa,
                         const float* __restrict__ Wga, const float* __restrict__ Woa,
                         const float* __restrict__ Wx, const float* __restrict__ Wig)
{
    if (blockIdx.x < 8512) {
        int idx = blockIdx.x * 256 + threadIdx.x;
        if (idx >= 7 * 8 * 19 * 64 * 32) return;
        int c2    = idx & 31;
        int oc    = (idx >> 5) & 63;
        int rem   = idx >> 11;
        int chunk = rem % 19;
        int g     = (rem / 19) & 7;
        int type  = rem / 152;
        if (type < 3 && chunk == 18) return;

        float w0, w1;
        if (chunk < 18) {
            const float* W3 = (type == 0) ? Wq : (type == 1) ? Wk : (type == 2) ? Wv :
                              (type == 3) ? Wix : (type == 4) ? Wfx :
                              (type == 5) ? Wgx : Wox;
            int t9 = chunk >> 1, cb = chunk & 1;
            size_t b = ((size_t)(g * 64 + oc) * 128 + cb * 64 + c2 * 2) * 9 + t9;
            w0 = W3[b]; w1 = W3[b + 9];
        } else {
            const float* Wa = (type == 3) ? Wia : (type == 4) ? Wfa :
                              (type == 5) ? Wga : Woa;
            size_t b = (size_t)(g * 64 + oc) * 64 + c2 * 2;
            w0 = Wa[b]; w1 = Wa[b + 1];
        }
        g_wb32[(size_t)rem * 2048 + oc * 32 + c2] = packh(w0, w1);
    } else {
        int idx = (blockIdx.x - 8512) * 256 + threadIdx.x;
        if (idx >= 8 * 12 * 64 * 32) return;
        int c2    = idx & 31;
        int oc    = (idx >> 5) & 63;
        int rem   = idx >> 11;
        int chunk = rem % 12;
        int g     = rem / 12;

        float w0, w1;
        if (chunk < 4) {
            size_t b = (size_t)(g * 64 + oc) * 256 + chunk * 64 + c2 * 2;
            w0 = Wx[b]; w1 = Wx[b + 1];
        } else {
            size_t b = (size_t)(g * 64 + oc) * 512 + (chunk - 4) * 64 + c2 * 2;
            w0 = Wig[b]; w1 = Wig[b + 1];
        }
        g_wpb32[(size_t)rem * 2048 + oc * 32 + c2] = packh(w0, w1);
    }
}

// ------------------------------------------------------------------
// prep_x: transpose x_in+h -> pixel-major fp16 + xh h-half
// ------------------------------------------------------------------
__global__ __launch_bounds__(256) void prep_x(
    const float* __restrict__ x_in, const float* __restrict__ h)
{
    __shared__ float t[64][129];
    int px0 = blockIdx.x * 128;
    int chb = blockIdx.y;
    int n   = blockIdx.z;
    int tid = threadIdx.x;

    for (int i = tid; i < 64 * 128; i += 256) {
        int cl = i >> 7, p = i & 127;
        int ch = chb * 64 + cl;
        float v = (ch < 256)
            ? x_in[((size_t)n * 256 + ch) * HW + px0 + p]
            : h[((size_t)n * 512 + (ch - 256)) * HW + px0 + p];
        t[cl][p] = v;
    }
    __syncthreads();

    for (int i = tid; i < 128 * 32; i += 256) {
        int p = i >> 5, c2 = i & 31;
        uint32_t hv = packh(t[c2 * 2][p], t[c2 * 2 + 1][p]);
        g_apm[((size_t)n * HW + px0 + p) * 384 + chb * 32 + c2] = hv;
        if (chb >= 4) {
            int g = chb - 4;
            ((uint32_t*)g_xhp)[((size_t)(n * 8 + g) * HW + px0 + p) * 64 + 32 + c2] = hv;
        }
    }
}

// ------------------------------------------------------------------
// proj_mma: dense GEMM, N=128, 512 threads, 3-stage (32K/stage).
// ------------------------------------------------------------------
__global__ __launch_bounds__(512, 1) void proj_mma()
{
    extern __shared__ char smem[];
    const int STAGE = 32768;
    uint32_t sb = s2u(smem);
    const int tid = threadIdx.x, w = tid >> 5, lane = tid & 31;
    const int nb = blockIdx.y, n = blockIdx.z;
    const int tile = blockIdx.x;
    const int NCH = 12;
    const int lsub = lane >> 3, lrow = lane & 7;

    auto fill = [&](int s, int k) {
        uint32_t base = sb + s * STAGE;
        {
            int r = tid >> 2, q = tid & 3;
            int px = tile * 128 + r;
            const uint32_t* src = g_apm + ((size_t)n * HW + px) * 384 + k * 32;
            uint32_t sw = (r & 7) << 4;
#pragma unroll
            for (int j = 0; j < 2; j++) {
                int gc = q * 2 + j;
                cpa16(base + r * 128 + ((gc * 16) ^ sw), src + gc * 4, true);
            }
        }
#pragma unroll
        for (int i = 0; i < 2; i++) {
            int p = tid + i * 512;
            int row = p >> 3, gr = p & 7;
            int srctile = (nb * 2 + (row >> 6)) * 12 + k;
            int srow = row & 63;
            const uint32_t* src = g_wpb32 + (size_t)srctile * 2048 + srow * 32 + gr * 4;
            cpa16(base + 16384 + row * 128 + ((gr * 16) ^ ((row & 7) << 4)), src, true);
        }
    };

    float acc[8][4];
#pragma unroll
    for (int nt = 0; nt < 8; nt++)
#pragma unroll
        for (int i = 0; i < 4; i++) acc[nt][i] = 0.f;

    fill(0, 0); CP_COMMIT();
    fill(1, 1); CP_COMMIT();

    for (int k = 0; k < NCH; k++) {
        int s = k % 3;
        if (k + 1 < NCH) { CP_WAIT1(); } else { CP_WAIT0(); }
        __syncthreads();
        if (k + 2 < NCH) { fill((k + 2) % 3, k + 2); CP_COMMIT(); }
        uint32_t Ab = sb + s * STAGE;
        uint32_t Bb = Ab + 16384;
#pragma unroll
        for (int ks = 0; ks < 4; ks++) {
            uint32_t aq[4];
            {
                int r = (w >> 1) * 16 + (lsub & 1) * 8 + lrow;
                uint32_t gran = ks * 2 + (lsub >> 1);
                LDSM4(aq, Ab + r * 128 + ((gran * 16) ^ ((r & 7) << 4)));
            }
#pragma unroll
            for (int p = 0; p < 4; p++) {
                int nn = (w & 1) * 64 + p * 16 + (lsub >> 1) * 8 + lrow;
                uint32_t gran = ks * 2 + (lsub & 1);
                uint32_t bq[4];
                LDSM4(bq, Bb + nn * 128 + ((gran * 16) ^ ((nn & 7) << 4)));
                mma16816(acc[2 * p],     aq, bq[0], bq[1]);
                mma16816(acc[2 * p + 1], aq, bq[2], bq[3]);
            }
        }
    }

    int hd = n * 8 + nb * 2 + (w & 1);
    uint32_t* xh32 = (uint32_t*)g_xhp;
#pragma unroll
    for (int half = 0; half < 2; half++) {
        int m = tile * 128 + (w >> 1) * 16 + (lane >> 2) + half * 8;
        size_t rb = ((size_t)hd * HW + m) * 64;
#pragma unroll
        for (int nt = 0; nt < 8; nt++) {
            int ocp = nt * 4 + (lane & 3);
            xh32[rb + ocp] = packh(acc[nt][half * 2], acc[nt][half * 2 + 1]);
        }
    }
}

// ------------------------------------------------------------------
// qkv_kernel: 384 threads, 12 warps; warp = (32px = w&3, zz = w>>2).
// Fill addressing hoisted out of the chunk loop.
// ------------------------------------------------------------------
__global__ __launch_bounds__(384, 1) void qkv_kernel()
{
    extern __shared__ char smem[];
    const int STAGE = 40960;
    uint32_t sb = s2u(smem);
    const int tid = threadIdx.x, w = tid >> 5, lane = tid & 31;
    const int hd = blockIdx.y, g = hd & 7;
    const int tile = blockIdx.x;
    const int NCH = 18;
    const int lsub = lane >> 3, lrow = lane & 7;
    const int pxg = w & 3, z = w >> 2;

    const __half* xbase = g_xhp + (size_t)hd * HW * 128;

    // hoisted A-fill addressing: 3 granules per thread (1024 total)
    int apy[3], apx[3];
    uint32_t adst[3], agc[3];
    bool aval[3];
#pragma unroll
    for (int i = 0; i < 3; i++) {
        int p = tid + i * 384;
        aval[i] = p < 1024;
        int pp = aval[i] ? p : 0;
        int r = pp >> 3, gc = pp & 7;
        int px_ = tile * 128 + r;
        apy[i] = px_ / 48;
        apx[i] = px_ - apy[i] * 48;
        adst[i] = r * 128 + (uint32_t)((gc * 16) ^ ((r & 7) << 4));
        agc[i] = gc * 16;
    }
    // hoisted B-fill addressing: 4 granules per thread (1536 total)
    uint32_t bdst[4];
    const uint32_t* bsrc[4];
#pragma unroll
    for (int i = 0; i < 4; i++) {
        int p = tid + i * 384;
        int zz = p >> 9, pg = p & 511;
        int oc = pg >> 3, gr = pg & 7;
        bdst[i] = 16384 + zz * 8192 + oc * 128 + (uint32_t)((gr * 16) ^ ((oc & 7) << 4));
        bsrc[i] = g_wb32 + ((size_t)(zz * 8 + g) * 19) * 2048 + pg * 4;
    }

    auto fill = [&](int s, int k) {
        uint32_t base = sb + s * STAGE;
        int t9 = k >> 1, cb = k & 1, ky = t9 / 3, kx = t9 - ky * 3;
        int chof = cb * 64;
#pragma unroll
        for (int i = 0; i < 3; i++) {
            if (aval[i]) {
                int iy = apy[i] + ky - 1, ix = apx[i] + kx - 1;
                bool in = ((unsigned)iy < 48u) && ((unsigned)ix < 48u);
                const __half* rp = in ? (xbase + ((size_t)(iy * 48 + ix)) * 128 + chof)
                                      : g_xhp;
                cpa16(base + adst[i], (const char*)rp + agc[i], in);
            }
        }
#pragma unroll
        for (int i = 0; i < 4; i++)
            cpa16(base + bdst[i], bsrc[i] + (size_t)k * 2048, true);
    };

    float acc[2][8][4];
#pragma unroll
    for (int mt = 0; mt < 2; mt++)
#pragma unroll
        for (int nt = 0; nt < 8; nt++)
#pragma unroll
            for (int i = 0; i < 4; i++) acc[mt][nt][i] = 0.f;

    fill(0, 0); CP_COMMIT();
    fill(1, 1); CP_COMMIT();

    for (int k = 0; k < NCH; k++) {
        int s = k % 3;
        if (k + 1 < NCH) { CP_WAIT1(); } else { CP_WAIT0(); }
        __syncthreads();
        if (k + 2 < NCH) { fill((k + 2) % 3, k + 2); CP_COMMIT(); }
        uint32_t Ab = sb + s * STAGE;
        uint32_t Bb = Ab + 16384 + z * 8192;
#pragma unroll
        for (int ks = 0; ks < 4; ks++) {
            uint32_t aq[2][4];
#pragma unroll
            for (int mt = 0; mt < 2; mt++) {
                int r = pxg * 32 + mt * 16 + (lsub & 1) * 8 + lrow;
                uint32_t gran = ks * 2 + (lsub >> 1);
                LDSM4(aq[mt], Ab + r * 128 + ((gran * 16) ^ ((r & 7) << 4)));
            }
#pragma unroll
            for (int p = 0; p < 4; p++) {
                int nn = p * 16 + (lsub >> 1) * 8 + lrow;
                uint32_t gran = ks * 2 + (lsub & 1);
                uint32_t bq[4];
                LDSM4(bq, Bb + nn * 128 + ((gran * 16) ^ ((nn & 7) << 4)));
#pragma unroll
                for (int mt = 0; mt < 2; mt++) {
                    mma16816(acc[mt][2 * p],     aq[mt], bq[0], bq[1]);
                    mma16816(acc[mt][2 * p + 1], aq[mt], bq[2], bq[3]);
                }
            }
        }
    }

    uint32_t* q32 = (uint32_t*)g_q;
#pragma unroll
    for (int mt = 0; mt < 2; mt++) {
#pragma unroll
        for (int half = 0; half < 2; half++) {
            int m = tile * 128 + pxg * 32 + mt * 16 + (lane >> 2) + half * 8;
            if (z == 0) {
                size_t rb = ((size_t)hd * HW + m) * 32;
#pragma unroll
                for (int nt = 0; nt < 8; nt++) {
                    int ocp = nt * 4 + (lane & 3);
                    q32[rb + ocp] = packh(acc[mt][nt][half * 2],
                                          acc[mt][nt][half * 2 + 1]);
                }
            } else {
                int oy = m / 48, ox = m - oy * 48;
                if (oy >= 1 && oy <= 46 && ox >= 1 && ox <= 46) {
                    int d = (oy - 1) * 46 + (ox - 1);
                    size_t rb = ((size_t)hd * DPAD + d) * 32;
                    uint32_t* dst = (uint32_t*)((z == 1) ? g_k : g_v);
#pragma unroll
                    for (int nt = 0; nt < 8; nt++) {
                        int ocp = nt * 4 + (lane & 3);
                        dst[rb + ocp] = packh(acc[mt][nt][half * 2],
                                              acc[mt][nt][half * 2 + 1]);
                    }
                }
            }
        }
    }
}

// ------------------------------------------------------------------
// gate_kernel: 512 threads, 3-stage.  warp = (32px = w&3, 1 gate = w>>2).
// Fill addressing hoisted; LSTM fused via smem exchange.
// ------------------------------------------------------------------
__global__ __launch_bounds__(512, 1) void gate_kernel(
    const float* __restrict__ bbi, const float* __restrict__ bbf,
    const float* __restrict__ bbg, const float* __restrict__ bbo,
    const float* __restrict__ cold, float* __restrict__ out)
{
    extern __shared__ char smem[];
    const int STAGE = 49152;
    uint32_t sb = s2u(smem);
    const int tid = threadIdx.x, w = tid >> 5, lane = tid & 31;
    const int hd = blockIdx.y, g = hd & 7;
    const int tile = blockIdx.x;
    const int NCH = 19;
    const int lsub = lane >> 3, lrow = lane & 7;
    const int pxg = w & 3, z = w >> 2;

    const __half* xbase = g_xhp + (size_t)hd * HW * 128;

    // hoisted A-fill addressing: thread covers row r = tid>>2, granules q*2, q*2+1
    const int ar = tid >> 2, aq4 = tid & 3;
    const int apx_ = tile * 128 + ar;
    const int apy = apx_ / 48, apxx = apx_ - apy * 48;
    const uint32_t asw = (ar & 7) << 4;
    uint32_t adst[2], agc[2];
#pragma unroll
    for (int j = 0; j < 2; j++) {
        int gc = aq4 * 2 + j;
        adst[j] = ar * 128 + (uint32_t)((gc * 16) ^ asw);
        agc[j] = gc * 16;
    }
    const char* abase_a = (const char*)(g_a + ((size_t)hd * HW + apx_) * 64);
    // hoisted B-fill
    uint32_t bdst[4];
    const uint32_t* bsrc[4];
#pragma unroll
    for (int i = 0; i < 4; i++) {
        int p = tid + i * 512;
        int zz = p >> 9, pg = p & 511;
        int oc = pg >> 3, gr = pg & 7;
        bdst[i] = 16384 + zz * 8192 + oc * 128 + (uint32_t)((gr * 16) ^ ((oc & 7) << 4));
        bsrc[i] = g_wb32 + ((size_t)((3 + zz) * 8 + g) * 19) * 2048 + pg * 4;
    }

    auto fill = [&](int s, int k) {
        uint32_t base = sb + s * STAGE;
        const char* sh;
        bool in;
        if (k < 18) {
            int t9 = k >> 1, cb = k & 1, ky = t9 / 3, kx = t9 - ky * 3;
            int iy = apy + ky - 1, ix = apxx + kx - 1;
            in = ((unsigned)iy < 48u) && ((unsigned)ix < 48u);
            const __half* rp = in ? (xbase + ((size_t)(iy * 48 + ix)) * 128 + cb * 64)
                                  : g_xhp;
            sh = (const char*)rp;
        } else {
            in = true;
            sh = abase_a;
        }
#pragma unroll
        for (int j = 0; j < 2; j++)
            cpa16(base + adst[j], sh + agc[j], in);
#pragma unroll
        for (int i = 0; i < 4; i++)
            cpa16(base + bdst[i], bsrc[i] + (size_t)k * 2048, true);
    };

    float acc[2][8][4];
#pragma unroll
    for (int mt = 0; mt < 2; mt++)
#pragma unroll
        for (int nt = 0; nt < 8; nt++)
#pragma unroll
            for (int i = 0; i < 4; i++) acc[mt][nt][i] = 0.f;

    fill(0, 0); CP_COMMIT();
    fill(1, 1); CP_COMMIT();

    for (int k = 0; k < NCH; k++) {
        int s = k % 3;
        if (k + 1 < NCH) { CP_WAIT1(); } else { CP_WAIT0(); }
        __syncthreads();
        if (k + 2 < NCH) { fill((k + 2) % 3, k + 2); CP_COMMIT(); }
        uint32_t Ab = sb + s * STAGE;
        uint32_t Bb = Ab + 16384 + z * 8192;
#pragma unroll
        for (int ks = 0; ks < 4; ks++) {
            uint32_t aq[2][4];
#pragma unroll
            for (int mt = 0; mt < 2; mt++) {
                int r = pxg * 32 + mt * 16 + (lsub & 1) * 8 + lrow;
                uint32_t gran = ks * 2 + (lsub >> 1);
                LDSM4(aq[mt], Ab + r * 128 + ((gran * 16) ^ ((r & 7) << 4)));
            }
#pragma unroll
            for (int p = 0; p < 4; p++) {
                int nn = p * 16 + (lsub >> 1) * 8 + lrow;
                uint32_t gran = ks * 2 + (lsub & 1);
                uint32_t bq[4];
                LDSM4(bq, Bb + nn * 128 + ((gran * 16) ^ ((nn & 7) << 4)));
#pragma unroll
                for (int mt = 0; mt < 2; mt++) {
                    mma16816(acc[mt][2 * p],     aq[mt], bq[0], bq[1]);
                    mma16816(acc[mt][2 * p + 1], aq[mt], bq[2], bq[3]);
                }
            }
        }
    }

    // ---- epilogue: exchange gate fragments via smem, LSTM, write ----
    float* smf = (float*)smem;      // [z][px128][oc64] fp32 = 128 KB
    __syncthreads();
#pragma unroll
    for (int mt = 0; mt < 2; mt++) {
#pragma unroll
        for (int half = 0; half < 2; half++) {
            int pxl = pxg * 32 + mt * 16 + (lane >> 2) + half * 8;
#pragma unroll
            for (int nt = 0; nt < 8; nt++) {
                int oc0 = nt * 8 + (lane & 3) * 2;
                float2 v = make_float2(acc[mt][nt][half * 2],
                                       acc[mt][nt][half * 2 + 1]);
                *(float2*)(smf + z * 8192 + pxl * 64 + oc0) = v;
            }
        }
    }
    __syncthreads();

    int n = hd >> 3;
#pragma unroll
    for (int i = 0; i < 16; i++) {
        int elem = i * 512 + tid;
        int pxl = elem >> 6, oc = elem & 63;
        float pi = smf[0 * 8192 + pxl * 64 + oc] + bbi[g * 64 + oc];
        float pf = smf[1 * 8192 + pxl * 64 + oc] + bbf[g * 64 + oc];
        float pg = smf[2 * 8192 + pxl * 64 + oc] + bbg[g * 64 + oc];
        float po = smf[3 * 8192 + pxl * 64 + oc] + bbo[g * 64 + oc];
        float ig = 1.f / (1.f + __expf(-pi));
        float fg = 1.f / (1.f + __expf(-pf));
        float gg = tanhf(pg);
        float og = 1.f / (1.f + __expf(-po));
        size_t ci = ((size_t)n * 512 + g * 64 + oc) * HW + tile * 128 + pxl;
        float cn = fg * cold[ci] + ig * gg;
        out[ci] = og * tanhf(cn);
    }
}

// ------------------------------------------------------------------
// attn_kernel: 256 threads, 8 warps, warp = 32 queries x 64 keys.
// CTA = 256 queries, 3-stage KV.  SMEM: Q 32K | 3 x 16K = 80K.
// ------------------------------------------------------------------
__global__ __launch_bounds__(256, 1) void attn_kernel(const float* __restrict__ tau)
{
    extern __shared__ char smem[];
    uint32_t sb = s2u(smem);
    const int tid = threadIdx.x, w = tid >> 5, lane = tid & 31;
    const int hd = blockIdx.y, g = hd & 7;
    const int qbase = blockIdx.x * 256;
    const int lsub = lane >> 3, lrow = lane & 7;
    const float ts2 = tau[g] * 1.44269504f;
    const int NCHK = (DS + 63) / 64;   // 34

    // Q fill (once): 256 rows x 128 bytes, 1 thread per row
    {
        int r = tid;
        const char* qs = (const char*)g_q + ((size_t)hd * HW + qbase + r) * 128;
        uint32_t sw = (r & 7) << 4;
#pragma unroll
        for (int gc = 0; gc < 8; gc++)
            cpa16(sb + r * 128 + ((gc * 16) ^ sw), qs + gc * 16, true);
    }
    auto fillkv = [&](int s, int c) {
        uint32_t base = sb + 32768 + s * 16384;
        int r = tid >> 2;
        int q4 = tid & 3;
        int d = c * 64 + r;
        bool ok = d < DS;
        size_t rb = ((size_t)hd * DPAD + (ok ? d : 0)) * 128;  // bytes
        uint32_t sw = (r & 7) << 4;
#pragma unroll
        for (int gg = 0; gg < 2; gg++) {
            int gran = q4 * 2 + gg;
            uint32_t off = r * 128 + ((gran * 16) ^ sw);
            cpa16(base + off,        (const char*)g_k + rb + gran * 16, ok);
            cpa16(base + 8192 + off, (const char*)g_v + rb + gran * 16, ok);
        }
    };

    fillkv(0, 0); CP_COMMIT();
    fillkv(1, 1); CP_COMMIT();

    float o[2][8][4];
#pragma unroll
    for (int mt = 0; mt < 2; mt++)
#pragma unroll
        for (int nt = 0; nt < 8; nt++)
#pragma unroll
            for (int i = 0; i < 4; i++) o[mt][nt][i] = 0.f;
    float mrow[2][2] = {{-1e30f, -1e30f}, {-1e30f, -1e30f}};
    float lsum[2][2] = {{0.f, 0.f}, {0.f, 0.f}};

    for (int c = 0; c < NCHK; c++) {
        int s = c % 3;
        if (c + 1 < NCHK) { CP_WAIT1(); } else { CP_WAIT0(); }
        __syncthreads();
        if (c + 2 < NCHK) { fillkv((c + 2) % 3, c + 2); CP_COMMIT(); }
        uint32_t Kb = sb + 32768 + s * 16384;
        uint32_t Vb = Kb + 8192;

        float sf[2][8][4];
#pragma unroll
        for (int mt = 0; mt < 2; mt++)
#pragma unroll
            for (int nt = 0; nt < 8; nt++)
#pragma unroll
                for (int i = 0; i < 4; i++) sf[mt][nt][i] = 0.f;
#pragma unroll
        for (int ks = 0; ks < 4; ks++) {
            uint32_t aq[2][4];
#pragma unroll
            for (int mt = 0; mt < 2; mt++) {
                int r = w * 32 + mt * 16 + (lsub & 1) * 8 + lrow;
                uint32_t gran = ks * 2 + (lsub >> 1);
                LDSM4(aq[mt], sb + r * 128 + ((gran * 16) ^ ((r & 7) << 4)));
            }
#pragma unroll
            for (int p = 0; p < 4; p++) {
                int nn = p * 16 + (lsub >> 1) * 8 + lrow;
                uint32_t gran = ks * 2 + (lsub & 1);
                uint32_t bq[4];
                LDSM4(bq, Kb + nn * 128 + ((gran * 16) ^ ((nn & 7) << 4)));
#pragma unroll
                for (int mt = 0; mt < 2; mt++) {
                    mma16816(sf[mt][2 * p],     aq[mt], bq[0], bq[1]);
                    mma16816(sf[mt][2 * p + 1], aq[mt], bq[2], bq[3]);
                }
            }
        }

        // mask tail keys (only last chunk)
        if (c == NCHK - 1) {
            int dbase = c * 64 + (lane & 3) * 2;
#pragma unroll
            for (int mt = 0; mt < 2; mt++)
#pragma unroll
                for (int nt = 0; nt < 8; nt++)
#pragma unroll
                    for (int i = 0; i < 4; i++) {
                        int d = dbase + nt * 8 + (i & 1);
                        if (d >= DS) sf[mt][nt][i] = -1e30f;
                    }
        }

        // online softmax (s-domain max, ex2)
        float alpha[2][2];
#pragma unroll
        for (int mt = 0; mt < 2; mt++) {
#pragma unroll
            for (int h = 0; h < 2; h++) {
                float mx = mrow[mt][h];
#pragma unroll
                for (int nt = 0; nt < 8; nt++) {
                    mx = fmaxf(mx, sf[mt][nt][h * 2]);
                    mx = fmaxf(mx, sf[mt][nt][h * 2 + 1]);
                }
                mx = fmaxf(mx, __shfl_xor_sync(0xffffffffu, mx, 1));
                mx = fmaxf(mx, __shfl_xor_sync(0xffffffffu, mx, 2));
                float nm = mx * ts2;
                float al_ = ex2(fmaf(mrow[mt][h], ts2, -nm));
                mrow[mt][h] = mx;
                alpha[mt][h] = al_;
                float ls = lsum[mt][h] * al_;
#pragma unroll
                for (int nt = 0; nt < 8; nt++) {
#pragma unroll
                    for (int e = 0; e < 2; e++) {
                        float p = ex2(fmaf(sf[mt][nt][h * 2 + e], ts2, -nm));
                        sf[mt][nt][h * 2 + e] = p;
                        ls += p;
                    }
                }
                lsum[mt][h] = ls;
            }
        }
#pragma unroll
        for (int mt = 0; mt < 2; mt++)
#pragma unroll
            for (int nt = 0; nt < 8; nt++) {
                o[mt][nt][0] *= alpha[mt][0];
                o[mt][nt][1] *= alpha[mt][0];
                o[mt][nt][2] *= alpha[mt][1];
                o[mt][nt][3] *= alpha[mt][1];
            }

        // O += P V
#pragma unroll
        for (int kt = 0; kt < 4; kt++) {
            uint32_t pa[2][4];
#pragma unroll
            for (int mt = 0; mt < 2; mt++)
#pragma unroll
                for (int i = 0; i < 4; i++) {
                    int nt = 2 * kt + (i >> 1);
                    pa[mt][i] = packh(sf[mt][nt][(i & 1) * 2],
                                      sf[mt][nt][(i & 1) * 2 + 1]);
                }
#pragma unroll
            for (int np = 0; np < 4; np++) {
                int rr = kt * 16 + (lane & 15);
                uint32_t gran = np * 2 + (lane >> 4);
                uint32_t vq[4];
                LDSM4T(vq, Vb + rr * 128 + ((gran * 16) ^ ((rr & 7) << 4)));
#pragma unroll
                for (int mt = 0; mt < 2; mt++) {
                    mma16816(o[mt][2 * np],     pa[mt], vq[0], vq[1]);
                    mma16816(o[mt][2 * np + 1], pa[mt], vq[2], vq[3]);
                }
            }
        }
    }

    uint32_t* a32 = (uint32_t*)g_a;
#pragma unroll
    for (int mt = 0; mt < 2; mt++) {
#pragma unroll
        for (int h = 0; h < 2; h++) {
            float l = lsum[mt][h];
            l += __shfl_xor_sync(0xffffffffu, l, 1);
            l += __shfl_xor_sync(0xffffffffu, l, 2);
            float inv = 1.f / l;
            int m = qbase + w * 32 + mt * 16 + (lane >> 2) + h * 8;
            size_t rb = ((size_t)hd * HW + m) * 32;
#pragma unroll
            for (int nt = 0; nt < 8; nt++) {
                int ocp = nt * 4 + (lane & 3);
                a32[rb + ocp] = packh(o[mt][nt][h * 2] * inv,
                                      o[mt][nt][h * 2 + 1] * inv);
            }
        }
    }
}

// ------------------------------------------------------------------
extern "C" void kernel_launch(void* const* d_in, const int* in_sizes, int n_in,
                              void* d_out, int out_size)
{
    const float* x_in = (const float*)d_in[0];
    const float* h    = (const float*)d_in[1];
    const float* c    = (const float*)d_in[2];
    const float* tau  = (const float*)d_in[3];
    const float* Wx   = (const float*)d_in[4];
    const float* Wig  = (const float*)d_in[5];
    const float* Wq   = (const float*)d_in[6];
    const float* Wk   = (const float*)d_in[7];
    const float* Wv   = (const float*)d_in[8];
    const float* Wia  = (const float*)d_in[9];
    const float* Wix  = (const float*)d_in[10];
    const float* bi   = (const float*)d_in[11];
    const float* Wfa  = (const float*)d_in[12];
    const float* Wfx  = (const float*)d_in[13];
    const float* bf   = (const float*)d_in[14];
    const float* Wga  = (const float*)d_in[15];
    const float* Wgx  = (const float*)d_in[16];
    const float* bg   = (const float*)d_in[17];
    const float* Woa  = (const float*)d_in[18];
    const float* Wox  = (const float*)d_in[19];
    const float* bo   = (const float*)d_in[20];
    float* out = (float*)d_out;

    const int PSMEM = 3 * 32768;            //  96 KB proj
    const int QSMEM = 3 * 40960;            // 120 KB qkv
    const int GSMEM = 3 * 49152;            // 144 KB gates
    const int ASMEM = 32768 + 3 * 16384;    //  80 KB attn
    cudaFuncSetAttribute(proj_mma,
                         cudaFuncAttributeMaxDynamicSharedMemorySize, PSMEM);
    cudaFuncSetAttribute(qkv_kernel,
                         cudaFuncAttributeMaxDynamicSharedMemorySize, QSMEM);
    cudaFuncSetAttribute(gate_kernel,
                         cudaFuncAttributeMaxDynamicSharedMemorySize, GSMEM);
    cudaFuncSetAttribute(attn_kernel,
                         cudaFuncAttributeMaxDynamicSharedMemorySize, ASMEM);

    prep_all<<<9280, 256>>>(Wq, Wk, Wv, Wix, Wfx, Wgx, Wox,
                            Wia, Wfa, Wga, Woa, Wx, Wig);
    prep_x<<<dim3(18, 12, 2), 256>>>(x_in, h);
    proj_mma<<<dim3(18, 4, 2), 512, PSMEM>>>();
    qkv_kernel<<<dim3(18, 16), 384, QSMEM>>>();
    attn_kernel<<<dim3(9, 16), 256, ASMEM>>>(tau);
    gate_kernel<<<dim3(18, 16), 512, GSMEM>>>(bi, bf, bg, bo, c, out);
}